// round 1
// baseline (speedup 1.0000x reference)
#include <cuda_runtime.h>

// ---------------- problem constants ----------------
#define Bsz   8
#define Sq    4096
#define Dm    1280
#define Cm    2048
#define Hn    20
#define DHd   64
#define LT    77
#define LI    16
#define LTOT  109          // 77 + 16 + 16
#define MQ    (Bsz*Sq)     // 32768

// ---------------- scratch (__device__ globals: allocation-free) ----------------
__device__ float g_Q[(size_t)MQ * Dm];        // scaled Q  [B*S, D]
__device__ float g_O[(size_t)MQ * Dm];        // summed attention out [B*S, D]
__device__ float g_K[(size_t)Bsz * LTOT * Dm];// concat K  [B, 109, D]
__device__ float g_V[(size_t)Bsz * LTOT * Dm];// concat V  [B, 109, D]

// ---------------- fp32 tiled SGEMM: C = alpha*(A@B) + bias ----------------
// A: M x K (row-major, lda=K), B: K x N (ldb=N), C: M x N (ldc=N)
// batched over blockIdx.z with strides sA (A) and sC (C); B shared across batch.
// BM=BN=128, BK=8, 256 threads, 8x8 per thread.
__global__ __launch_bounds__(256, 2)
void sgemm_kernel(const float* __restrict__ A, const float* __restrict__ Bm,
                  const float* __restrict__ bias, float* __restrict__ C,
                  int M, int N, int K, long long sA, long long sC, float alpha)
{
    __shared__ float As[8][128];   // transposed A tile
    __shared__ float Bs[8][128];

    A += (size_t)blockIdx.z * sA;
    C += (size_t)blockIdx.z * sC;

    const int tid  = threadIdx.x;
    const int brow = blockIdx.y * 128;
    const int bcol = blockIdx.x * 128;

    const int ar  = tid >> 1;          // 0..127 : A row in tile
    const int ak  = (tid & 1) * 4;     // 0 or 4 : A k-offset
    const int bkr = tid >> 5;          // 0..7   : B k row
    const int bc  = (tid & 31) * 4;    // B col offset
    const int tr  = tid >> 4;          // 0..15
    const int tc  = tid & 15;          // 0..15

    float acc[8][8];
#pragma unroll
    for (int i = 0; i < 8; i++)
#pragma unroll
        for (int j = 0; j < 8; j++) acc[i][j] = 0.0f;

    for (int k0 = 0; k0 < K; k0 += 8) {
        float4 av = make_float4(0.f, 0.f, 0.f, 0.f);
        if (brow + ar < M)
            av = *(const float4*)&A[(size_t)(brow + ar) * K + k0 + ak];
        float4 bv = *(const float4*)&Bm[(size_t)(k0 + bkr) * N + bcol + bc];

        As[ak + 0][ar] = av.x;
        As[ak + 1][ar] = av.y;
        As[ak + 2][ar] = av.z;
        As[ak + 3][ar] = av.w;
        *(float4*)&Bs[bkr][bc] = bv;
        __syncthreads();

#pragma unroll
        for (int kk = 0; kk < 8; kk++) {
            float4 a0 = *(const float4*)&As[kk][tr * 8];
            float4 a1 = *(const float4*)&As[kk][tr * 8 + 4];
            float4 b0 = *(const float4*)&Bs[kk][tc * 8];
            float4 b1 = *(const float4*)&Bs[kk][tc * 8 + 4];
            float a[8] = {a0.x, a0.y, a0.z, a0.w, a1.x, a1.y, a1.z, a1.w};
            float b[8] = {b0.x, b0.y, b0.z, b0.w, b1.x, b1.y, b1.z, b1.w};
#pragma unroll
            for (int i = 0; i < 8; i++)
#pragma unroll
                for (int j = 0; j < 8; j++)
                    acc[i][j] = fmaf(a[i], b[j], acc[i][j]);
        }
        __syncthreads();
    }

#pragma unroll
    for (int i = 0; i < 8; i++) {
        int r = brow + tr * 8 + i;
        if (r < M) {
#pragma unroll
            for (int jq = 0; jq < 2; jq++) {
                int c = bcol + tc * 8 + jq * 4;
                float4 o;
                o.x = alpha * acc[i][jq * 4 + 0];
                o.y = alpha * acc[i][jq * 4 + 1];
                o.z = alpha * acc[i][jq * 4 + 2];
                o.w = alpha * acc[i][jq * 4 + 3];
                if (bias) {
                    o.x += bias[c + 0]; o.y += bias[c + 1];
                    o.z += bias[c + 2]; o.w += bias[c + 3];
                }
                *(float4*)&C[(size_t)r * N + c] = o;
            }
        }
    }
}

// ---------------- fused 3-branch attention ----------------
// One block per (b, h, 32-row q tile). K/V for all 3 branches (109 rows) live
// in shared; per-segment softmax; o = sum of the 3 branch outputs directly.
#define TQ    32
#define QPAD  68    // 16B-aligned row stride, 4r%32 bank pattern -> conflict-free LDS.128
#define SPAD  113   // odd stride -> conflict-free row walks

#define ATTN_SMEM_FLOATS (TQ*QPAD + 2*LTOT*DHd + TQ*SPAD)
#define ATTN_SMEM_BYTES  (ATTN_SMEM_FLOATS * 4)

__global__ __launch_bounds__(256)
void attn_kernel()
{
    extern __shared__ float sm[];
    float* Qs = sm;                       // [TQ][QPAD]
    float* Ks = Qs + TQ * QPAD;           // [LTOT][DHd]
    float* Vs = Ks + LTOT * DHd;          // [LTOT][DHd]
    float* Sc = Vs + LTOT * DHd;          // [TQ][SPAD]

    const int t  = threadIdx.x;
    const int b  = blockIdx.z;
    const int h  = blockIdx.y;
    const int s0 = blockIdx.x * TQ;

    const float* Qg = g_Q + ((size_t)(b * Sq + s0)) * Dm + h * DHd;
    const float* Kg = g_K + ((size_t)b * LTOT) * Dm + h * DHd;
    const float* Vg = g_V + ((size_t)b * LTOT) * Dm + h * DHd;

    // load Q tile (already scaled by 1/sqrt(dh) in the Q GEMM)
    for (int j = t; j < TQ * DHd / 4; j += 256) {
        int r = j >> 4, d4 = (j & 15) * 4;
        *(float4*)(Qs + r * QPAD + d4) = *(const float4*)(Qg + (size_t)r * Dm + d4);
    }
    // load K and V (109 x 64)
    for (int j = t; j < LTOT * DHd / 4; j += 256) {
        int l = j >> 4, d4 = (j & 15) * 4;
        *(float4*)(Ks + l * DHd + d4) = *(const float4*)(Kg + (size_t)l * Dm + d4);
        *(float4*)(Vs + l * DHd + d4) = *(const float4*)(Vg + (size_t)l * Dm + d4);
    }
    __syncthreads();

    // scores: Sc[r][l] = Qs[r] . Ks[l]    (warp = one l across all 32 r)
    for (int idx = t; idx < TQ * LTOT; idx += 256) {
        int r = idx & 31, l = idx >> 5;
        const float4* qp = (const float4*)(Qs + r * QPAD);
        const float4* kp = (const float4*)(Ks + l * DHd);
        float acc = 0.f;
#pragma unroll
        for (int d = 0; d < DHd / 4; d++) {
            float4 a = qp[d], c = kp[d];
            acc += a.x * c.x + a.y * c.y + a.z * c.z + a.w * c.w;
        }
        Sc[r * SPAD + l] = acc;
    }
    __syncthreads();

    // per-(row, segment) softmax: segments [0,77) [77,93) [93,109)
    if (t < 96) {
        const int seg0[3] = {0, LT, LT + LI};
        const int seg1[3] = {LT, LT + LI, LTOT};
        int r = t & 31, sg = t >> 5;
        float* row = Sc + r * SPAD;
        int a0 = seg0[sg], a1 = seg1[sg];
        float mx = -1e30f;
        for (int l = a0; l < a1; l++) mx = fmaxf(mx, row[l]);
        float sum = 0.f;
        for (int l = a0; l < a1; l++) { float e = __expf(row[l] - mx); row[l] = e; sum += e; }
        float inv = 1.0f / sum;
        for (int l = a0; l < a1; l++) row[l] *= inv;
    }
    __syncthreads();

    // o[r][d] = sum_l P[r][l] * V[l][d]   (sum over all 3 segments = branch sum)
    float* Og = g_O + ((size_t)(b * Sq + s0)) * Dm + h * DHd;
    for (int j = t; j < TQ * DHd / 4; j += 256) {
        int r = j >> 4, d4 = (j & 15) * 4;
        const float* prow = Sc + r * SPAD;
        float4 acc = make_float4(0.f, 0.f, 0.f, 0.f);
        for (int l = 0; l < LTOT; l++) {
            float p  = prow[l];
            float4 v = *(const float4*)(Vs + l * DHd + d4);
            acc.x = fmaf(p, v.x, acc.x);
            acc.y = fmaf(p, v.y, acc.y);
            acc.z = fmaf(p, v.z, acc.z);
            acc.w = fmaf(p, v.w, acc.w);
        }
        *(float4*)(Og + (size_t)r * Dm + d4) = acc;
    }
}

// ---------------- launch ----------------
extern "C" void kernel_launch(void* const* d_in, const int* in_sizes, int n_in,
                              void* d_out, int out_size)
{
    const float* hidden  = (const float*)d_in[0];
    const float* text    = (const float*)d_in[1];
    const float* ids     = (const float*)d_in[2];
    const float* hair    = (const float*)d_in[3];
    const float* Wq      = (const float*)d_in[4];
    const float* Wk      = (const float*)d_in[5];
    const float* Wv      = (const float*)d_in[6];
    const float* Wo      = (const float*)d_in[7];
    const float* bo      = (const float*)d_in[8];
    const float* Wk_id   = (const float*)d_in[9];
    const float* Wv_id   = (const float*)d_in[10];
    const float* Wk_hair = (const float*)d_in[11];
    const float* Wv_hair = (const float*)d_in[12];
    float* out = (float*)d_out;

    float *pQ, *pO, *pK, *pV;
    cudaGetSymbolAddress((void**)&pQ, g_Q);
    cudaGetSymbolAddress((void**)&pO, g_O);
    cudaGetSymbolAddress((void**)&pK, g_K);
    cudaGetSymbolAddress((void**)&pV, g_V);

    const float scale = 0.125f;  // 1/sqrt(64)

    // Q = scale * (hidden @ Wq)        [32768 x 1280], K=1280
    sgemm_kernel<<<dim3(Dm / 128, MQ / 128, 1), 256>>>(
        hidden, Wq, nullptr, pQ, MQ, Dm, Dm, 0, 0, scale);

    // K/V projections, concatenated rows per batch: [0,77)=text, [77,93)=id, [93,109)=hair
    const long long sKC = (long long)LTOT * Dm;
    sgemm_kernel<<<dim3(Dm / 128, 1, Bsz), 256>>>(
        text, Wk,      nullptr, pK,              LT, Dm, Cm, (long long)LT * Cm, sKC, 1.0f);
    sgemm_kernel<<<dim3(Dm / 128, 1, Bsz), 256>>>(
        text, Wv,      nullptr, pV,              LT, Dm, Cm, (long long)LT * Cm, sKC, 1.0f);
    sgemm_kernel<<<dim3(Dm / 128, 1, Bsz), 256>>>(
        ids,  Wk_id,   nullptr, pK + (size_t)LT * Dm,        LI, Dm, Cm, (long long)LI * Cm, sKC, 1.0f);
    sgemm_kernel<<<dim3(Dm / 128, 1, Bsz), 256>>>(
        ids,  Wv_id,   nullptr, pV + (size_t)LT * Dm,        LI, Dm, Cm, (long long)LI * Cm, sKC, 1.0f);
    sgemm_kernel<<<dim3(Dm / 128, 1, Bsz), 256>>>(
        hair, Wk_hair, nullptr, pK + (size_t)(LT + LI) * Dm, LI, Dm, Cm, (long long)LI * Cm, sKC, 1.0f);
    sgemm_kernel<<<dim3(Dm / 128, 1, Bsz), 256>>>(
        hair, Wv_hair, nullptr, pV + (size_t)(LT + LI) * Dm, LI, Dm, Cm, (long long)LI * Cm, sKC, 1.0f);

    // fused 3-branch attention -> g_O (branch outputs summed in-kernel)
    cudaFuncSetAttribute(attn_kernel, cudaFuncAttributeMaxDynamicSharedMemorySize,
                         ATTN_SMEM_BYTES);
    attn_kernel<<<dim3(Sq / TQ, Hn, Bsz), 256, ATTN_SMEM_BYTES>>>();

    // out = g_O @ Wo + bo   (single output GEMM thanks to shared Wo)
    sgemm_kernel<<<dim3(Dm / 128, MQ / 128, 1), 256>>>(
        pO, Wo, bo, out, MQ, Dm, Dm, 0, 0, 1.0f);
}

// round 3
// speedup vs baseline: 2.5981x; 2.5981x over previous
#include <cuda_runtime.h>
#include <cuda_bf16.h>

// ---------------- problem constants ----------------
#define Bsz   8
#define Sq    4096
#define Dm    1280
#define Cm    2048
#define Hn    20
#define DHd   64
#define LT    77
#define LI    16
#define LTOT  109          // 77 + 16 + 16
#define MQ    (Bsz*Sq)     // 32768

// ---------------- scratch ----------------
__device__ float g_Q[(size_t)MQ * Dm];
__device__ float g_O[(size_t)MQ * Dm];
__device__ float g_K[(size_t)Bsz * LTOT * Dm];
__device__ float g_V[(size_t)Bsz * LTOT * Dm];

// ================= bf16-split tensor-core GEMM =================
// C[M,N] = alpha * (A[M,K] @ W[K,N]) + bias, fp32 in/out.
// Split: x = hi + lo (bf16 each); acc = Ah*Bh + Ah*Bl + Al*Bh  (error ~2^-16).
// BM=BN=128, BK=32, 256 threads = 8 warps (2x4), warp tile 64x32, mma m16n8k16.

#define BKP 40    // padded A k-stride (elements): conflict-free ldmatrix
#define BNP 136   // padded B n-stride (elements): conflict-free ldmatrix.trans

__device__ __forceinline__ void split2(float x, float y, unsigned& hi, unsigned& lo)
{
    __nv_bfloat16 hx = __float2bfloat16_rn(x);
    __nv_bfloat16 hy = __float2bfloat16_rn(y);
    float rx = x - __bfloat162float(hx);
    float ry = y - __bfloat162float(hy);
    __nv_bfloat162 hp = __halves2bfloat162(hx, hy);
    __nv_bfloat162 lp = __halves2bfloat162(__float2bfloat16_rn(rx), __float2bfloat16_rn(ry));
    hi = *reinterpret_cast<unsigned*>(&hp);
    lo = *reinterpret_cast<unsigned*>(&lp);
}

__device__ __forceinline__ void ldsm4(unsigned& r0, unsigned& r1, unsigned& r2, unsigned& r3,
                                      const void* p)
{
    unsigned a = (unsigned)__cvta_generic_to_shared(p);
    asm volatile("ldmatrix.sync.aligned.m8n8.x4.shared.b16 {%0,%1,%2,%3},[%4];"
                 : "=r"(r0), "=r"(r1), "=r"(r2), "=r"(r3) : "r"(a));
}

__device__ __forceinline__ void ldsm4t(unsigned& r0, unsigned& r1, unsigned& r2, unsigned& r3,
                                       const void* p)
{
    unsigned a = (unsigned)__cvta_generic_to_shared(p);
    asm volatile("ldmatrix.sync.aligned.m8n8.x4.trans.shared.b16 {%0,%1,%2,%3},[%4];"
                 : "=r"(r0), "=r"(r1), "=r"(r2), "=r"(r3) : "r"(a));
}

__device__ __forceinline__ void mma16816(float* c, const unsigned* a, const unsigned* b)
{
    asm volatile(
        "mma.sync.aligned.m16n8k16.row.col.f32.bf16.bf16.f32 "
        "{%0,%1,%2,%3}, {%4,%5,%6,%7}, {%8,%9}, {%0,%1,%2,%3};"
        : "+f"(c[0]), "+f"(c[1]), "+f"(c[2]), "+f"(c[3])
        : "r"(a[0]), "r"(a[1]), "r"(a[2]), "r"(a[3]), "r"(b[0]), "r"(b[1]));
}

// out-row mapping: Lseg==0 -> identity; else r -> (r/Lseg)*LTOT + segOff + r%Lseg
__device__ __forceinline__ int orow(int r, int Lseg, int segOff)
{
    if (Lseg == 0) return r;
    int b = r / Lseg;
    return b * LTOT + segOff + (r - b * Lseg);
}

__device__ __forceinline__ void gemm_core(
    const float* __restrict__ A, const float* __restrict__ W,
    const float* __restrict__ bias, float* __restrict__ C,
    int M, int K, int Lseg, int segOff, float alpha, int bx, int by,
    unsigned short* AsH, unsigned short* AsL, unsigned short* BsH, unsigned short* BsL)
{
    const int N = Dm;
    const int tid  = threadIdx.x;
    const int lane = tid & 31;
    const int warp = tid >> 5;
    const int wM = warp >> 2;   // 0..1
    const int wN = warp & 3;    // 0..3
    const int brow = by * 128;
    const int bcol = bx * 128;

    float acc[4][4][4];
#pragma unroll
    for (int i = 0; i < 4; i++)
#pragma unroll
        for (int j = 0; j < 4; j++)
#pragma unroll
            for (int q = 0; q < 4; q++) acc[i][j][q] = 0.f;

    const int akc = (tid & 7) * 4;      // A k offset 0..28
    const int ar0 = tid >> 3;           // A row base 0..31 (+32*i)
    const int bnc = (tid & 31) * 4;     // B n offset
    const int bk0 = tid >> 5;           // B k row base 0..7 (+8*i)

    for (int k0 = 0; k0 < K; k0 += 32) {
        // ---- load + split A tile [128][32] ----
#pragma unroll
        for (int i = 0; i < 4; i++) {
            int r = ar0 + 32 * i;
            float4 v = make_float4(0.f, 0.f, 0.f, 0.f);
            if (brow + r < M)
                v = *(const float4*)&A[(size_t)(brow + r) * K + k0 + akc];
            unsigned h0, l0, h1, l1;
            split2(v.x, v.y, h0, l0);
            split2(v.z, v.w, h1, l1);
            *(uint2*)&AsH[r * BKP + akc] = make_uint2(h0, h1);
            *(uint2*)&AsL[r * BKP + akc] = make_uint2(l0, l1);
        }
        // ---- load + split B tile [32][128] ----
#pragma unroll
        for (int i = 0; i < 4; i++) {
            int kr = bk0 + 8 * i;
            float4 v = *(const float4*)&W[(size_t)(k0 + kr) * N + bcol + bnc];
            unsigned h0, l0, h1, l1;
            split2(v.x, v.y, h0, l0);
            split2(v.z, v.w, h1, l1);
            *(uint2*)&BsH[kr * BNP + bnc] = make_uint2(h0, h1);
            *(uint2*)&BsL[kr * BNP + bnc] = make_uint2(l0, l1);
        }
        __syncthreads();

#pragma unroll
        for (int ks = 0; ks < 2; ks++) {
            unsigned ah[4][4], al[4][4], bh[4][2], bl[4][2];
            // A fragments: 4 m-tiles
            {
                int row = wM * 64 + (lane & 15);
                int kk  = ks * 16 + (lane >> 4) * 8;
#pragma unroll
                for (int mt = 0; mt < 4; mt++) {
                    int off = (row + mt * 16) * BKP + kk;
                    ldsm4(ah[mt][0], ah[mt][1], ah[mt][2], ah[mt][3], &AsH[off]);
                    ldsm4(al[mt][0], al[mt][1], al[mt][2], al[mt][3], &AsL[off]);
                }
            }
            // B fragments: 2 ldmatrix.x4 cover 4 n-tiles
            {
                int kk = ks * 16 + (lane & 7) + ((lane >> 3) & 1) * 8;
#pragma unroll
                for (int p = 0; p < 2; p++) {
                    int nn = wN * 32 + p * 16 + (lane >> 4) * 8;
                    int off = kk * BNP + nn;
                    unsigned t0, t1, t2, t3;
                    ldsm4t(t0, t1, t2, t3, &BsH[off]);
                    bh[2 * p][0] = t0; bh[2 * p][1] = t1;
                    bh[2 * p + 1][0] = t2; bh[2 * p + 1][1] = t3;
                    ldsm4t(t0, t1, t2, t3, &BsL[off]);
                    bl[2 * p][0] = t0; bl[2 * p][1] = t1;
                    bl[2 * p + 1][0] = t2; bl[2 * p + 1][1] = t3;
                }
            }
#pragma unroll
            for (int mt = 0; mt < 4; mt++)
#pragma unroll
                for (int nt = 0; nt < 4; nt++) {
                    mma16816(acc[mt][nt], ah[mt], bh[nt]);
                    mma16816(acc[mt][nt], ah[mt], bl[nt]);
                    mma16816(acc[mt][nt], al[mt], bh[nt]);
                }
        }
        __syncthreads();
    }

    // ---- epilogue ----
#pragma unroll
    for (int mt = 0; mt < 4; mt++) {
        int r0 = brow + wM * 64 + mt * 16 + (lane >> 2);
#pragma unroll
        for (int nt = 0; nt < 4; nt++) {
            int col = bcol + wN * 32 + nt * 8 + (lane & 3) * 2;
            float b0 = bias ? bias[col] : 0.f;
            float b1 = bias ? bias[col + 1] : 0.f;
            if (r0 < M) {
                float2 v = make_float2(alpha * acc[mt][nt][0] + b0,
                                       alpha * acc[mt][nt][1] + b1);
                *(float2*)&C[(size_t)orow(r0, Lseg, segOff) * N + col] = v;
            }
            if (r0 + 8 < M) {
                float2 v = make_float2(alpha * acc[mt][nt][2] + b0,
                                       alpha * acc[mt][nt][3] + b1);
                *(float2*)&C[(size_t)orow(r0 + 8, Lseg, segOff) * N + col] = v;
            }
        }
    }
}

__global__ __launch_bounds__(256)
void big_gemm(const float* __restrict__ A, const float* __restrict__ W,
              const float* __restrict__ bias, float* __restrict__ C,
              int M, int K, float alpha)
{
    __shared__ __align__(16) unsigned short AsH[128 * BKP], AsL[128 * BKP];
    __shared__ __align__(16) unsigned short BsH[32 * BNP], BsL[32 * BNP];
    gemm_core(A, W, bias, C, M, K, 0, 0, alpha, blockIdx.x, blockIdx.y,
              AsH, AsL, BsH, BsL);
}

struct Seg { const float* A; const float* W; float* C; int M; int Lseg; int segOff; };
struct SegArr { Seg s[12]; };

__global__ __launch_bounds__(256)
void kv_gemm(SegArr P)
{
    __shared__ __align__(16) unsigned short AsH[128 * BKP], AsL[128 * BKP];
    __shared__ __align__(16) unsigned short BsH[32 * BNP], BsL[32 * BNP];
    const Seg s = P.s[blockIdx.z];
    if ((int)blockIdx.y * 128 >= s.M) return;
    gemm_core(s.A, s.W, nullptr, s.C, s.M, Cm, s.Lseg, s.segOff, 1.0f,
              blockIdx.x, blockIdx.y, AsH, AsL, BsH, BsL);
}

// ---------------- fused 3-branch attention (unchanged from R1) ----------------
#define TQ    32
#define QPAD  68
#define SPAD  113
#define ATTN_SMEM_FLOATS (TQ*QPAD + 2*LTOT*DHd + TQ*SPAD)
#define ATTN_SMEM_BYTES  (ATTN_SMEM_FLOATS * 4)

__global__ __launch_bounds__(256)
void attn_kernel()
{
    extern __shared__ float sm[];
    float* Qs = sm;
    float* Ks = Qs + TQ * QPAD;
    float* Vs = Ks + LTOT * DHd;
    float* Sc = Vs + LTOT * DHd;

    const int t  = threadIdx.x;
    const int b  = blockIdx.z;
    const int h  = blockIdx.y;
    const int s0 = blockIdx.x * TQ;

    const float* Qg = g_Q + ((size_t)(b * Sq + s0)) * Dm + h * DHd;
    const float* Kg = g_K + ((size_t)b * LTOT) * Dm + h * DHd;
    const float* Vg = g_V + ((size_t)b * LTOT) * Dm + h * DHd;

    for (int j = t; j < TQ * DHd / 4; j += 256) {
        int r = j >> 4, d4 = (j & 15) * 4;
        *(float4*)(Qs + r * QPAD + d4) = *(const float4*)(Qg + (size_t)r * Dm + d4);
    }
    for (int j = t; j < LTOT * DHd / 4; j += 256) {
        int l = j >> 4, d4 = (j & 15) * 4;
        *(float4*)(Ks + l * DHd + d4) = *(const float4*)(Kg + (size_t)l * Dm + d4);
        *(float4*)(Vs + l * DHd + d4) = *(const float4*)(Vg + (size_t)l * Dm + d4);
    }
    __syncthreads();

    for (int idx = t; idx < TQ * LTOT; idx += 256) {
        int r = idx & 31, l = idx >> 5;
        const float4* qp = (const float4*)(Qs + r * QPAD);
        const float4* kp = (const float4*)(Ks + l * DHd);
        float acc = 0.f;
#pragma unroll
        for (int d = 0; d < DHd / 4; d++) {
            float4 a = qp[d], c = kp[d];
            acc += a.x * c.x + a.y * c.y + a.z * c.z + a.w * c.w;
        }
        Sc[r * SPAD + l] = acc;
    }
    __syncthreads();

    if (t < 96) {
        const int seg0[3] = {0, LT, LT + LI};
        const int seg1[3] = {LT, LT + LI, LTOT};
        int r = t & 31, sg = t >> 5;
        float* row = Sc + r * SPAD;
        int a0 = seg0[sg], a1 = seg1[sg];
        float mx = -1e30f;
        for (int l = a0; l < a1; l++) mx = fmaxf(mx, row[l]);
        float sum = 0.f;
        for (int l = a0; l < a1; l++) { float e = __expf(row[l] - mx); row[l] = e; sum += e; }
        float inv = 1.0f / sum;
        for (int l = a0; l < a1; l++) row[l] *= inv;
    }
    __syncthreads();

    float* Og = g_O + ((size_t)(b * Sq + s0)) * Dm + h * DHd;
    for (int j = t; j < TQ * DHd / 4; j += 256) {
        int r = j >> 4, d4 = (j & 15) * 4;
        const float* prow = Sc + r * SPAD;
        float4 acc = make_float4(0.f, 0.f, 0.f, 0.f);
        for (int l = 0; l < LTOT; l++) {
            float p  = prow[l];
            float4 v = *(const float4*)(Vs + l * DHd + d4);
            acc.x = fmaf(p, v.x, acc.x);
            acc.y = fmaf(p, v.y, acc.y);
            acc.z = fmaf(p, v.z, acc.z);
            acc.w = fmaf(p, v.w, acc.w);
        }
        *(float4*)(Og + (size_t)r * Dm + d4) = acc;
    }
}

// ---------------- launch ----------------
extern "C" void kernel_launch(void* const* d_in, const int* in_sizes, int n_in,
                              void* d_out, int out_size)
{
    const float* hidden  = (const float*)d_in[0];
    const float* text    = (const float*)d_in[1];
    const float* ids     = (const float*)d_in[2];
    const float* hair    = (const float*)d_in[3];
    const float* Wq      = (const float*)d_in[4];
    const float* Wk      = (const float*)d_in[5];
    const float* Wv      = (const float*)d_in[6];
    const float* Wo      = (const float*)d_in[7];
    const float* bo      = (const float*)d_in[8];
    const float* Wk_id   = (const float*)d_in[9];
    const float* Wv_id   = (const float*)d_in[10];
    const float* Wk_hair = (const float*)d_in[11];
    const float* Wv_hair = (const float*)d_in[12];
    float* out = (float*)d_out;

    float *pQ, *pO, *pK, *pV;
    cudaGetSymbolAddress((void**)&pQ, g_Q);
    cudaGetSymbolAddress((void**)&pO, g_O);
    cudaGetSymbolAddress((void**)&pK, g_K);
    cudaGetSymbolAddress((void**)&pV, g_V);

    // Q = 0.125 * hidden @ Wq
    big_gemm<<<dim3(Dm / 128, MQ / 128), 256>>>(hidden, Wq, nullptr, pQ, MQ, Dm, 0.125f);

    // all 6 KV projections in one launch (12 segments: {text,id,hair} x {K,V})
    SegArr P;
    P.s[0]  = { text, Wk,      pK, Bsz * LT, LT, 0 };
    P.s[1]  = { text, Wv,      pV, Bsz * LT, LT, 0 };
    P.s[2]  = { ids,  Wk_id,   pK, Bsz * LI, LI, LT };
    P.s[3]  = { ids,  Wv_id,   pV, Bsz * LI, LI, LT };
    P.s[4]  = { hair, Wk_hair, pK, Bsz * LI, LI, LT + LI };
    P.s[5]  = { hair, Wv_hair, pV, Bsz * LI, LI, LT + LI };
    P.s[6]  = P.s[0]; P.s[7] = P.s[1]; P.s[8] = P.s[2];   // pad (unused z>5 guarded by M via y)
    P.s[9]  = P.s[3]; P.s[10] = P.s[4]; P.s[11] = P.s[5];
    kv_gemm<<<dim3(Dm / 128, 5, 6), 256>>>(P);

    // fused 3-branch attention
    cudaFuncSetAttribute(attn_kernel, cudaFuncAttributeMaxDynamicSharedMemorySize,
                         ATTN_SMEM_BYTES);
    attn_kernel<<<dim3(Sq / TQ, Hn, Bsz), 256, ATTN_SMEM_BYTES>>>();

    // out = g_O @ Wo + bo
    big_gemm<<<dim3(Dm / 128, MQ / 128), 256>>>(pO, Wo, bo, out, MQ, Dm, 1.0f);
}

// round 4
// speedup vs baseline: 3.0454x; 1.1722x over previous
#include <cuda_runtime.h>
#include <cuda_bf16.h>
#include <cstdint>

// ---------------- problem constants ----------------
#define Bsz   8
#define Sq    4096
#define Dm    1280
#define Cm    2048
#define Hn    20
#define DHd   64
#define LT    77
#define LI    16
#define LTOT  109
#define MQ    (Bsz*Sq)

typedef __nv_bfloat16 bf;

// ---------------- scratch (bf16 hi/lo pairs) ----------------
__device__ bf gHh[(size_t)MQ*Dm], gHl[(size_t)MQ*Dm];      // hidden split
__device__ bf gQh[(size_t)MQ*Dm], gQl[(size_t)MQ*Dm];      // Q (scaled) split
__device__ bf gOh[(size_t)MQ*Dm], gOl[(size_t)MQ*Dm];      // attention out split
__device__ bf gTh[(size_t)Bsz*LT*Cm], gTl[(size_t)Bsz*LT*Cm];
__device__ bf gIh[(size_t)Bsz*LI*Cm], gIl[(size_t)Bsz*LI*Cm];
__device__ bf gRh[(size_t)Bsz*LI*Cm], gRl[(size_t)Bsz*LI*Cm];
__device__ bf gKh[(size_t)Bsz*LTOT*Dm], gKl[(size_t)Bsz*LTOT*Dm];
__device__ bf gVh[(size_t)Bsz*LTOT*Dm], gVl[(size_t)Bsz*LTOT*Dm];
__device__ bf gWqH[1280*1280], gWqL[1280*1280];
__device__ bf gWoH[1280*1280], gWoL[1280*1280];
__device__ bf gWkH[2048*1280], gWkL[2048*1280];
__device__ bf gWvH[2048*1280], gWvL[2048*1280];
__device__ bf gWkiH[2048*1280], gWkiL[2048*1280];
__device__ bf gWviH[2048*1280], gWviL[2048*1280];
__device__ bf gWkhH[2048*1280], gWkhL[2048*1280];
__device__ bf gWvhH[2048*1280], gWvhL[2048*1280];

// ---------------- helpers ----------------
__device__ __forceinline__ void split2u(float x, float y, unsigned& hi, unsigned& lo)
{
    __nv_bfloat16 hx = __float2bfloat16_rn(x);
    __nv_bfloat16 hy = __float2bfloat16_rn(y);
    float rx = x - __bfloat162float(hx);
    float ry = y - __bfloat162float(hy);
    __nv_bfloat162 hp = __halves2bfloat162(hx, hy);
    __nv_bfloat162 lp = __halves2bfloat162(__float2bfloat16_rn(rx), __float2bfloat16_rn(ry));
    hi = *reinterpret_cast<unsigned*>(&hp);
    lo = *reinterpret_cast<unsigned*>(&lp);
}

__device__ __forceinline__ void ldsm4(unsigned& r0, unsigned& r1, unsigned& r2, unsigned& r3,
                                      const void* p)
{
    unsigned a = (unsigned)__cvta_generic_to_shared(p);
    asm volatile("ldmatrix.sync.aligned.m8n8.x4.shared.b16 {%0,%1,%2,%3},[%4];"
                 : "=r"(r0), "=r"(r1), "=r"(r2), "=r"(r3) : "r"(a));
}
__device__ __forceinline__ void ldsm4t(unsigned& r0, unsigned& r1, unsigned& r2, unsigned& r3,
                                       const void* p)
{
    unsigned a = (unsigned)__cvta_generic_to_shared(p);
    asm volatile("ldmatrix.sync.aligned.m8n8.x4.trans.shared.b16 {%0,%1,%2,%3},[%4];"
                 : "=r"(r0), "=r"(r1), "=r"(r2), "=r"(r3) : "r"(a));
}
__device__ __forceinline__ void mma16816(float* c, const unsigned* a, const unsigned* b)
{
    asm volatile(
        "mma.sync.aligned.m16n8k16.row.col.f32.bf16.bf16.f32 "
        "{%0,%1,%2,%3}, {%4,%5,%6,%7}, {%8,%9}, {%0,%1,%2,%3};"
        : "+f"(c[0]), "+f"(c[1]), "+f"(c[2]), "+f"(c[3])
        : "r"(a[0]), "r"(a[1]), "r"(a[2]), "r"(a[3]), "r"(b[0]), "r"(b[1]));
}
__device__ __forceinline__ void cpa16(unsigned dst, const void* src, int sz)
{
    asm volatile("cp.async.cg.shared.global [%0], [%1], 16, %2;\n"
                 :: "r"(dst), "l"(src), "r"(sz));
}
#define CP_COMMIT() asm volatile("cp.async.commit_group;\n")
#define CP_WAIT0()  asm volatile("cp.async.wait_group 0;\n")

// FMA-only exp (degree-6 2^f poly, rel err ~2e-6). x <= 0 expected.
__device__ __forceinline__ float fexp(float x)
{
    float t  = x * 1.4426950408889634f;
    float fl = floorf(t);
    float f  = t - fl;
    float p  = 1.5403e-4f;
    p = fmaf(p, f, 1.3333558e-3f);
    p = fmaf(p, f, 9.6181291e-3f);
    p = fmaf(p, f, 5.5504109e-2f);
    p = fmaf(p, f, 2.4022651e-1f);
    p = fmaf(p, f, 6.9314718e-1f);
    p = fmaf(p, f, 1.0f);
    int i = (int)fl;
    i = max(i, -126);
    return p * __int_as_float((i + 127) << 23);
}

__device__ __forceinline__ void splitw(float v, bf& h, bf& l)
{
    h = __float2bfloat16_rn(v);
    l = __float2bfloat16_rn(v - __bfloat162float(h));
}

// ---------------- split kernel: fp32 -> bf16 hi/lo ----------------
__global__ void split_kernel(const float4* __restrict__ src, uint2* __restrict__ dh,
                             uint2* __restrict__ dl, int n4)
{
    int i = blockIdx.x * 256 + threadIdx.x;
    if (i >= n4) return;
    float4 v = src[i];
    unsigned h0, l0, h1, l1;
    split2u(v.x, v.y, h0, l0);
    split2u(v.z, v.w, h1, l1);
    dh[i] = make_uint2(h0, h1);
    dl[i] = make_uint2(l0, l1);
}

// ---------------- bf16-split GEMM (cp.async double-buffered) ----------------
#define BKP 40
#define BNP 136
#define STG_A (128*BKP)          // 5120 elems
#define STG_B (32*BNP)           // 4352 elems
#define STG   (2*STG_A + 2*STG_B)// 18944 elems per stage
#define GEMM_SMEM_BYTES (2*STG*2)// 75776 B

__device__ __forceinline__ int orow(int r, int Lseg, int segOff)
{
    if (Lseg == 0) return r;
    int b = r / Lseg;
    return b * LTOT + segOff + (r - b * Lseg);
}

__device__ __forceinline__ void gemm_dev(
    bf* dynsm, unsigned sbase,
    const bf* __restrict__ Ah, const bf* __restrict__ Al,
    const bf* __restrict__ Wh, const bf* __restrict__ Wl,
    int M, int K, int bx, int by, float alpha, int mode,
    const float* __restrict__ bias, float* __restrict__ outF,
    bf* __restrict__ outH, bf* __restrict__ outL, int Lseg, int segOff)
{
    const int N = Dm;
    const int tid = threadIdx.x, lane = tid & 31, warp = tid >> 5;
    const int wM = warp >> 2, wN = warp & 3;
    const int brow = by * 128, bcol = bx * 128;

    float acc[4][4][4];
#pragma unroll
    for (int i = 0; i < 4; i++)
#pragma unroll
        for (int j = 0; j < 4; j++)
#pragma unroll
            for (int q = 0; q < 4; q++) acc[i][j][q] = 0.f;

    const int nT = K / 32;

    // ---- stage loader (8 cp.async per thread) ----
    auto load_stage = [&](int st, int k0) {
        unsigned aH = sbase + (unsigned)(st * STG) * 2;
        unsigned aL = aH + STG_A * 2;
        unsigned bH = aL + STG_A * 2;
        unsigned bL = bH + STG_B * 2;
#pragma unroll
        for (int u = 0; u < 2; u++) {
            int i   = tid + u * 256;
            int row = i >> 2, k8 = (i & 3) * 8;
            const bf* sH = Ah + (size_t)(brow + row) * K + k0 + k8;
            const bf* sL = Al + (size_t)(brow + row) * K + k0 + k8;
            int ok = 16;
            if (brow + row >= M) { sH = Ah; sL = Al; ok = 0; }
            cpa16(aH + (unsigned)(row * BKP + k8) * 2, sH, ok);
            cpa16(aL + (unsigned)(row * BKP + k8) * 2, sL, ok);
            int kr = i >> 4, n8 = (i & 15) * 8;
            cpa16(bH + (unsigned)(kr * BNP + n8) * 2, Wh + (size_t)(k0 + kr) * N + bcol + n8, 16);
            cpa16(bL + (unsigned)(kr * BNP + n8) * 2, Wl + (size_t)(k0 + kr) * N + bcol + n8, 16);
        }
    };

    load_stage(0, 0);
    CP_COMMIT();

    for (int t = 0; t < nT; t++) {
        CP_WAIT0();
        __syncthreads();
        if (t + 1 < nT) { load_stage((t + 1) & 1, (t + 1) * 32); CP_COMMIT(); }

        bf* AsH = dynsm + (t & 1) * STG;
        bf* AsL = AsH + STG_A;
        bf* BsH = AsL + STG_A;
        bf* BsL = BsH + STG_B;

#pragma unroll
        for (int ks = 0; ks < 2; ks++) {
            unsigned ah[4][4], al[4][4], bh[4][2], bl[4][2];
            {
                int rowb = wM * 64 + (lane & 15);
                int kk   = ks * 16 + (lane >> 4) * 8;
#pragma unroll
                for (int mt = 0; mt < 4; mt++) {
                    int off = (rowb + mt * 16) * BKP + kk;
                    ldsm4(ah[mt][0], ah[mt][1], ah[mt][2], ah[mt][3], AsH + off);
                    ldsm4(al[mt][0], al[mt][1], al[mt][2], al[mt][3], AsL + off);
                }
            }
            {
                int kk = ks * 16 + (lane & 7) + ((lane >> 3) & 1) * 8;
#pragma unroll
                for (int p = 0; p < 2; p++) {
                    int nn = wN * 32 + p * 16 + (lane >> 4) * 8;
                    unsigned t0, t1, t2, t3;
                    ldsm4t(t0, t1, t2, t3, BsH + kk * BNP + nn);
                    bh[2*p][0] = t0; bh[2*p][1] = t1;
                    bh[2*p+1][0] = t2; bh[2*p+1][1] = t3;
                    ldsm4t(t0, t1, t2, t3, BsL + kk * BNP + nn);
                    bl[2*p][0] = t0; bl[2*p][1] = t1;
                    bl[2*p+1][0] = t2; bl[2*p+1][1] = t3;
                }
            }
#pragma unroll
            for (int mt = 0; mt < 4; mt++)
#pragma unroll
                for (int nt = 0; nt < 4; nt++) {
                    mma16816(acc[mt][nt], ah[mt], bh[nt]);
                    mma16816(acc[mt][nt], ah[mt], bl[nt]);
                    mma16816(acc[mt][nt], al[mt], bh[nt]);
                }
        }
        __syncthreads();
    }

    // ---- epilogue ----
#pragma unroll
    for (int mt = 0; mt < 4; mt++) {
        int r0 = brow + wM * 64 + mt * 16 + (lane >> 2);
#pragma unroll
        for (int nt = 0; nt < 4; nt++) {
            int col = bcol + wN * 32 + nt * 8 + (lane & 3) * 2;
#pragma unroll
            for (int half = 0; half < 2; half++) {
                int r = r0 + half * 8;
                if (r >= M) continue;
                float v0 = alpha * acc[mt][nt][half * 2 + 0];
                float v1 = alpha * acc[mt][nt][half * 2 + 1];
                if (mode == 0) {
                    if (bias) { v0 += bias[col]; v1 += bias[col + 1]; }
                    *(float2*)&outF[(size_t)r * N + col] = make_float2(v0, v1);
                } else {
                    bf h0, l0, h1, l1;
                    splitw(v0, h0, l0); splitw(v1, h1, l1);
                    size_t ro = (size_t)orow(r, Lseg, segOff) * N + col;
                    *(__nv_bfloat162*)(outH + ro) = __halves2bfloat162(h0, h1);
                    *(__nv_bfloat162*)(outL + ro) = __halves2bfloat162(l0, l1);
                }
            }
        }
    }
}

__global__ __launch_bounds__(256) void gemm_main(
    const bf* Ah, const bf* Al, const bf* Wh, const bf* Wl,
    const float* bias, float* outF, bf* outH, bf* outL,
    int M, int K, float alpha, int mode)
{
    extern __shared__ __align__(16) bf dynsm_g[];
    unsigned sbase = (unsigned)__cvta_generic_to_shared(dynsm_g);
    gemm_dev(dynsm_g, sbase, Ah, Al, Wh, Wl, M, K, blockIdx.x, blockIdx.y,
             alpha, mode, bias, outF, outH, outL, 0, 0);
}

struct GSeg { const bf *Ah, *Al, *Wh, *Wl; bf *Ch, *Cl; int M, Lseg, segOff; };
struct GSegArr { GSeg s[6]; };

__global__ __launch_bounds__(256) void gemm_kv(GSegArr P)
{
    extern __shared__ __align__(16) bf dynsm_k[];
    const GSeg s = P.s[blockIdx.z];
    if ((int)blockIdx.y * 128 >= s.M) return;
    unsigned sbase = (unsigned)__cvta_generic_to_shared(dynsm_k);
    gemm_dev(dynsm_k, sbase, s.Ah, s.Al, s.Wh, s.Wl, s.M, Cm, blockIdx.x, blockIdx.y,
             1.0f, 2, nullptr, nullptr, s.Ch, s.Cl, s.Lseg, s.segOff);
}

// ---------------- tensor-core fused attention ----------------
// grid (4, Hn, Bsz): block = (b,h) x quarter of S. K^T/V resident in smem.
// 256 threads = 8 warps: wM = warp>>1 (m16 tile of 64 q rows), wN = warp&1.
#define AQS 72
#define AKS 120
#define AVS 72
#define ASS 116
#define O_QH  0
#define O_QL  4608
#define O_KTH 9216
#define O_KTL 16896
#define O_VH  24576
#define O_VL  32640
#define O_PH  40704
#define O_PL  48384
#define O_SF  56064
#define ATT_SMEM_BYTES (O_SF*2 + 64*ASS*4)   // 141824

__global__ __launch_bounds__(256) void attn2()
{
    extern __shared__ __align__(16) bf dynsm_a[];
    bf* Qh  = dynsm_a + O_QH;
    bf* Ql  = dynsm_a + O_QL;
    bf* Kth = dynsm_a + O_KTH;
    bf* Ktl = dynsm_a + O_KTL;
    bf* Vh  = dynsm_a + O_VH;
    bf* Vl  = dynsm_a + O_VL;
    bf* Ph  = dynsm_a + O_PH;
    bf* Pl  = dynsm_a + O_PL;
    float* S = (float*)(dynsm_a + O_SF);

    const int t = threadIdx.x, lane = t & 31, warp = t >> 5;
    const int wM = warp >> 1, wN = warp & 1;
    const int qq = blockIdx.x, h = blockIdx.y, b = blockIdx.z;
    const size_t kvbase = ((size_t)b * LTOT) * Dm + h * 64;

    // ---- K^T (transposed) + V load, once per block ----
    for (int idx = t; idx < LTOT * 64; idx += 256) {
        int l = idx >> 6, d = idx & 63;
        Kth[d * AKS + l] = gKh[kvbase + (size_t)l * Dm + d];
        Ktl[d * AKS + l] = gKl[kvbase + (size_t)l * Dm + d];
    }
    for (int idx = t; idx < LTOT * 8; idx += 256) {
        int l = idx >> 3, j = idx & 7;
        *(uint4*)(Vh + l * AVS + j * 8) = *(const uint4*)(gVh + kvbase + (size_t)l * Dm + j * 8);
        *(uint4*)(Vl + l * AVS + j * 8) = *(const uint4*)(gVl + kvbase + (size_t)l * Dm + j * 8);
    }
    // zero V pad rows 109..111 and P pad cols 109..119 (once)
    uint4 z4 = make_uint4(0, 0, 0, 0);
    for (int idx = t; idx < 3 * 9; idx += 256) {
        int r = LTOT + idx / 9, j = idx % 9;
        *(uint4*)(Vh + r * AVS + j * 8) = z4;
        *(uint4*)(Vl + r * AVS + j * 8) = z4;
    }
    bf bz = __float2bfloat16(0.f);
    for (int idx = t; idx < 64 * 11; idx += 256) {
        int r = idx / 11, c = 109 + idx % 11;
        Ph[r * AKS + c] = bz;
        Pl[r * AKS + c] = bz;
    }
    __syncthreads();

    const int qbase = b * Sq + qq * 1024;

    for (int tile = 0; tile < 16; tile++) {
        int q0 = qbase + tile * 64;
        // load 64x64 Q tile (hi/lo)
        for (int idx = t; idx < 64 * 8; idx += 256) {
            int r = idx >> 3, j = idx & 7;
            size_t go = (size_t)(q0 + r) * Dm + h * 64 + j * 8;
            *(uint4*)(Qh + r * AQS + j * 8) = *(const uint4*)(gQh + go);
            *(uint4*)(Ql + r * AQS + j * 8) = *(const uint4*)(gQl + go);
        }
        __syncthreads();

        // ---- S = Q @ K^T ----
        float accs[8][4];
#pragma unroll
        for (int i = 0; i < 8; i++)
#pragma unroll
            for (int j = 0; j < 4; j++) accs[i][j] = 0.f;

#pragma unroll
        for (int ks = 0; ks < 4; ks++) {
            unsigned ah[4], al[4];
            int aoff = (wM * 16 + (lane & 15)) * AQS + ks * 16 + (lane >> 4) * 8;
            ldsm4(ah[0], ah[1], ah[2], ah[3], Qh + aoff);
            ldsm4(al[0], al[1], al[2], al[3], Ql + aoff);
            int kk = ks * 16 + (lane & 7) + ((lane >> 3) & 1) * 8;
#pragma unroll
            for (int p = 0; p < 4; p++) {
                int nn = wN * 56 + p * 16 + (lane >> 4) * 8;
                unsigned t0, t1, t2, t3;
                ldsm4t(t0, t1, t2, t3, Kth + kk * AKS + nn);
                unsigned bh0[2] = {t0, t1}, bh1[2] = {t2, t3};
                ldsm4t(t0, t1, t2, t3, Ktl + kk * AKS + nn);
                unsigned bl0[2] = {t0, t1}, bl1[2] = {t2, t3};
                mma16816(accs[2*p],   ah, bh0);
                mma16816(accs[2*p],   ah, bl0);
                mma16816(accs[2*p],   al, bh0);
                mma16816(accs[2*p+1], ah, bh1);
                mma16816(accs[2*p+1], ah, bl1);
                mma16816(accs[2*p+1], al, bh1);
            }
        }
        // store S fragments (skip pad tile 14)
#pragma unroll
        for (int nt = 0; nt < 8; nt++) {
            int gnt = wN * 7 + nt;
            if (gnt < 14) {
                int r = wM * 16 + (lane >> 2);
                int c = gnt * 8 + (lane & 3) * 2;
                *(float2*)&S[r * ASS + c]       = make_float2(accs[nt][0], accs[nt][1]);
                *(float2*)&S[(r + 8) * ASS + c] = make_float2(accs[nt][2], accs[nt][3]);
            }
        }
        __syncthreads();

        // ---- per-segment softmax + split-write P ----
        if (t < 192) {
            int r = t & 63, sg = t >> 6;
            int a0 = (sg == 0) ? 0  : (sg == 1 ? LT : LT + LI);
            int a1 = (sg == 0) ? LT : (sg == 1 ? LT + LI : LTOT);
            float* row = S + r * ASS;
            float mx = -1e30f;
            for (int l = a0; l < a1; l++) mx = fmaxf(mx, row[l]);
            float sum = 0.f;
            for (int l = a0; l < a1; l++) { float e = fexp(row[l] - mx); row[l] = e; sum += e; }
            float inv = 1.0f / sum;
            for (int l = a0; l < a1; l++) {
                float p = row[l] * inv;
                bf hh, ll;
                splitw(p, hh, ll);
                Ph[r * AKS + l] = hh;
                Pl[r * AKS + l] = ll;
            }
        }
        __syncthreads();

        // ---- O = P @ V ----
        float acco[4][4];
#pragma unroll
        for (int i = 0; i < 4; i++)
#pragma unroll
            for (int j = 0; j < 4; j++) acco[i][j] = 0.f;

#pragma unroll
        for (int ks = 0; ks < 7; ks++) {
            unsigned ah[4], al[4];
            int aoff = (wM * 16 + (lane & 15)) * AKS + ks * 16 + (lane >> 4) * 8;
            ldsm4(ah[0], ah[1], ah[2], ah[3], Ph + aoff);
            ldsm4(al[0], al[1], al[2], al[3], Pl + aoff);
            int kk = ks * 16 + (lane & 7) + ((lane >> 3) & 1) * 8;
#pragma unroll
            for (int p = 0; p < 2; p++) {
                int nn = wN * 32 + p * 16 + (lane >> 4) * 8;
                unsigned t0, t1, t2, t3;
                ldsm4t(t0, t1, t2, t3, Vh + kk * AVS + nn);
                unsigned bh0[2] = {t0, t1}, bh1[2] = {t2, t3};
                ldsm4t(t0, t1, t2, t3, Vl + kk * AVS + nn);
                unsigned bl0[2] = {t0, t1}, bl1[2] = {t2, t3};
                mma16816(acco[2*p],   ah, bh0);
                mma16816(acco[2*p],   ah, bl0);
                mma16816(acco[2*p],   al, bh0);
                mma16816(acco[2*p+1], ah, bh1);
                mma16816(acco[2*p+1], ah, bl1);
                mma16816(acco[2*p+1], al, bh1);
            }
        }
        // epilogue: split-write O
#pragma unroll
        for (int nt = 0; nt < 4; nt++) {
            int c = h * 64 + wN * 32 + nt * 8 + (lane & 3) * 2;
#pragma unroll
            for (int half = 0; half < 2; half++) {
                int r = wM * 16 + (lane >> 2) + half * 8;
                size_t ro = (size_t)(q0 + r) * Dm + c;
                bf h0, l0, h1, l1;
                splitw(acco[nt][half * 2 + 0], h0, l0);
                splitw(acco[nt][half * 2 + 1], h1, l1);
                *(__nv_bfloat162*)(gOh + ro) = __halves2bfloat162(h0, h1);
                *(__nv_bfloat162*)(gOl + ro) = __halves2bfloat162(l0, l1);
            }
        }
        __syncthreads();
    }
}

// ---------------- launch ----------------
static void do_split(const float* src, bf* dh, bf* dl, size_t n)
{
    int n4 = (int)(n / 4);
    split_kernel<<<(n4 + 255) / 256, 256>>>((const float4*)src, (uint2*)dh, (uint2*)dl, n4);
}

extern "C" void kernel_launch(void* const* d_in, const int* in_sizes, int n_in,
                              void* d_out, int out_size)
{
    const float* hidden  = (const float*)d_in[0];
    const float* text    = (const float*)d_in[1];
    const float* ids     = (const float*)d_in[2];
    const float* hair    = (const float*)d_in[3];
    const float* Wq      = (const float*)d_in[4];
    const float* Wk      = (const float*)d_in[5];
    const float* Wv      = (const float*)d_in[6];
    const float* Wo      = (const float*)d_in[7];
    const float* bo      = (const float*)d_in[8];
    const float* Wk_id   = (const float*)d_in[9];
    const float* Wv_id   = (const float*)d_in[10];
    const float* Wk_hair = (const float*)d_in[11];
    const float* Wv_hair = (const float*)d_in[12];
    float* out = (float*)d_out;

    bf *pHh, *pHl, *pQh, *pQl, *pOh, *pOl, *pTh, *pTl, *pIh, *pIl, *pRh, *pRl;
    bf *pKh, *pKl, *pVh, *pVl;
    bf *pWqH, *pWqL, *pWoH, *pWoL, *pWkH, *pWkL, *pWvH, *pWvL;
    bf *pWkiH, *pWkiL, *pWviH, *pWviL, *pWkhH, *pWkhL, *pWvhH, *pWvhL;
    cudaGetSymbolAddress((void**)&pHh, gHh);   cudaGetSymbolAddress((void**)&pHl, gHl);
    cudaGetSymbolAddress((void**)&pQh, gQh);   cudaGetSymbolAddress((void**)&pQl, gQl);
    cudaGetSymbolAddress((void**)&pOh, gOh);   cudaGetSymbolAddress((void**)&pOl, gOl);
    cudaGetSymbolAddress((void**)&pTh, gTh);   cudaGetSymbolAddress((void**)&pTl, gTl);
    cudaGetSymbolAddress((void**)&pIh, gIh);   cudaGetSymbolAddress((void**)&pIl, gIl);
    cudaGetSymbolAddress((void**)&pRh, gRh);   cudaGetSymbolAddress((void**)&pRl, gRl);
    cudaGetSymbolAddress((void**)&pKh, gKh);   cudaGetSymbolAddress((void**)&pKl, gKl);
    cudaGetSymbolAddress((void**)&pVh, gVh);   cudaGetSymbolAddress((void**)&pVl, gVl);
    cudaGetSymbolAddress((void**)&pWqH, gWqH); cudaGetSymbolAddress((void**)&pWqL, gWqL);
    cudaGetSymbolAddress((void**)&pWoH, gWoH); cudaGetSymbolAddress((void**)&pWoL, gWoL);
    cudaGetSymbolAddress((void**)&pWkH, gWkH); cudaGetSymbolAddress((void**)&pWkL, gWkL);
    cudaGetSymbolAddress((void**)&pWvH, gWvH); cudaGetSymbolAddress((void**)&pWvL, gWvL);
    cudaGetSymbolAddress((void**)&pWkiH, gWkiH); cudaGetSymbolAddress((void**)&pWkiL, gWkiL);
    cudaGetSymbolAddress((void**)&pWviH, gWviH); cudaGetSymbolAddress((void**)&pWviL, gWviL);
    cudaGetSymbolAddress((void**)&pWkhH, gWkhH); cudaGetSymbolAddress((void**)&pWkhL, gWkhL);
    cudaGetSymbolAddress((void**)&pWvhH, gWvhH); cudaGetSymbolAddress((void**)&pWvhL, gWvhL);

    cudaFuncSetAttribute(gemm_main, cudaFuncAttributeMaxDynamicSharedMemorySize, GEMM_SMEM_BYTES);
    cudaFuncSetAttribute(gemm_kv,   cudaFuncAttributeMaxDynamicSharedMemorySize, GEMM_SMEM_BYTES);
    cudaFuncSetAttribute(attn2,     cudaFuncAttributeMaxDynamicSharedMemorySize, ATT_SMEM_BYTES);

    // ---- splits ----
    do_split(hidden,  pHh,  pHl,  (size_t)MQ * Dm);
    do_split(text,    pTh,  pTl,  (size_t)Bsz * LT * Cm);
    do_split(ids,     pIh,  pIl,  (size_t)Bsz * LI * Cm);
    do_split(hair,    pRh,  pRl,  (size_t)Bsz * LI * Cm);
    do_split(Wq,      pWqH, pWqL, (size_t)Dm * Dm);
    do_split(Wo,      pWoH, pWoL, (size_t)Dm * Dm);
    do_split(Wk,      pWkH, pWkL, (size_t)Cm * Dm);
    do_split(Wv,      pWvH, pWvL, (size_t)Cm * Dm);
    do_split(Wk_id,   pWkiH, pWkiL, (size_t)Cm * Dm);
    do_split(Wv_id,   pWviH, pWviL, (size_t)Cm * Dm);
    do_split(Wk_hair, pWkhH, pWkhL, (size_t)Cm * Dm);
    do_split(Wv_hair, pWvhH, pWvhL, (size_t)Cm * Dm);

    // ---- Q projection (scaled, split output) ----
    gemm_main<<<dim3(Dm / 128, MQ / 128), 256, GEMM_SMEM_BYTES>>>(
        pHh, pHl, pWqH, pWqL, nullptr, nullptr, pQh, pQl, MQ, Dm, 0.125f, 1);

    // ---- all 6 KV projections in one launch ----
    GSegArr P;
    P.s[0] = { pTh, pTl, pWkH,  pWkL,  pKh, pKl, Bsz * LT, LT, 0 };
    P.s[1] = { pTh, pTl, pWvH,  pWvL,  pVh, pVl, Bsz * LT, LT, 0 };
    P.s[2] = { pIh, pIl, pWkiH, pWkiL, pKh, pKl, Bsz * LI, LI, LT };
    P.s[3] = { pIh, pIl, pWviH, pWviL, pVh, pVl, Bsz * LI, LI, LT };
    P.s[4] = { pRh, pRl, pWkhH, pWkhL, pKh, pKl, Bsz * LI, LI, LT + LI };
    P.s[5] = { pRh, pRl, pWvhH, pWvhL, pVh, pVl, Bsz * LI, LI, LT + LI };
    gemm_kv<<<dim3(Dm / 128, 5, 6), 256, GEMM_SMEM_BYTES>>>(P);

    // ---- fused tensor-core attention ----
    attn2<<<dim3(4, Hn, Bsz), 256, ATT_SMEM_BYTES>>>();

    // ---- output projection ----
    gemm_main<<<dim3(Dm / 128, MQ / 128), 256, GEMM_SMEM_BYTES>>>(
        pOh, pOl, pWoH, pWoL, bo, out, nullptr, nullptr, MQ, Dm, 1.0f, 0);
}

// round 7
// speedup vs baseline: 3.2466x; 1.0661x over previous
#include <cuda_runtime.h>
#include <cuda_bf16.h>
#include <cstdint>

// ---------------- problem constants ----------------
#define Bsz   8
#define Sq    4096
#define Dm    1280
#define Cm    2048
#define Hn    20
#define DHd   64
#define LT    77
#define LI    16
#define LTOT  109
#define MQ    (Bsz*Sq)

typedef __nv_bfloat16 bf;

// ---------------- scratch (bf16 hi/lo pairs) ----------------
__device__ bf gHh[(size_t)MQ*Dm], gHl[(size_t)MQ*Dm];
__device__ bf gQh[(size_t)MQ*Dm], gQl[(size_t)MQ*Dm];
__device__ bf gOh[(size_t)MQ*Dm], gOl[(size_t)MQ*Dm];
__device__ bf gTh[(size_t)Bsz*LT*Cm], gTl[(size_t)Bsz*LT*Cm];
__device__ bf gIh[(size_t)Bsz*LI*Cm], gIl[(size_t)Bsz*LI*Cm];
__device__ bf gRh[(size_t)Bsz*LI*Cm], gRl[(size_t)Bsz*LI*Cm];
__device__ bf gKh[(size_t)Bsz*LTOT*Dm], gKl[(size_t)Bsz*LTOT*Dm];
__device__ bf gVh[(size_t)Bsz*LTOT*Dm], gVl[(size_t)Bsz*LTOT*Dm];
__device__ bf gWqH[1280*1280], gWqL[1280*1280];
__device__ bf gWoH[1280*1280], gWoL[1280*1280];
__device__ bf gWkH[2048*1280], gWkL[2048*1280];
__device__ bf gWvH[2048*1280], gWvL[2048*1280];
__device__ bf gWkiH[2048*1280], gWkiL[2048*1280];
__device__ bf gWviH[2048*1280], gWviL[2048*1280];
__device__ bf gWkhH[2048*1280], gWkhL[2048*1280];
__device__ bf gWvhH[2048*1280], gWvhL[2048*1280];

// ---------------- helpers ----------------
__device__ __forceinline__ void split2u(float x, float y, unsigned& hi, unsigned& lo)
{
    __nv_bfloat16 hx = __float2bfloat16_rn(x);
    __nv_bfloat16 hy = __float2bfloat16_rn(y);
    float rx = x - __bfloat162float(hx);
    float ry = y - __bfloat162float(hy);
    __nv_bfloat162 hp = __halves2bfloat162(hx, hy);
    __nv_bfloat162 lp = __halves2bfloat162(__float2bfloat16_rn(rx), __float2bfloat16_rn(ry));
    hi = *reinterpret_cast<unsigned*>(&hp);
    lo = *reinterpret_cast<unsigned*>(&lp);
}
__device__ __forceinline__ void splitw(float v, bf& h, bf& l)
{
    h = __float2bfloat16_rn(v);
    l = __float2bfloat16_rn(v - __bfloat162float(h));
}
__device__ __forceinline__ unsigned s2u(const void* p)
{
    return (unsigned)__cvta_generic_to_shared(p);
}
__device__ __forceinline__ void cpa16(unsigned dst, const void* src, int sz)
{
    asm volatile("cp.async.cg.shared.global [%0], [%1], 16, %2;\n"
                 :: "r"(dst), "l"(src), "r"(sz));
}
#define CP_COMMIT() asm volatile("cp.async.commit_group;\n")
#define CP_WAIT0()  asm volatile("cp.async.wait_group 0;\n")

__device__ __forceinline__ void ldsm4(unsigned& r0, unsigned& r1, unsigned& r2, unsigned& r3,
                                      const void* p)
{
    unsigned a = s2u(p);
    asm volatile("ldmatrix.sync.aligned.m8n8.x4.shared.b16 {%0,%1,%2,%3},[%4];"
                 : "=r"(r0), "=r"(r1), "=r"(r2), "=r"(r3) : "r"(a));
}
__device__ __forceinline__ void ldsm4t(unsigned& r0, unsigned& r1, unsigned& r2, unsigned& r3,
                                       const void* p)
{
    unsigned a = s2u(p);
    asm volatile("ldmatrix.sync.aligned.m8n8.x4.trans.shared.b16 {%0,%1,%2,%3},[%4];"
                 : "=r"(r0), "=r"(r1), "=r"(r2), "=r"(r3) : "r"(a));
}
__device__ __forceinline__ void mma16816(float* c, const unsigned* a, const unsigned* b)
{
    asm volatile(
        "mma.sync.aligned.m16n8k16.row.col.f32.bf16.bf16.f32 "
        "{%0,%1,%2,%3}, {%4,%5,%6,%7}, {%8,%9}, {%0,%1,%2,%3};"
        : "+f"(c[0]), "+f"(c[1]), "+f"(c[2]), "+f"(c[3])
        : "r"(a[0]), "r"(a[1]), "r"(a[2]), "r"(a[3]), "r"(b[0]), "r"(b[1]));
}

// FMA-only exp (x <= 0 expected)
__device__ __forceinline__ float fexp(float x)
{
    float t  = x * 1.4426950408889634f;
    float fl = floorf(t);
    float f  = t - fl;
    float p  = 1.5403e-4f;
    p = fmaf(p, f, 1.3333558e-3f);
    p = fmaf(p, f, 9.6181291e-3f);
    p = fmaf(p, f, 5.5504109e-2f);
    p = fmaf(p, f, 2.4022651e-1f);
    p = fmaf(p, f, 6.9314718e-1f);
    p = fmaf(p, f, 1.0f);
    int i = (int)fl;
    i = max(i, -126);
    return p * __int_as_float((i + 127) << 23);
}

// ---------------- split kernels ----------------
__global__ void split_kernel(const float4* __restrict__ src, uint2* __restrict__ dh,
                             uint2* __restrict__ dl, int n4)
{
    int i = blockIdx.x * 256 + threadIdx.x;
    if (i >= n4) return;
    float4 v = src[i];
    unsigned h0, l0, h1, l1;
    split2u(v.x, v.y, h0, l0);
    split2u(v.z, v.w, h1, l1);
    dh[i] = make_uint2(h0, h1);
    dl[i] = make_uint2(l0, l1);
}

// ---------------- bf16-split GEMM (cp.async double-buffered, mma.sync) ----------------
#define BKP 40
#define BNP 136
#define STG_A (128*BKP)
#define STG_B (32*BNP)
#define STG   (2*STG_A + 2*STG_B)
#define GEMM_SMEM_BYTES (2*STG*2)   // 75776

__device__ __forceinline__ int orow(int r, int Lseg, int segOff)
{
    if (Lseg == 0) return r;
    int b = r / Lseg;
    return b * LTOT + segOff + (r - b * Lseg);
}

__device__ __forceinline__ void gemm_dev(
    bf* dynsm, unsigned sbase,
    const bf* __restrict__ Ah, const bf* __restrict__ Al,
    const bf* __restrict__ Wh, const bf* __restrict__ Wl,
    int M, int K, int bx, int by, float alpha, int mode,
    const float* __restrict__ bias, float* __restrict__ outF,
    bf* __restrict__ outH, bf* __restrict__ outL, int Lseg, int segOff)
{
    const int N = Dm;
    const int tid = threadIdx.x, lane = tid & 31, warp = tid >> 5;
    const int wM = warp >> 2, wN = warp & 3;
    const int brow = by * 128, bcol = bx * 128;

    float acc[4][4][4];
#pragma unroll
    for (int i = 0; i < 4; i++)
#pragma unroll
        for (int j = 0; j < 4; j++)
#pragma unroll
            for (int q = 0; q < 4; q++) acc[i][j][q] = 0.f;

    const int nT = K / 32;

    auto load_stage = [&](int st, int k0) {
        unsigned aH = sbase + (unsigned)(st * STG) * 2;
        unsigned aL = aH + STG_A * 2;
        unsigned bH = aL + STG_A * 2;
        unsigned bL = bH + STG_B * 2;
#pragma unroll
        for (int u = 0; u < 2; u++) {
            int i   = tid + u * 256;
            int row = i >> 2, k8 = (i & 3) * 8;
            const bf* sH = Ah + (size_t)(brow + row) * K + k0 + k8;
            const bf* sL = Al + (size_t)(brow + row) * K + k0 + k8;
            int ok = 16;
            if (brow + row >= M) { sH = Ah; sL = Al; ok = 0; }
            cpa16(aH + (unsigned)(row * BKP + k8) * 2, sH, ok);
            cpa16(aL + (unsigned)(row * BKP + k8) * 2, sL, ok);
            int kr = i >> 4, n8 = (i & 15) * 8;
            cpa16(bH + (unsigned)(kr * BNP + n8) * 2, Wh + (size_t)(k0 + kr) * N + bcol + n8, 16);
            cpa16(bL + (unsigned)(kr * BNP + n8) * 2, Wl + (size_t)(k0 + kr) * N + bcol + n8, 16);
        }
    };

    load_stage(0, 0);
    CP_COMMIT();

    for (int t = 0; t < nT; t++) {
        CP_WAIT0();
        __syncthreads();
        if (t + 1 < nT) { load_stage((t + 1) & 1, (t + 1) * 32); CP_COMMIT(); }

        bf* AsH = dynsm + (t & 1) * STG;
        bf* AsL = AsH + STG_A;
        bf* BsH = AsL + STG_A;
        bf* BsL = BsH + STG_B;

#pragma unroll
        for (int ks = 0; ks < 2; ks++) {
            unsigned ah[4][4], al[4][4], bh[4][2], bl[4][2];
            {
                int rowb = wM * 64 + (lane & 15);
                int kk   = ks * 16 + (lane >> 4) * 8;
#pragma unroll
                for (int mt = 0; mt < 4; mt++) {
                    int off = (rowb + mt * 16) * BKP + kk;
                    ldsm4(ah[mt][0], ah[mt][1], ah[mt][2], ah[mt][3], AsH + off);
                    ldsm4(al[mt][0], al[mt][1], al[mt][2], al[mt][3], AsL + off);
                }
            }
            {
                int kk = ks * 16 + (lane & 7) + ((lane >> 3) & 1) * 8;
#pragma unroll
                for (int p = 0; p < 2; p++) {
                    int nn = wN * 32 + p * 16 + (lane >> 4) * 8;
                    unsigned t0, t1, t2, t3;
                    ldsm4t(t0, t1, t2, t3, BsH + kk * BNP + nn);
                    bh[2*p][0] = t0; bh[2*p][1] = t1;
                    bh[2*p+1][0] = t2; bh[2*p+1][1] = t3;
                    ldsm4t(t0, t1, t2, t3, BsL + kk * BNP + nn);
                    bl[2*p][0] = t0; bl[2*p][1] = t1;
                    bl[2*p+1][0] = t2; bl[2*p+1][1] = t3;
                }
            }
#pragma unroll
            for (int mt = 0; mt < 4; mt++)
#pragma unroll
                for (int nt = 0; nt < 4; nt++) {
                    mma16816(acc[mt][nt], ah[mt], bh[nt]);
                    mma16816(acc[mt][nt], ah[mt], bl[nt]);
                    mma16816(acc[mt][nt], al[mt], bh[nt]);
                }
        }
        __syncthreads();
    }

#pragma unroll
    for (int mt = 0; mt < 4; mt++) {
        int r0 = brow + wM * 64 + mt * 16 + (lane >> 2);
#pragma unroll
        for (int nt = 0; nt < 4; nt++) {
            int col = bcol + wN * 32 + nt * 8 + (lane & 3) * 2;
#pragma unroll
            for (int half = 0; half < 2; half++) {
                int r = r0 + half * 8;
                if (r >= M) continue;
                float v0 = alpha * acc[mt][nt][half * 2 + 0];
                float v1 = alpha * acc[mt][nt][half * 2 + 1];
                if (mode == 0) {
                    if (bias) { v0 += bias[col]; v1 += bias[col + 1]; }
                    *(float2*)&outF[(size_t)r * N + col] = make_float2(v0, v1);
                } else {
                    bf h0, l0, h1, l1;
                    splitw(v0, h0, l0); splitw(v1, h1, l1);
                    size_t ro = (size_t)orow(r, Lseg, segOff) * N + col;
                    *(__nv_bfloat162*)(outH + ro) = __halves2bfloat162(h0, h1);
                    *(__nv_bfloat162*)(outL + ro) = __halves2bfloat162(l0, l1);
                }
            }
        }
    }
}

__global__ __launch_bounds__(256, 2) void gemm_main(
    const bf* Ah, const bf* Al, const bf* Wh, const bf* Wl,
    const float* bias, float* outF, bf* outH, bf* outL,
    int M, int K, float alpha, int mode)
{
    extern __shared__ __align__(16) bf dynsm_g[];
    unsigned sbase = (unsigned)__cvta_generic_to_shared(dynsm_g);
    gemm_dev(dynsm_g, sbase, Ah, Al, Wh, Wl, M, K, blockIdx.x, blockIdx.y,
             alpha, mode, bias, outF, outH, outL, 0, 0);
}

struct GSeg { const bf *Ah, *Al, *Wh, *Wl; bf *Ch, *Cl; int M, Lseg, segOff; };
struct GSegArr { GSeg s[6]; };

__global__ __launch_bounds__(256, 2) void gemm_kv(GSegArr P)
{
    extern __shared__ __align__(16) bf dynsm_k[];
    const GSeg s = P.s[blockIdx.z];
    if ((int)blockIdx.y * 128 >= s.M) return;
    unsigned sbase = (unsigned)__cvta_generic_to_shared(dynsm_k);
    gemm_dev(dynsm_k, sbase, s.Ah, s.Al, s.Wh, s.Wl, s.M, Cm, blockIdx.x, blockIdx.y,
             1.0f, 2, nullptr, nullptr, s.Ch, s.Cl, s.Lseg, s.segOff);
}

// ---------------- tensor-core fused attention ----------------
#define AQS 72
#define AKS 120
#define AVS 72
#define ASS 116
#define O_QH  0
#define O_QL  4608
#define O_KTH 9216
#define O_KTL 16896
#define O_VH  24576
#define O_VL  32640
#define O_PH  40704
#define O_PL  48384
#define O_SF  56064
#define ATT_SMEM_BYTES (O_SF*2 + 64*ASS*4)

__global__ __launch_bounds__(256) void attn2()
{
    extern __shared__ __align__(16) bf dynsm_a[];
    bf* Qh  = dynsm_a + O_QH;
    bf* Ql  = dynsm_a + O_QL;
    bf* Kth = dynsm_a + O_KTH;
    bf* Ktl = dynsm_a + O_KTL;
    bf* Vh  = dynsm_a + O_VH;
    bf* Vl  = dynsm_a + O_VL;
    bf* Ph  = dynsm_a + O_PH;
    bf* Pl  = dynsm_a + O_PL;
    float* S = (float*)(dynsm_a + O_SF);

    const int t = threadIdx.x, lane = t & 31, warp = t >> 5;
    const int wM = warp >> 1, wN = warp & 1;
    const int qq = blockIdx.x, h = blockIdx.y, b = blockIdx.z;
    const size_t kvbase = ((size_t)b * LTOT) * Dm + h * 64;

    for (int idx = t; idx < LTOT * 64; idx += 256) {
        int l = idx >> 6, d = idx & 63;
        Kth[d * AKS + l] = gKh[kvbase + (size_t)l * Dm + d];
        Ktl[d * AKS + l] = gKl[kvbase + (size_t)l * Dm + d];
    }
    for (int idx = t; idx < LTOT * 8; idx += 256) {
        int l = idx >> 3, j = idx & 7;
        *(uint4*)(Vh + l * AVS + j * 8) = *(const uint4*)(gVh + kvbase + (size_t)l * Dm + j * 8);
        *(uint4*)(Vl + l * AVS + j * 8) = *(const uint4*)(gVl + kvbase + (size_t)l * Dm + j * 8);
    }
    uint4 z4 = make_uint4(0, 0, 0, 0);
    for (int idx = t; idx < 3 * 9; idx += 256) {
        int r = LTOT + idx / 9, j = idx % 9;
        *(uint4*)(Vh + r * AVS + j * 8) = z4;
        *(uint4*)(Vl + r * AVS + j * 8) = z4;
    }
    bf bz = __float2bfloat16(0.f);
    for (int idx = t; idx < 64 * 11; idx += 256) {
        int r = idx / 11, c = 109 + idx % 11;
        Ph[r * AKS + c] = bz;
        Pl[r * AKS + c] = bz;
    }

    const int qbase = b * Sq + qq * 1024;

    // cp.async Q tile loader (hi+lo: 1024 16B-chunks / 256 threads = 4 each)
    auto loadQ = [&](int tile) {
        int q0 = qbase + tile * 64;
#pragma unroll
        for (int u = 0; u < 2; u++) {
            int i = t + u * 256;
            int r = i >> 3, j = i & 7;
            size_t go = (size_t)(q0 + r) * Dm + h * 64 + j * 8;
            cpa16(s2u(Qh + r * AQS + j * 8), gQh + go, 16);
            cpa16(s2u(Ql + r * AQS + j * 8), gQl + go, 16);
        }
    };

    loadQ(0);
    CP_COMMIT();
    __syncthreads();

    for (int tile = 0; tile < 16; tile++) {
        CP_WAIT0();
        __syncthreads();   // Q(tile) ready for all warps

        // ---- S = Q @ K^T ----
        float accs[8][4];
#pragma unroll
        for (int i = 0; i < 8; i++)
#pragma unroll
            for (int j = 0; j < 4; j++) accs[i][j] = 0.f;

#pragma unroll
        for (int ks = 0; ks < 4; ks++) {
            unsigned ah[4], al[4];
            int aoff = (wM * 16 + (lane & 15)) * AQS + ks * 16 + (lane >> 4) * 8;
            ldsm4(ah[0], ah[1], ah[2], ah[3], Qh + aoff);
            ldsm4(al[0], al[1], al[2], al[3], Ql + aoff);
            int kk = ks * 16 + (lane & 7) + ((lane >> 3) & 1) * 8;
#pragma unroll
            for (int p = 0; p < 4; p++) {
                int nn = wN * 56 + p * 16 + (lane >> 4) * 8;
                unsigned t0, t1, t2, t3;
                ldsm4t(t0, t1, t2, t3, Kth + kk * AKS + nn);
                unsigned bh0[2] = {t0, t1}, bh1[2] = {t2, t3};
                ldsm4t(t0, t1, t2, t3, Ktl + kk * AKS + nn);
                unsigned bl0[2] = {t0, t1}, bl1[2] = {t2, t3};
                mma16816(accs[2*p],   ah, bh0);
                mma16816(accs[2*p],   ah, bl0);
                mma16816(accs[2*p],   al, bh0);
                mma16816(accs[2*p+1], ah, bh1);
                mma16816(accs[2*p+1], ah, bl1);
                mma16816(accs[2*p+1], al, bh1);
            }
        }
#pragma unroll
        for (int nt = 0; nt < 8; nt++) {
            int gnt = wN * 7 + nt;
            if (gnt < 14) {
                int r = wM * 16 + (lane >> 2);
                int c = gnt * 8 + (lane & 3) * 2;
                *(float2*)&S[r * ASS + c]       = make_float2(accs[nt][0], accs[nt][1]);
                *(float2*)&S[(r + 8) * ASS + c] = make_float2(accs[nt][2], accs[nt][3]);
            }
        }
        __syncthreads();   // S complete; Q no longer needed

        // prefetch next Q tile (hidden behind softmax + PV)
        if (tile + 1 < 16) { loadQ(tile + 1); CP_COMMIT(); }

        // ---- parallel per-segment softmax: 4 threads per row ----
        {
            int r = t >> 2, q = t & 3;
            float* row = S + r * ASS;
            float mx0 = -1e30f, mx1 = -1e30f, mx2 = -1e30f;
            for (int l = q; l < LTOT; l += 4) {
                float v = row[l];
                if (l < LT) mx0 = fmaxf(mx0, v);
                else if (l < LT + LI) mx1 = fmaxf(mx1, v);
                else mx2 = fmaxf(mx2, v);
            }
#pragma unroll
            for (int d = 1; d < 4; d <<= 1) {
                mx0 = fmaxf(mx0, __shfl_xor_sync(0xffffffffu, mx0, d));
                mx1 = fmaxf(mx1, __shfl_xor_sync(0xffffffffu, mx1, d));
                mx2 = fmaxf(mx2, __shfl_xor_sync(0xffffffffu, mx2, d));
            }
            float s0 = 0.f, s1 = 0.f, s2 = 0.f;
            for (int l = q; l < LTOT; l += 4) {
                float v = row[l], e;
                if (l < LT)          { e = fexp(v - mx0); s0 += e; }
                else if (l < LT+LI)  { e = fexp(v - mx1); s1 += e; }
                else                 { e = fexp(v - mx2); s2 += e; }
                row[l] = e;
            }
#pragma unroll
            for (int d = 1; d < 4; d <<= 1) {
                s0 += __shfl_xor_sync(0xffffffffu, s0, d);
                s1 += __shfl_xor_sync(0xffffffffu, s1, d);
                s2 += __shfl_xor_sync(0xffffffffu, s2, d);
            }
            float i0 = 1.0f / s0, i1 = 1.0f / s1, i2 = 1.0f / s2;
            for (int l = q; l < LTOT; l += 4) {
                float inv = (l < LT) ? i0 : (l < LT + LI) ? i1 : i2;
                float p = row[l] * inv;
                bf hh, ll;
                splitw(p, hh, ll);
                Ph[r * AKS + l] = hh;
                Pl[r * AKS + l] = ll;
            }
        }
        __syncthreads();

        // ---- O = P @ V ----
        float acco[4][4];
#pragma unroll
        for (int i = 0; i < 4; i++)
#pragma unroll
            for (int j = 0; j < 4; j++) acco[i][j] = 0.f;

#pragma unroll
        for (int ks = 0; ks < 7; ks++) {
            unsigned ah[4], al[4];
            int aoff = (wM * 16 + (lane & 15)) * AKS + ks * 16 + (lane >> 4) * 8;
            ldsm4(ah[0], ah[1], ah[2], ah[3], Ph + aoff);
            ldsm4(al[0], al[1], al[2], al[3], Pl + aoff);
            int kk = ks * 16 + (lane & 7) + ((lane >> 3) & 1) * 8;
#pragma unroll
            for (int p = 0; p < 2; p++) {
                int nn = wN * 32 + p * 16 + (lane >> 4) * 8;
                unsigned t0, t1, t2, t3;
                ldsm4t(t0, t1, t2, t3, Vh + kk * AVS + nn);
                unsigned bh0[2] = {t0, t1}, bh1[2] = {t2, t3};
                ldsm4t(t0, t1, t2, t3, Vl + kk * AVS + nn);
                unsigned bl0[2] = {t0, t1}, bl1[2] = {t2, t3};
                mma16816(acco[2*p],   ah, bh0);
                mma16816(acco[2*p],   ah, bl0);
                mma16816(acco[2*p],   al, bh0);
                mma16816(acco[2*p+1], ah, bh1);
                mma16816(acco[2*p+1], ah, bl1);
                mma16816(acco[2*p+1], al, bh1);
            }
        }
        int q0 = qbase + tile * 64;
#pragma unroll
        for (int nt = 0; nt < 4; nt++) {
            int c = h * 64 + wN * 32 + nt * 8 + (lane & 3) * 2;
#pragma unroll
            for (int half = 0; half < 2; half++) {
                int r = wM * 16 + (lane >> 2) + half * 8;
                size_t ro = (size_t)(q0 + r) * Dm + c;
                bf h0, l0, h1, l1;
                splitw(acco[nt][half * 2 + 0], h0, l0);
                splitw(acco[nt][half * 2 + 1], h1, l1);
                *(__nv_bfloat162*)(gOh + ro) = __halves2bfloat162(h0, h1);
                *(__nv_bfloat162*)(gOl + ro) = __halves2bfloat162(l0, l1);
            }
        }
        __syncthreads();
    }
}

// ---------------- launch ----------------
static void do_split(const float* src, bf* dh, bf* dl, size_t n)
{
    int n4 = (int)(n / 4);
    split_kernel<<<(n4 + 255) / 256, 256>>>((const float4*)src, (uint2*)dh, (uint2*)dl, n4);
}

extern "C" void kernel_launch(void* const* d_in, const int* in_sizes, int n_in,
                              void* d_out, int out_size)
{
    const float* hidden  = (const float*)d_in[0];
    const float* text    = (const float*)d_in[1];
    const float* ids     = (const float*)d_in[2];
    const float* hair    = (const float*)d_in[3];
    const float* Wq      = (const float*)d_in[4];
    const float* Wk      = (const float*)d_in[5];
    const float* Wv      = (const float*)d_in[6];
    const float* Wo      = (const float*)d_in[7];
    const float* bo      = (const float*)d_in[8];
    const float* Wk_id   = (const float*)d_in[9];
    const float* Wv_id   = (const float*)d_in[10];
    const float* Wk_hair = (const float*)d_in[11];
    const float* Wv_hair = (const float*)d_in[12];
    float* out = (float*)d_out;

    bf *pHh, *pHl, *pQh, *pQl, *pOh, *pOl, *pTh, *pTl, *pIh, *pIl, *pRh, *pRl;
    bf *pKh, *pKl, *pVh, *pVl;
    bf *pWqH, *pWqL, *pWoH, *pWoL, *pWkH, *pWkL, *pWvH, *pWvL;
    bf *pWkiH, *pWkiL, *pWviH, *pWviL, *pWkhH, *pWkhL, *pWvhH, *pWvhL;
    cudaGetSymbolAddress((void**)&pHh, gHh);   cudaGetSymbolAddress((void**)&pHl, gHl);
    cudaGetSymbolAddress((void**)&pQh, gQh);   cudaGetSymbolAddress((void**)&pQl, gQl);
    cudaGetSymbolAddress((void**)&pOh, gOh);   cudaGetSymbolAddress((void**)&pOl, gOl);
    cudaGetSymbolAddress((void**)&pTh, gTh);   cudaGetSymbolAddress((void**)&pTl, gTl);
    cudaGetSymbolAddress((void**)&pIh, gIh);   cudaGetSymbolAddress((void**)&pIl, gIl);
    cudaGetSymbolAddress((void**)&pRh, gRh);   cudaGetSymbolAddress((void**)&pRl, gRl);
    cudaGetSymbolAddress((void**)&pKh, gKh);   cudaGetSymbolAddress((void**)&pKl, gKl);
    cudaGetSymbolAddress((void**)&pVh, gVh);   cudaGetSymbolAddress((void**)&pVl, gVl);
    cudaGetSymbolAddress((void**)&pWqH, gWqH); cudaGetSymbolAddress((void**)&pWqL, gWqL);
    cudaGetSymbolAddress((void**)&pWoH, gWoH); cudaGetSymbolAddress((void**)&pWoL, gWoL);
    cudaGetSymbolAddress((void**)&pWkH, gWkH); cudaGetSymbolAddress((void**)&pWkL, gWkL);
    cudaGetSymbolAddress((void**)&pWvH, gWvH); cudaGetSymbolAddress((void**)&pWvL, gWvL);
    cudaGetSymbolAddress((void**)&pWkiH, gWkiH); cudaGetSymbolAddress((void**)&pWkiL, gWkiL);
    cudaGetSymbolAddress((void**)&pWviH, gWviH); cudaGetSymbolAddress((void**)&pWviL, gWviL);
    cudaGetSymbolAddress((void**)&pWkhH, gWkhH); cudaGetSymbolAddress((void**)&pWkhL, gWkhL);
    cudaGetSymbolAddress((void**)&pWvhH, gWvhH); cudaGetSymbolAddress((void**)&pWvhL, gWvhL);

    cudaFuncSetAttribute(gemm_main, cudaFuncAttributeMaxDynamicSharedMemorySize, GEMM_SMEM_BYTES);
    cudaFuncSetAttribute(gemm_kv,   cudaFuncAttributeMaxDynamicSharedMemorySize, GEMM_SMEM_BYTES);
    cudaFuncSetAttribute(attn2,     cudaFuncAttributeMaxDynamicSharedMemorySize, ATT_SMEM_BYTES);

    do_split(hidden,  pHh,  pHl,  (size_t)MQ * Dm);
    do_split(text,    pTh,  pTl,  (size_t)Bsz * LT * Cm);
    do_split(ids,     pIh,  pIl,  (size_t)Bsz * LI * Cm);
    do_split(hair,    pRh,  pRl,  (size_t)Bsz * LI * Cm);
    do_split(Wq,      pWqH, pWqL, (size_t)Dm * Dm);
    do_split(Wo,      pWoH, pWoL, (size_t)Dm * Dm);
    do_split(Wk,      pWkH, pWkL, (size_t)Cm * Dm);
    do_split(Wv,      pWvH, pWvL, (size_t)Cm * Dm);
    do_split(Wk_id,   pWkiH, pWkiL, (size_t)Cm * Dm);
    do_split(Wv_id,   pWviH, pWviL, (size_t)Cm * Dm);
    do_split(Wk_hair, pWkhH, pWkhL, (size_t)Cm * Dm);
    do_split(Wv_hair, pWvhH, pWvhL, (size_t)Cm * Dm);

    gemm_main<<<dim3(Dm / 128, MQ / 128), 256, GEMM_SMEM_BYTES>>>(
        pHh, pHl, pWqH, pWqL, nullptr, nullptr, pQh, pQl, MQ, Dm, 0.125f, 1);

    GSegArr P;
    P.s[0] = { pTh, pTl, pWkH,  pWkL,  pKh, pKl, Bsz * LT, LT, 0 };
    P.s[1] = { pTh, pTl, pWvH,  pWvL,  pVh, pVl, Bsz * LT, LT, 0 };
    P.s[2] = { pIh, pIl, pWkiH, pWkiL, pKh, pKl, Bsz * LI, LI, LT };
    P.s[3] = { pIh, pIl, pWviH, pWviL, pVh, pVl, Bsz * LI, LI, LT };
    P.s[4] = { pRh, pRl, pWkhH, pWkhL, pKh, pKl, Bsz * LI, LI, LT + LI };
    P.s[5] = { pRh, pRl, pWvhH, pWvhL, pVh, pVl, Bsz * LI, LI, LT + LI };
    gemm_kv<<<dim3(Dm / 128, 5, 6), 256, GEMM_SMEM_BYTES>>>(P);

    attn2<<<dim3(4, Hn, Bsz), 256, ATT_SMEM_BYTES>>>();

    gemm_main<<<dim3(Dm / 128, MQ / 128), 256, GEMM_SMEM_BYTES>>>(
        pOh, pOl, pWoH, pWoL, bo, out, nullptr, nullptr, MQ, Dm, 1.0f, 0);
}

// round 8
// speedup vs baseline: 3.8360x; 1.1815x over previous
#include <cuda_runtime.h>
#include <cuda_bf16.h>
#include <cstdint>

// ---------------- problem constants ----------------
#define Bsz   8
#define Sq    4096
#define Dm    1280
#define Cm    2048
#define Hn    20
#define DHd   64
#define LT    77
#define LI    16
#define LTOT  109
#define MQ    (Bsz*Sq)

typedef __nv_bfloat16 bf;

// ---------------- scratch (bf16 hi/lo pairs) ----------------
__device__ bf gHh[(size_t)MQ*Dm], gHl[(size_t)MQ*Dm];
__device__ bf gQh[(size_t)MQ*Dm], gQl[(size_t)MQ*Dm];
__device__ bf gOh[(size_t)MQ*Dm], gOl[(size_t)MQ*Dm];
__device__ bf gTh[(size_t)Bsz*LT*Cm], gTl[(size_t)Bsz*LT*Cm];
__device__ bf gIh[(size_t)Bsz*LI*Cm], gIl[(size_t)Bsz*LI*Cm];
__device__ bf gRh[(size_t)Bsz*LI*Cm], gRl[(size_t)Bsz*LI*Cm];
__device__ bf gKh[(size_t)Bsz*LTOT*Dm], gKl[(size_t)Bsz*LTOT*Dm];
__device__ bf gVh[(size_t)Bsz*LTOT*Dm], gVl[(size_t)Bsz*LTOT*Dm];
__device__ bf gWqH[1280*1280], gWqL[1280*1280];
__device__ bf gWoH[1280*1280], gWoL[1280*1280];
__device__ bf gWkH[2048*1280], gWkL[2048*1280];
__device__ bf gWvH[2048*1280], gWvL[2048*1280];
__device__ bf gWkiH[2048*1280], gWkiL[2048*1280];
__device__ bf gWviH[2048*1280], gWviL[2048*1280];
__device__ bf gWkhH[2048*1280], gWkhL[2048*1280];
__device__ bf gWvhH[2048*1280], gWvhL[2048*1280];

// ---------------- helpers ----------------
__device__ __forceinline__ void split2u(float x, float y, unsigned& hi, unsigned& lo)
{
    __nv_bfloat16 hx = __float2bfloat16_rn(x);
    __nv_bfloat16 hy = __float2bfloat16_rn(y);
    float rx = x - __bfloat162float(hx);
    float ry = y - __bfloat162float(hy);
    __nv_bfloat162 hp = __halves2bfloat162(hx, hy);
    __nv_bfloat162 lp = __halves2bfloat162(__float2bfloat16_rn(rx), __float2bfloat16_rn(ry));
    hi = *reinterpret_cast<unsigned*>(&hp);
    lo = *reinterpret_cast<unsigned*>(&lp);
}
__device__ __forceinline__ void splitw(float v, bf& h, bf& l)
{
    h = __float2bfloat16_rn(v);
    l = __float2bfloat16_rn(v - __bfloat162float(h));
}
__device__ __forceinline__ unsigned s2u(const void* p)
{
    return (unsigned)__cvta_generic_to_shared(p);
}
__device__ __forceinline__ void cpa16(unsigned dst, const void* src, int sz)
{
    asm volatile("cp.async.cg.shared.global [%0], [%1], 16, %2;\n"
                 :: "r"(dst), "l"(src), "r"(sz));
}
#define CP_COMMIT() asm volatile("cp.async.commit_group;\n")
#define CP_WAIT0()  asm volatile("cp.async.wait_group 0;\n")

__device__ __forceinline__ void ldsm4(unsigned& r0, unsigned& r1, unsigned& r2, unsigned& r3,
                                      const void* p)
{
    unsigned a = s2u(p);
    asm volatile("ldmatrix.sync.aligned.m8n8.x4.shared.b16 {%0,%1,%2,%3},[%4];"
                 : "=r"(r0), "=r"(r1), "=r"(r2), "=r"(r3) : "r"(a));
}
__device__ __forceinline__ void ldsm4t(unsigned& r0, unsigned& r1, unsigned& r2, unsigned& r3,
                                       const void* p)
{
    unsigned a = s2u(p);
    asm volatile("ldmatrix.sync.aligned.m8n8.x4.trans.shared.b16 {%0,%1,%2,%3},[%4];"
                 : "=r"(r0), "=r"(r1), "=r"(r2), "=r"(r3) : "r"(a));
}
__device__ __forceinline__ void mma16816(float* c, const unsigned* a, const unsigned* b)
{
    asm volatile(
        "mma.sync.aligned.m16n8k16.row.col.f32.bf16.bf16.f32 "
        "{%0,%1,%2,%3}, {%4,%5,%6,%7}, {%8,%9}, {%0,%1,%2,%3};"
        : "+f"(c[0]), "+f"(c[1]), "+f"(c[2]), "+f"(c[3])
        : "r"(a[0]), "r"(a[1]), "r"(a[2]), "r"(a[3]), "r"(b[0]), "r"(b[1]));
}

// FMA-only exp (x <= 0 expected)
__device__ __forceinline__ float fexp(float x)
{
    float t  = x * 1.4426950408889634f;
    float fl = floorf(t);
    float f  = t - fl;
    float p  = 1.5403e-4f;
    p = fmaf(p, f, 1.3333558e-3f);
    p = fmaf(p, f, 9.6181291e-3f);
    p = fmaf(p, f, 5.5504109e-2f);
    p = fmaf(p, f, 2.4022651e-1f);
    p = fmaf(p, f, 6.9314718e-1f);
    p = fmaf(p, f, 1.0f);
    int i = (int)fl;
    i = max(i, -126);
    return p * __int_as_float((i + 127) << 23);
}

// ---------------- split kernel ----------------
__global__ void split_kernel(const float4* __restrict__ src, uint2* __restrict__ dh,
                             uint2* __restrict__ dl, int n4)
{
    int i = blockIdx.x * 256 + threadIdx.x;
    if (i >= n4) return;
    float4 v = src[i];
    unsigned h0, l0, h1, l1;
    split2u(v.x, v.y, h0, l0);
    split2u(v.z, v.w, h1, l1);
    dh[i] = make_uint2(h0, h1);
    dl[i] = make_uint2(l0, l1);
}

// ---------------- bf16-split GEMM ----------------
#define BKP 40
#define BNP 136
#define STG_A (128*BKP)
#define STG_B (32*BNP)
#define STG   (2*STG_A + 2*STG_B)
#define GEMM_SMEM_BYTES (2*STG*2)

__device__ __forceinline__ int orow(int r, int Lseg, int segOff)
{
    if (Lseg == 0) return r;
    int b = r / Lseg;
    return b * LTOT + segOff + (r - b * Lseg);
}

__device__ __forceinline__ void gemm_dev(
    bf* dynsm, unsigned sbase,
    const bf* __restrict__ Ah, const bf* __restrict__ Al,
    const bf* __restrict__ Wh, const bf* __restrict__ Wl,
    int M, int K, int bx, int by, float alpha, int mode,
    const float* __restrict__ bias, float* __restrict__ outF,
    bf* __restrict__ outH, bf* __restrict__ outL, int Lseg, int segOff)
{
    const int N = Dm;
    const int tid = threadIdx.x, lane = tid & 31, warp = tid >> 5;
    const int wM = warp >> 2, wN = warp & 3;
    const int brow = by * 128, bcol = bx * 128;

    float acc[4][4][4];
#pragma unroll
    for (int i = 0; i < 4; i++)
#pragma unroll
        for (int j = 0; j < 4; j++)
#pragma unroll
            for (int q = 0; q < 4; q++) acc[i][j][q] = 0.f;

    const int nT = K / 32;

    auto load_stage = [&](int st, int k0) {
        unsigned aH = sbase + (unsigned)(st * STG) * 2;
        unsigned aL = aH + STG_A * 2;
        unsigned bH = aL + STG_A * 2;
        unsigned bL = bH + STG_B * 2;
#pragma unroll
        for (int u = 0; u < 2; u++) {
            int i   = tid + u * 256;
            int row = i >> 2, k8 = (i & 3) * 8;
            const bf* sH = Ah + (size_t)(brow + row) * K + k0 + k8;
            const bf* sL = Al + (size_t)(brow + row) * K + k0 + k8;
            int ok = 16;
            if (brow + row >= M) { sH = Ah; sL = Al; ok = 0; }
            cpa16(aH + (unsigned)(row * BKP + k8) * 2, sH, ok);
            cpa16(aL + (unsigned)(row * BKP + k8) * 2, sL, ok);
            int kr = i >> 4, n8 = (i & 15) * 8;
            cpa16(bH + (unsigned)(kr * BNP + n8) * 2, Wh + (size_t)(k0 + kr) * N + bcol + n8, 16);
            cpa16(bL + (unsigned)(kr * BNP + n8) * 2, Wl + (size_t)(k0 + kr) * N + bcol + n8, 16);
        }
    };

    load_stage(0, 0);
    CP_COMMIT();

    for (int t = 0; t < nT; t++) {
        CP_WAIT0();
        __syncthreads();   // single sync per iter: orders compute(t-1) before load(t+1)
        if (t + 1 < nT) { load_stage((t + 1) & 1, (t + 1) * 32); CP_COMMIT(); }

        bf* AsH = dynsm + (t & 1) * STG;
        bf* AsL = AsH + STG_A;
        bf* BsH = AsL + STG_A;
        bf* BsL = BsH + STG_B;

#pragma unroll
        for (int ks = 0; ks < 2; ks++) {
            unsigned ah[4][4], al[4][4], bh[4][2], bl[4][2];
            {
                int rowb = wM * 64 + (lane & 15);
                int kk   = ks * 16 + (lane >> 4) * 8;
#pragma unroll
                for (int mt = 0; mt < 4; mt++) {
                    int off = (rowb + mt * 16) * BKP + kk;
                    ldsm4(ah[mt][0], ah[mt][1], ah[mt][2], ah[mt][3], AsH + off);
                    ldsm4(al[mt][0], al[mt][1], al[mt][2], al[mt][3], AsL + off);
                }
            }
            {
                int kk = ks * 16 + (lane & 7) + ((lane >> 3) & 1) * 8;
#pragma unroll
                for (int p = 0; p < 2; p++) {
                    int nn = wN * 32 + p * 16 + (lane >> 4) * 8;
                    unsigned t0, t1, t2, t3;
                    ldsm4t(t0, t1, t2, t3, BsH + kk * BNP + nn);
                    bh[2*p][0] = t0; bh[2*p][1] = t1;
                    bh[2*p+1][0] = t2; bh[2*p+1][1] = t3;
                    ldsm4t(t0, t1, t2, t3, BsL + kk * BNP + nn);
                    bl[2*p][0] = t0; bl[2*p][1] = t1;
                    bl[2*p+1][0] = t2; bl[2*p+1][1] = t3;
                }
            }
#pragma unroll
            for (int mt = 0; mt < 4; mt++)
#pragma unroll
                for (int nt = 0; nt < 4; nt++) {
                    mma16816(acc[mt][nt], ah[mt], bh[nt]);
                    mma16816(acc[mt][nt], ah[mt], bl[nt]);
                    mma16816(acc[mt][nt], al[mt], bh[nt]);
                }
        }
    }

#pragma unroll
    for (int mt = 0; mt < 4; mt++) {
        int r0 = brow + wM * 64 + mt * 16 + (lane >> 2);
#pragma unroll
        for (int nt = 0; nt < 4; nt++) {
            int col = bcol + wN * 32 + nt * 8 + (lane & 3) * 2;
#pragma unroll
            for (int half = 0; half < 2; half++) {
                int r = r0 + half * 8;
                if (r >= M) continue;
                float v0 = alpha * acc[mt][nt][half * 2 + 0];
                float v1 = alpha * acc[mt][nt][half * 2 + 1];
                if (mode == 0) {
                    if (bias) { v0 += bias[col]; v1 += bias[col + 1]; }
                    *(float2*)&outF[(size_t)r * N + col] = make_float2(v0, v1);
                } else {
                    bf h0, l0, h1, l1;
                    splitw(v0, h0, l0); splitw(v1, h1, l1);
                    size_t ro = (size_t)orow(r, Lseg, segOff) * N + col;
                    *(__nv_bfloat162*)(outH + ro) = __halves2bfloat162(h0, h1);
                    *(__nv_bfloat162*)(outL + ro) = __halves2bfloat162(l0, l1);
                }
            }
        }
    }
}

__global__ __launch_bounds__(256, 2) void gemm_main(
    const bf* Ah, const bf* Al, const bf* Wh, const bf* Wl,
    const float* bias, float* outF, bf* outH, bf* outL,
    int M, int K, float alpha, int mode)
{
    extern __shared__ __align__(16) bf dynsm_g[];
    unsigned sbase = (unsigned)__cvta_generic_to_shared(dynsm_g);
    gemm_dev(dynsm_g, sbase, Ah, Al, Wh, Wl, M, K, blockIdx.x, blockIdx.y,
             alpha, mode, bias, outF, outH, outL, 0, 0);
}

struct GSeg { const bf *Ah, *Al, *Wh, *Wl; bf *Ch, *Cl; int M, Lseg, segOff; };
struct GSegArr { GSeg s[6]; };

__global__ __launch_bounds__(256, 2) void gemm_kv(GSegArr P)
{
    extern __shared__ __align__(16) bf dynsm_k[];
    const GSeg s = P.s[blockIdx.z];
    if ((int)blockIdx.y * 128 >= s.M) return;
    unsigned sbase = (unsigned)__cvta_generic_to_shared(dynsm_k);
    gemm_dev(dynsm_k, sbase, s.Ah, s.Al, s.Wh, s.Wl, s.M, Cm, blockIdx.x, blockIdx.y,
             1.0f, 2, nullptr, nullptr, s.Ch, s.Cl, s.Lseg, s.segOff);
}

// ---------------- register-resident fused attention ----------------
// 128-row Q tile, 8 warps, warp = 16 rows x 112 cols of S (accs[14][4]).
// Softmax in registers (quad shuffles); S fragments reused directly as
// PV A-operand fragments (C-layout == A-layout with bf16x2 packing).
#define TMA2 128
#define AQS 72
#define AKS 120
#define AVS 72
#define A2_QH  0
#define A2_QL  (A2_QH + TMA2*AQS)
#define A2_KTH (A2_QL + TMA2*AQS)
#define A2_KTL (A2_KTH + 64*AKS)
#define A2_VH  (A2_KTL + 64*AKS)
#define A2_VL  (A2_VH + 112*AVS)
#define ATT2_SMEM_BYTES ((A2_VL + 112*AVS) * 2)   // 99840

__global__ __launch_bounds__(256, 2) void attn3()
{
    extern __shared__ __align__(16) bf sm3[];
    bf* Qh  = sm3 + A2_QH;
    bf* Ql  = sm3 + A2_QL;
    bf* Kth = sm3 + A2_KTH;
    bf* Ktl = sm3 + A2_KTL;
    bf* Vh  = sm3 + A2_VH;
    bf* Vl  = sm3 + A2_VL;

    const int t = threadIdx.x, lane = t & 31, warp = t >> 5;
    const int qq = blockIdx.x, h = blockIdx.y, b = blockIdx.z;
    const size_t kvbase = ((size_t)b * LTOT) * Dm + h * 64;

    // K^T load [d=64][l], pad cols 109..111 zero
    for (int idx = t; idx < LTOT * 64; idx += 256) {
        int l = idx >> 6, d = idx & 63;
        Kth[d * AKS + l] = gKh[kvbase + (size_t)l * Dm + d];
        Ktl[d * AKS + l] = gKl[kvbase + (size_t)l * Dm + d];
    }
    if (t < 192) {
        int d = t / 3, l = LTOT + t % 3;
        Kth[d * AKS + l] = __float2bfloat16(0.f);
        Ktl[d * AKS + l] = __float2bfloat16(0.f);
    }
    // V load [l][d], pad rows 109..111 zero
    for (int idx = t; idx < LTOT * 8; idx += 256) {
        int l = idx >> 3, j = idx & 7;
        *(uint4*)(Vh + l * AVS + j * 8) = *(const uint4*)(gVh + kvbase + (size_t)l * Dm + j * 8);
        *(uint4*)(Vl + l * AVS + j * 8) = *(const uint4*)(gVl + kvbase + (size_t)l * Dm + j * 8);
    }
    uint4 z4 = make_uint4(0, 0, 0, 0);
    if (t < 24) {
        int l = LTOT + t / 8, j = t & 7;
        *(uint4*)(Vh + l * AVS + j * 8) = z4;
        *(uint4*)(Vl + l * AVS + j * 8) = z4;
    }

    const int qbase = b * Sq + qq * 2048;

    auto loadQ = [&](int tile) {
        int q0 = qbase + tile * TMA2;
#pragma unroll
        for (int u = 0; u < 4; u++) {
            int i = t + u * 256;
            int r = i >> 3, j = i & 7;
            size_t go = (size_t)(q0 + r) * Dm + h * 64 + j * 8;
            cpa16(s2u(Qh + r * AQS + j * 8), gQh + go, 16);
            cpa16(s2u(Ql + r * AQS + j * 8), gQl + go, 16);
        }
    };

    loadQ(0);
    CP_COMMIT();

    for (int tile = 0; tile < 16; tile++) {
        CP_WAIT0();
        __syncthreads();   // Q(tile) + (tile==0: KT/V) visible

        // ---- S = Q @ K^T : accs[14][4], 16 rows x 112 cols per warp ----
        float accs[14][4];
#pragma unroll
        for (int i = 0; i < 14; i++)
#pragma unroll
            for (int j = 0; j < 4; j++) accs[i][j] = 0.f;

#pragma unroll
        for (int ks = 0; ks < 4; ks++) {
            unsigned ah[4], al[4];
            int aoff = (warp * 16 + (lane & 15)) * AQS + ks * 16 + (lane >> 4) * 8;
            ldsm4(ah[0], ah[1], ah[2], ah[3], Qh + aoff);
            ldsm4(al[0], al[1], al[2], al[3], Ql + aoff);
            int kk = ks * 16 + (lane & 7) + ((lane >> 3) & 1) * 8;
#pragma unroll
            for (int p = 0; p < 7; p++) {
                int nn = p * 16 + (lane >> 4) * 8;
                unsigned t0, t1, t2, t3;
                ldsm4t(t0, t1, t2, t3, Kth + kk * AKS + nn);
                unsigned bh0[2] = {t0, t1}, bh1[2] = {t2, t3};
                ldsm4t(t0, t1, t2, t3, Ktl + kk * AKS + nn);
                unsigned bl0[2] = {t0, t1}, bl1[2] = {t2, t3};
                mma16816(accs[2*p],   ah, bh0);
                mma16816(accs[2*p],   ah, bl0);
                mma16816(accs[2*p],   al, bh0);
                mma16816(accs[2*p+1], ah, bh1);
                mma16816(accs[2*p+1], ah, bl1);
                mma16816(accs[2*p+1], al, bh1);
            }
        }
        __syncthreads();   // all warps done reading Qh/Ql
        if (tile + 1 < 16) { loadQ(tile + 1); CP_COMMIT(); }

        // ---- in-register per-segment softmax (cols live across the quad) ----
        const int cbase = (lane & 3) * 2;
#pragma unroll
        for (int j = 0; j < 2; j++) {         // row halves: regs {0,1} and {2,3}
            float mx0 = -1e30f, mx1 = -1e30f, mx2 = -1e30f;
#pragma unroll
            for (int nt = 0; nt < 14; nt++)
#pragma unroll
                for (int e = 0; e < 2; e++) {
                    int c = nt * 8 + cbase + e;
                    float v = accs[nt][2*j + e];
                    if (c < LT) mx0 = fmaxf(mx0, v);
                    else if (c < LT + LI) mx1 = fmaxf(mx1, v);
                    else if (c < LTOT) mx2 = fmaxf(mx2, v);
                }
#pragma unroll
            for (int d = 1; d < 4; d <<= 1) {
                mx0 = fmaxf(mx0, __shfl_xor_sync(0xffffffffu, mx0, d));
                mx1 = fmaxf(mx1, __shfl_xor_sync(0xffffffffu, mx1, d));
                mx2 = fmaxf(mx2, __shfl_xor_sync(0xffffffffu, mx2, d));
            }
            float s0 = 0.f, s1 = 0.f, s2 = 0.f;
#pragma unroll
            for (int nt = 0; nt < 14; nt++)
#pragma unroll
                for (int e = 0; e < 2; e++) {
                    int c = nt * 8 + cbase + e;
                    float v = accs[nt][2*j + e], r;
                    if (c < LT)           { r = fexp(v - mx0); s0 += r; }
                    else if (c < LT + LI) { r = fexp(v - mx1); s1 += r; }
                    else if (c < LTOT)    { r = fexp(v - mx2); s2 += r; }
                    else r = 0.f;
                    accs[nt][2*j + e] = r;
                }
#pragma unroll
            for (int d = 1; d < 4; d <<= 1) {
                s0 += __shfl_xor_sync(0xffffffffu, s0, d);
                s1 += __shfl_xor_sync(0xffffffffu, s1, d);
                s2 += __shfl_xor_sync(0xffffffffu, s2, d);
            }
            float i0 = 1.0f / s0, i1 = 1.0f / s1, i2 = 1.0f / s2;
#pragma unroll
            for (int nt = 0; nt < 14; nt++)
#pragma unroll
                for (int e = 0; e < 2; e++) {
                    int c = nt * 8 + cbase + e;
                    float inv = (c < LT) ? i0 : (c < LT + LI) ? i1 : i2;
                    accs[nt][2*j + e] *= inv;   // pad cols already 0
                }
        }

        // ---- O = P @ V : P fragments packed straight from accs ----
        float acco[8][4];
#pragma unroll
        for (int i = 0; i < 8; i++)
#pragma unroll
            for (int j = 0; j < 4; j++) acco[i][j] = 0.f;

#pragma unroll
        for (int ks = 0; ks < 7; ks++) {
            unsigned ah[4], al[4];
#pragma unroll
            for (int q = 0; q < 2; q++)
#pragma unroll
                for (int rr = 0; rr < 2; rr++) {
                    float v0 = accs[2*ks + q][2*rr + 0];
                    float v1 = accs[2*ks + q][2*rr + 1];
                    bf h0, l0, h1, l1;
                    splitw(v0, h0, l0);
                    splitw(v1, h1, l1);
                    __nv_bfloat162 hp = __halves2bfloat162(h0, h1);
                    __nv_bfloat162 lp = __halves2bfloat162(l0, l1);
                    ah[q*2 + rr] = *reinterpret_cast<unsigned*>(&hp);
                    al[q*2 + rr] = *reinterpret_cast<unsigned*>(&lp);
                }
            int kk = ks * 16 + (lane & 7) + ((lane >> 3) & 1) * 8;
#pragma unroll
            for (int p = 0; p < 4; p++) {
                int nn = p * 16 + (lane >> 4) * 8;
                unsigned t0, t1, t2, t3;
                ldsm4t(t0, t1, t2, t3, Vh + kk * AVS + nn);
                unsigned bh0[2] = {t0, t1}, bh1[2] = {t2, t3};
                ldsm4t(t0, t1, t2, t3, Vl + kk * AVS + nn);
                unsigned bl0[2] = {t0, t1}, bl1[2] = {t2, t3};
                mma16816(acco[2*p],   ah, bh0);
                mma16816(acco[2*p],   ah, bl0);
                mma16816(acco[2*p],   al, bh0);
                mma16816(acco[2*p+1], ah, bh1);
                mma16816(acco[2*p+1], ah, bl1);
                mma16816(acco[2*p+1], al, bh1);
            }
        }

        // ---- epilogue: split-write O ----
        int q0 = qbase + tile * TMA2;
#pragma unroll
        for (int nt = 0; nt < 8; nt++) {
            int c = h * 64 + nt * 8 + (lane & 3) * 2;
#pragma unroll
            for (int half = 0; half < 2; half++) {
                int r = warp * 16 + (lane >> 2) + half * 8;
                size_t ro = (size_t)(q0 + r) * Dm + c;
                bf h0, l0, h1, l1;
                splitw(acco[nt][half * 2 + 0], h0, l0);
                splitw(acco[nt][half * 2 + 1], h1, l1);
                *(__nv_bfloat162*)(gOh + ro) = __halves2bfloat162(h0, h1);
                *(__nv_bfloat162*)(gOl + ro) = __halves2bfloat162(l0, l1);
            }
        }
    }
}

// ---------------- launch ----------------
static void do_split(const float* src, bf* dh, bf* dl, size_t n)
{
    int n4 = (int)(n / 4);
    split_kernel<<<(n4 + 255) / 256, 256>>>((const float4*)src, (uint2*)dh, (uint2*)dl, n4);
}

extern "C" void kernel_launch(void* const* d_in, const int* in_sizes, int n_in,
                              void* d_out, int out_size)
{
    const float* hidden  = (const float*)d_in[0];
    const float* text    = (const float*)d_in[1];
    const float* ids     = (const float*)d_in[2];
    const float* hair    = (const float*)d_in[3];
    const float* Wq      = (const float*)d_in[4];
    const float* Wk      = (const float*)d_in[5];
    const float* Wv      = (const float*)d_in[6];
    const float* Wo      = (const float*)d_in[7];
    const float* bo      = (const float*)d_in[8];
    const float* Wk_id   = (const float*)d_in[9];
    const float* Wv_id   = (const float*)d_in[10];
    const float* Wk_hair = (const float*)d_in[11];
    const float* Wv_hair = (const float*)d_in[12];
    float* out = (float*)d_out;

    bf *pHh, *pHl, *pQh, *pQl, *pOh, *pOl, *pTh, *pTl, *pIh, *pIl, *pRh, *pRl;
    bf *pKh, *pKl, *pVh, *pVl;
    bf *pWqH, *pWqL, *pWoH, *pWoL, *pWkH, *pWkL, *pWvH, *pWvL;
    bf *pWkiH, *pWkiL, *pWviH, *pWviL, *pWkhH, *pWkhL, *pWvhH, *pWvhL;
    cudaGetSymbolAddress((void**)&pHh, gHh);   cudaGetSymbolAddress((void**)&pHl, gHl);
    cudaGetSymbolAddress((void**)&pQh, gQh);   cudaGetSymbolAddress((void**)&pQl, gQl);
    cudaGetSymbolAddress((void**)&pOh, gOh);   cudaGetSymbolAddress((void**)&pOl, gOl);
    cudaGetSymbolAddress((void**)&pTh, gTh);   cudaGetSymbolAddress((void**)&pTl, gTl);
    cudaGetSymbolAddress((void**)&pIh, gIh);   cudaGetSymbolAddress((void**)&pIl, gIl);
    cudaGetSymbolAddress((void**)&pRh, gRh);   cudaGetSymbolAddress((void**)&pRl, gRl);
    cudaGetSymbolAddress((void**)&pKh, gKh);   cudaGetSymbolAddress((void**)&pKl, gKl);
    cudaGetSymbolAddress((void**)&pVh, gVh);   cudaGetSymbolAddress((void**)&pVl, gVl);
    cudaGetSymbolAddress((void**)&pWqH, gWqH); cudaGetSymbolAddress((void**)&pWqL, gWqL);
    cudaGetSymbolAddress((void**)&pWoH, gWoH); cudaGetSymbolAddress((void**)&pWoL, gWoL);
    cudaGetSymbolAddress((void**)&pWkH, gWkH); cudaGetSymbolAddress((void**)&pWkL, gWkL);
    cudaGetSymbolAddress((void**)&pWvH, gWvH); cudaGetSymbolAddress((void**)&pWvL, gWvL);
    cudaGetSymbolAddress((void**)&pWkiH, gWkiH); cudaGetSymbolAddress((void**)&pWkiL, gWkiL);
    cudaGetSymbolAddress((void**)&pWviH, gWviH); cudaGetSymbolAddress((void**)&pWviL, gWviL);
    cudaGetSymbolAddress((void**)&pWkhH, gWkhH); cudaGetSymbolAddress((void**)&pWkhL, gWkhL);
    cudaGetSymbolAddress((void**)&pWvhH, gWvhH); cudaGetSymbolAddress((void**)&pWvhL, gWvhL);

    cudaFuncSetAttribute(gemm_main, cudaFuncAttributeMaxDynamicSharedMemorySize, GEMM_SMEM_BYTES);
    cudaFuncSetAttribute(gemm_kv,   cudaFuncAttributeMaxDynamicSharedMemorySize, GEMM_SMEM_BYTES);
    cudaFuncSetAttribute(attn3,     cudaFuncAttributeMaxDynamicSharedMemorySize, ATT2_SMEM_BYTES);

    // launches 1-5: the splits the Q GEMM needs (so launch #6 = gemm_main for ncu -s 5 -c 1)
    do_split(hidden,  pHh,  pHl,  (size_t)MQ * Dm);
    do_split(Wq,      pWqH, pWqL, (size_t)Dm * Dm);
    do_split(text,    pTh,  pTl,  (size_t)Bsz * LT * Cm);
    do_split(ids,     pIh,  pIl,  (size_t)Bsz * LI * Cm);
    do_split(hair,    pRh,  pRl,  (size_t)Bsz * LI * Cm);

    // launch 6: Q projection (profiled next round)
    gemm_main<<<dim3(Dm / 128, MQ / 128), 256, GEMM_SMEM_BYTES>>>(
        pHh, pHl, pWqH, pWqL, nullptr, nullptr, pQh, pQl, MQ, Dm, 0.125f, 1);

    // remaining weight splits
    do_split(Wk,      pWkH, pWkL, (size_t)Cm * Dm);
    do_split(Wv,      pWvH, pWvL, (size_t)Cm * Dm);
    do_split(Wk_id,   pWkiH, pWkiL, (size_t)Cm * Dm);
    do_split(Wv_id,   pWviH, pWviL, (size_t)Cm * Dm);
    do_split(Wk_hair, pWkhH, pWkhL, (size_t)Cm * Dm);
    do_split(Wv_hair, pWvhH, pWvhL, (size_t)Cm * Dm);
    do_split(Wo,      pWoH, pWoL, (size_t)Dm * Dm);

    GSegArr P;
    P.s[0] = { pTh, pTl, pWkH,  pWkL,  pKh, pKl, Bsz * LT, LT, 0 };
    P.s[1] = { pTh, pTl, pWvH,  pWvL,  pVh, pVl, Bsz * LT, LT, 0 };
    P.s[2] = { pIh, pIl, pWkiH, pWkiL, pKh, pKl, Bsz * LI, LI, LT };
    P.s[3] = { pIh, pIl, pWviH, pWviL, pVh, pVl, Bsz * LI, LI, LT };
    P.s[4] = { pRh, pRl, pWkhH, pWkhL, pKh, pKl, Bsz * LI, LI, LT + LI };
    P.s[5] = { pRh, pRl, pWvhH, pWvhL, pVh, pVl, Bsz * LI, LI, LT + LI };
    gemm_kv<<<dim3(Dm / 128, 5, 6), 256, GEMM_SMEM_BYTES>>>(P);

    attn3<<<dim3(2, Hn, Bsz), 256, ATT2_SMEM_BYTES>>>();

    gemm_main<<<dim3(Dm / 128, MQ / 128), 256, GEMM_SMEM_BYTES>>>(
        pOh, pOl, pWoH, pWoL, bo, out, nullptr, nullptr, MQ, Dm, 1.0f, 0);
}

// round 9
// speedup vs baseline: 3.9948x; 1.0414x over previous
#include <cuda_runtime.h>
#include <cuda_bf16.h>
#include <cstdint>

// ---------------- problem constants ----------------
#define Bsz   8
#define Sq    4096
#define Dm    1280
#define Cm    2048
#define Hn    20
#define DHd   64
#define LT    77
#define LI    16
#define LTOT  109
#define MQ    (Bsz*Sq)

typedef __nv_bfloat16 bf;

// ---------------- scratch (bf16 hi/lo pairs) ----------------
__device__ bf gHh[(size_t)MQ*Dm], gHl[(size_t)MQ*Dm];
__device__ bf gQh[(size_t)MQ*Dm], gQl[(size_t)MQ*Dm];
__device__ bf gOh[(size_t)MQ*Dm], gOl[(size_t)MQ*Dm];
__device__ bf gTh[(size_t)Bsz*LT*Cm], gTl[(size_t)Bsz*LT*Cm];
__device__ bf gIh[(size_t)Bsz*LI*Cm], gIl[(size_t)Bsz*LI*Cm];
__device__ bf gRh[(size_t)Bsz*LI*Cm], gRl[(size_t)Bsz*LI*Cm];
__device__ bf gKh[(size_t)Bsz*LTOT*Dm], gKl[(size_t)Bsz*LTOT*Dm];
__device__ bf gVh[(size_t)Bsz*LTOT*Dm], gVl[(size_t)Bsz*LTOT*Dm];
__device__ bf gWqH[1280*1280], gWqL[1280*1280];
__device__ bf gWoH[1280*1280], gWoL[1280*1280];
__device__ bf gWkH[2048*1280], gWkL[2048*1280];
__device__ bf gWvH[2048*1280], gWvL[2048*1280];
__device__ bf gWkiH[2048*1280], gWkiL[2048*1280];
__device__ bf gWviH[2048*1280], gWviL[2048*1280];
__device__ bf gWkhH[2048*1280], gWkhL[2048*1280];
__device__ bf gWvhH[2048*1280], gWvhL[2048*1280];

// ---------------- helpers ----------------
__device__ __forceinline__ void split2u(float x, float y, unsigned& hi, unsigned& lo)
{
    __nv_bfloat16 hx = __float2bfloat16_rn(x);
    __nv_bfloat16 hy = __float2bfloat16_rn(y);
    float rx = x - __bfloat162float(hx);
    float ry = y - __bfloat162float(hy);
    __nv_bfloat162 hp = __halves2bfloat162(hx, hy);
    __nv_bfloat162 lp = __halves2bfloat162(__float2bfloat16_rn(rx), __float2bfloat16_rn(ry));
    hi = *reinterpret_cast<unsigned*>(&hp);
    lo = *reinterpret_cast<unsigned*>(&lp);
}
__device__ __forceinline__ void splitw(float v, bf& h, bf& l)
{
    h = __float2bfloat16_rn(v);
    l = __float2bfloat16_rn(v - __bfloat162float(h));
}
__device__ __forceinline__ unsigned s2u(const void* p)
{
    return (unsigned)__cvta_generic_to_shared(p);
}
__device__ __forceinline__ void cpa16(unsigned dst, const void* src, int sz)
{
    asm volatile("cp.async.cg.shared.global [%0], [%1], 16, %2;\n"
                 :: "r"(dst), "l"(src), "r"(sz));
}
#define CP_COMMIT() asm volatile("cp.async.commit_group;\n")
#define CP_WAIT0()  asm volatile("cp.async.wait_group 0;\n")

__device__ __forceinline__ void ldsm4(unsigned& r0, unsigned& r1, unsigned& r2, unsigned& r3,
                                      const void* p)
{
    unsigned a = s2u(p);
    asm volatile("ldmatrix.sync.aligned.m8n8.x4.shared.b16 {%0,%1,%2,%3},[%4];"
                 : "=r"(r0), "=r"(r1), "=r"(r2), "=r"(r3) : "r"(a));
}
__device__ __forceinline__ void ldsm4t(unsigned& r0, unsigned& r1, unsigned& r2, unsigned& r3,
                                       const void* p)
{
    unsigned a = s2u(p);
    asm volatile("ldmatrix.sync.aligned.m8n8.x4.trans.shared.b16 {%0,%1,%2,%3},[%4];"
                 : "=r"(r0), "=r"(r1), "=r"(r2), "=r"(r3) : "r"(a));
}
__device__ __forceinline__ void mma16816(float* c, const unsigned* a, const unsigned* b)
{
    asm volatile(
        "mma.sync.aligned.m16n8k16.row.col.f32.bf16.bf16.f32 "
        "{%0,%1,%2,%3}, {%4,%5,%6,%7}, {%8,%9}, {%0,%1,%2,%3};"
        : "+f"(c[0]), "+f"(c[1]), "+f"(c[2]), "+f"(c[3])
        : "r"(a[0]), "r"(a[1]), "r"(a[2]), "r"(a[3]), "r"(b[0]), "r"(b[1]));
}

// FMA-only exp (x <= 0 expected)
__device__ __forceinline__ float fexp(float x)
{
    float t  = x * 1.4426950408889634f;
    float fl = floorf(t);
    float f  = t - fl;
    float p  = 1.5403e-4f;
    p = fmaf(p, f, 1.3333558e-3f);
    p = fmaf(p, f, 9.6181291e-3f);
    p = fmaf(p, f, 5.5504109e-2f);
    p = fmaf(p, f, 2.4022651e-1f);
    p = fmaf(p, f, 6.9314718e-1f);
    p = fmaf(p, f, 1.0f);
    int i = (int)fl;
    i = max(i, -126);
    return p * __int_as_float((i + 127) << 23);
}

// ---------------- batched split kernel ----------------
struct SplitSeg { const float4* src; uint2* dh; uint2* dl; int off; int n4; };
struct SplitArr { SplitSeg s[8]; int cnt; };

__global__ __launch_bounds__(256) void split_batch(SplitArr P)
{
    int gid = blockIdx.x * 256 + threadIdx.x;
#pragma unroll 1
    for (int sg = 0; sg < P.cnt; sg++) {
        int local = gid - P.s[sg].off;
        if (local >= 0 && local < P.s[sg].n4) {
            float4 v = P.s[sg].src[local];
            unsigned h0, l0, h1, l1;
            split2u(v.x, v.y, h0, l0);
            split2u(v.z, v.w, h1, l1);
            P.s[sg].dh[local] = make_uint2(h0, h1);
            P.s[sg].dl[local] = make_uint2(l0, l1);
            return;
        }
    }
}

// ---------------- bf16-split GEMM ----------------
#define BKP 40
#define BNP 136
#define STG_A (128*BKP)
#define STG_B (32*BNP)
#define STG   (2*STG_A + 2*STG_B)
#define GEMM_SMEM_BYTES (2*STG*2)

__device__ __forceinline__ int orow(int r, int Lseg, int segOff)
{
    if (Lseg == 0) return r;
    int b = r / Lseg;
    return b * LTOT + segOff + (r - b * Lseg);
}

__device__ __forceinline__ void gemm_dev(
    bf* dynsm, unsigned sbase,
    const bf* __restrict__ Ah, const bf* __restrict__ Al,
    const bf* __restrict__ Wh, const bf* __restrict__ Wl,
    int M, int K, int bx, int by, float alpha, int mode,
    const float* __restrict__ bias, float* __restrict__ outF,
    bf* __restrict__ outH, bf* __restrict__ outL, int Lseg, int segOff)
{
    const int N = Dm;
    const int tid = threadIdx.x, lane = tid & 31, warp = tid >> 5;
    const int wM = warp >> 2, wN = warp & 3;
    const int brow = by * 128, bcol = bx * 128;

    float acc[4][4][4];
#pragma unroll
    for (int i = 0; i < 4; i++)
#pragma unroll
        for (int j = 0; j < 4; j++)
#pragma unroll
            for (int q = 0; q < 4; q++) acc[i][j][q] = 0.f;

    const int nT = K / 32;

    auto load_stage = [&](int st, int k0) {
        unsigned aH = sbase + (unsigned)(st * STG) * 2;
        unsigned aL = aH + STG_A * 2;
        unsigned bH = aL + STG_A * 2;
        unsigned bL = bH + STG_B * 2;
#pragma unroll
        for (int u = 0; u < 2; u++) {
            int i   = tid + u * 256;
            int row = i >> 2, k8 = (i & 3) * 8;
            const bf* sH = Ah + (size_t)(brow + row) * K + k0 + k8;
            const bf* sL = Al + (size_t)(brow + row) * K + k0 + k8;
            int ok = 16;
            if (brow + row >= M) { sH = Ah; sL = Al; ok = 0; }
            cpa16(aH + (unsigned)(row * BKP + k8) * 2, sH, ok);
            cpa16(aL + (unsigned)(row * BKP + k8) * 2, sL, ok);
            int kr = i >> 4, n8 = (i & 15) * 8;
            cpa16(bH + (unsigned)(kr * BNP + n8) * 2, Wh + (size_t)(k0 + kr) * N + bcol + n8, 16);
            cpa16(bL + (unsigned)(kr * BNP + n8) * 2, Wl + (size_t)(k0 + kr) * N + bcol + n8, 16);
        }
    };

    load_stage(0, 0);
    CP_COMMIT();

    for (int t = 0; t < nT; t++) {
        CP_WAIT0();
        __syncthreads();
        if (t + 1 < nT) { load_stage((t + 1) & 1, (t + 1) * 32); CP_COMMIT(); }

        bf* AsH = dynsm + (t & 1) * STG;
        bf* AsL = AsH + STG_A;
        bf* BsH = AsL + STG_A;
        bf* BsL = BsH + STG_B;

#pragma unroll
        for (int ks = 0; ks < 2; ks++) {
            unsigned ah[4][4], al[4][4], bh[4][2], bl[4][2];
            {
                int rowb = wM * 64 + (lane & 15);
                int kk   = ks * 16 + (lane >> 4) * 8;
#pragma unroll
                for (int mt = 0; mt < 4; mt++) {
                    int off = (rowb + mt * 16) * BKP + kk;
                    ldsm4(ah[mt][0], ah[mt][1], ah[mt][2], ah[mt][3], AsH + off);
                    ldsm4(al[mt][0], al[mt][1], al[mt][2], al[mt][3], AsL + off);
                }
            }
            {
                int kk = ks * 16 + (lane & 7) + ((lane >> 3) & 1) * 8;
#pragma unroll
                for (int p = 0; p < 2; p++) {
                    int nn = wN * 32 + p * 16 + (lane >> 4) * 8;
                    unsigned t0, t1, t2, t3;
                    ldsm4t(t0, t1, t2, t3, BsH + kk * BNP + nn);
                    bh[2*p][0] = t0; bh[2*p][1] = t1;
                    bh[2*p+1][0] = t2; bh[2*p+1][1] = t3;
                    ldsm4t(t0, t1, t2, t3, BsL + kk * BNP + nn);
                    bl[2*p][0] = t0; bl[2*p][1] = t1;
                    bl[2*p+1][0] = t2; bl[2*p+1][1] = t3;
                }
            }
#pragma unroll
            for (int mt = 0; mt < 4; mt++)
#pragma unroll
                for (int nt = 0; nt < 4; nt++) {
                    mma16816(acc[mt][nt], ah[mt], bh[nt]);
                    mma16816(acc[mt][nt], ah[mt], bl[nt]);
                    mma16816(acc[mt][nt], al[mt], bh[nt]);
                }
        }
    }

#pragma unroll
    for (int mt = 0; mt < 4; mt++) {
        int r0 = brow + wM * 64 + mt * 16 + (lane >> 2);
#pragma unroll
        for (int nt = 0; nt < 4; nt++) {
            int col = bcol + wN * 32 + nt * 8 + (lane & 3) * 2;
#pragma unroll
            for (int half = 0; half < 2; half++) {
                int r = r0 + half * 8;
                if (r >= M) continue;
                float v0 = alpha * acc[mt][nt][half * 2 + 0];
                float v1 = alpha * acc[mt][nt][half * 2 + 1];
                if (mode == 0) {
                    if (bias) { v0 += bias[col]; v1 += bias[col + 1]; }
                    *(float2*)&outF[(size_t)r * N + col] = make_float2(v0, v1);
                } else {
                    bf h0, l0, h1, l1;
                    splitw(v0, h0, l0); splitw(v1, h1, l1);
                    size_t ro = (size_t)orow(r, Lseg, segOff) * N + col;
                    *(__nv_bfloat162*)(outH + ro) = __halves2bfloat162(h0, h1);
                    *(__nv_bfloat162*)(outL + ro) = __halves2bfloat162(l0, l1);
                }
            }
        }
    }
}

__global__ __launch_bounds__(256, 2) void gemm_main(
    const bf* Ah, const bf* Al, const bf* Wh, const bf* Wl,
    const float* bias, float* outF, bf* outH, bf* outL,
    int M, int K, float alpha, int mode)
{
    extern __shared__ __align__(16) bf dynsm_g[];
    unsigned sbase = (unsigned)__cvta_generic_to_shared(dynsm_g);
    gemm_dev(dynsm_g, sbase, Ah, Al, Wh, Wl, M, K, blockIdx.x, blockIdx.y,
             alpha, mode, bias, outF, outH, outL, 0, 0);
}

struct GSeg { const bf *Ah, *Al, *Wh, *Wl; bf *Ch, *Cl; int M, Lseg, segOff; };
struct GSegArr { GSeg s[6]; };

__global__ __launch_bounds__(256, 2) void gemm_kv(GSegArr P)
{
    extern __shared__ __align__(16) bf dynsm_k[];
    const GSeg s = P.s[blockIdx.z];
    if ((int)blockIdx.y * 128 >= s.M) return;
    unsigned sbase = (unsigned)__cvta_generic_to_shared(dynsm_k);
    gemm_dev(dynsm_k, sbase, s.Ah, s.Al, s.Wh, s.Wl, s.M, Cm, blockIdx.x, blockIdx.y,
             1.0f, 2, nullptr, nullptr, s.Ch, s.Cl, s.Lseg, s.segOff);
}

// ---------------- register-resident fused attention ----------------
// 128-row Q tile, 8 warps, warp = 16 rows x 112 cols of S (accs[14][4]).
// grid (8, Hn, Bsz): 4 tiles per block -> 1280 blocks (kills wave-quant tail).
#define TMA2 128
#define NTILE 4
#define AQS 72
#define AKS 120
#define AVS 72
#define A2_QH  0
#define A2_QL  (A2_QH + TMA2*AQS)
#define A2_KTH (A2_QL + TMA2*AQS)
#define A2_KTL (A2_KTH + 64*AKS)
#define A2_VH  (A2_KTL + 64*AKS)
#define A2_VL  (A2_VH + 112*AVS)
#define ATT2_SMEM_BYTES ((A2_VL + 112*AVS) * 2)   // 99840

__global__ __launch_bounds__(256, 2) void attn3()
{
    extern __shared__ __align__(16) bf sm3[];
    bf* Qh  = sm3 + A2_QH;
    bf* Ql  = sm3 + A2_QL;
    bf* Kth = sm3 + A2_KTH;
    bf* Ktl = sm3 + A2_KTL;
    bf* Vh  = sm3 + A2_VH;
    bf* Vl  = sm3 + A2_VL;

    const int t = threadIdx.x, lane = t & 31, warp = t >> 5;
    const int qq = blockIdx.x, h = blockIdx.y, b = blockIdx.z;
    const size_t kvbase = ((size_t)b * LTOT) * Dm + h * 64;

    // K^T load [d=64][l], pad cols 109..111 zero
    for (int idx = t; idx < LTOT * 64; idx += 256) {
        int l = idx >> 6, d = idx & 63;
        Kth[d * AKS + l] = gKh[kvbase + (size_t)l * Dm + d];
        Ktl[d * AKS + l] = gKl[kvbase + (size_t)l * Dm + d];
    }
    if (t < 192) {
        int d = t / 3, l = LTOT + t % 3;
        Kth[d * AKS + l] = __float2bfloat16(0.f);
        Ktl[d * AKS + l] = __float2bfloat16(0.f);
    }
    // V load [l][d], pad rows 109..111 zero
    for (int idx = t; idx < LTOT * 8; idx += 256) {
        int l = idx >> 3, j = idx & 7;
        *(uint4*)(Vh + l * AVS + j * 8) = *(const uint4*)(gVh + kvbase + (size_t)l * Dm + j * 8);
        *(uint4*)(Vl + l * AVS + j * 8) = *(const uint4*)(gVl + kvbase + (size_t)l * Dm + j * 8);
    }
    uint4 z4 = make_uint4(0, 0, 0, 0);
    if (t < 24) {
        int l = LTOT + t / 8, j = t & 7;
        *(uint4*)(Vh + l * AVS + j * 8) = z4;
        *(uint4*)(Vl + l * AVS + j * 8) = z4;
    }

    const int qbase = b * Sq + qq * (TMA2 * NTILE);

    auto loadQ = [&](int tile) {
        int q0 = qbase + tile * TMA2;
#pragma unroll
        for (int u = 0; u < 4; u++) {
            int i = t + u * 256;
            int r = i >> 3, j = i & 7;
            size_t go = (size_t)(q0 + r) * Dm + h * 64 + j * 8;
            cpa16(s2u(Qh + r * AQS + j * 8), gQh + go, 16);
            cpa16(s2u(Ql + r * AQS + j * 8), gQl + go, 16);
        }
    };

    loadQ(0);
    CP_COMMIT();

    for (int tile = 0; tile < NTILE; tile++) {
        CP_WAIT0();
        __syncthreads();

        // ---- S = Q @ K^T ----
        float accs[14][4];
#pragma unroll
        for (int i = 0; i < 14; i++)
#pragma unroll
            for (int j = 0; j < 4; j++) accs[i][j] = 0.f;

#pragma unroll
        for (int ks = 0; ks < 4; ks++) {
            unsigned ah[4], al[4];
            int aoff = (warp * 16 + (lane & 15)) * AQS + ks * 16 + (lane >> 4) * 8;
            ldsm4(ah[0], ah[1], ah[2], ah[3], Qh + aoff);
            ldsm4(al[0], al[1], al[2], al[3], Ql + aoff);
            int kk = ks * 16 + (lane & 7) + ((lane >> 3) & 1) * 8;
#pragma unroll
            for (int p = 0; p < 7; p++) {
                int nn = p * 16 + (lane >> 4) * 8;
                unsigned t0, t1, t2, t3;
                ldsm4t(t0, t1, t2, t3, Kth + kk * AKS + nn);
                unsigned bh0[2] = {t0, t1}, bh1[2] = {t2, t3};
                ldsm4t(t0, t1, t2, t3, Ktl + kk * AKS + nn);
                unsigned bl0[2] = {t0, t1}, bl1[2] = {t2, t3};
                mma16816(accs[2*p],   ah, bh0);
                mma16816(accs[2*p],   ah, bl0);
                mma16816(accs[2*p],   al, bh0);
                mma16816(accs[2*p+1], ah, bh1);
                mma16816(accs[2*p+1], ah, bl1);
                mma16816(accs[2*p+1], al, bh1);
            }
        }
        __syncthreads();
        if (tile + 1 < NTILE) { loadQ(tile + 1); CP_COMMIT(); }

        // ---- in-register per-segment softmax ----
        const int cbase = (lane & 3) * 2;
#pragma unroll
        for (int j = 0; j < 2; j++) {
            float mx0 = -1e30f, mx1 = -1e30f, mx2 = -1e30f;
#pragma unroll
            for (int nt = 0; nt < 14; nt++)
#pragma unroll
                for (int e = 0; e < 2; e++) {
                    int c = nt * 8 + cbase + e;
                    float v = accs[nt][2*j + e];
                    if (c < LT) mx0 = fmaxf(mx0, v);
                    else if (c < LT + LI) mx1 = fmaxf(mx1, v);
                    else if (c < LTOT) mx2 = fmaxf(mx2, v);
                }
#pragma unroll
            for (int d = 1; d < 4; d <<= 1) {
                mx0 = fmaxf(mx0, __shfl_xor_sync(0xffffffffu, mx0, d));
                mx1 = fmaxf(mx1, __shfl_xor_sync(0xffffffffu, mx1, d));
                mx2 = fmaxf(mx2, __shfl_xor_sync(0xffffffffu, mx2, d));
            }
            float s0 = 0.f, s1 = 0.f, s2 = 0.f;
#pragma unroll
            for (int nt = 0; nt < 14; nt++)
#pragma unroll
                for (int e = 0; e < 2; e++) {
                    int c = nt * 8 + cbase + e;
                    float v = accs[nt][2*j + e], r;
                    if (c < LT)           { r = fexp(v - mx0); s0 += r; }
                    else if (c < LT + LI) { r = fexp(v - mx1); s1 += r; }
                    else if (c < LTOT)    { r = fexp(v - mx2); s2 += r; }
                    else r = 0.f;
                    accs[nt][2*j + e] = r;
                }
#pragma unroll
            for (int d = 1; d < 4; d <<= 1) {
                s0 += __shfl_xor_sync(0xffffffffu, s0, d);
                s1 += __shfl_xor_sync(0xffffffffu, s1, d);
                s2 += __shfl_xor_sync(0xffffffffu, s2, d);
            }
            float i0 = 1.0f / s0, i1 = 1.0f / s1, i2 = 1.0f / s2;
#pragma unroll
            for (int nt = 0; nt < 14; nt++)
#pragma unroll
                for (int e = 0; e < 2; e++) {
                    int c = nt * 8 + cbase + e;
                    float inv = (c < LT) ? i0 : (c < LT + LI) ? i1 : i2;
                    accs[nt][2*j + e] *= inv;
                }
        }

        // ---- O = P @ V ----
        float acco[8][4];
#pragma unroll
        for (int i = 0; i < 8; i++)
#pragma unroll
            for (int j = 0; j < 4; j++) acco[i][j] = 0.f;

#pragma unroll
        for (int ks = 0; ks < 7; ks++) {
            unsigned ah[4], al[4];
#pragma unroll
            for (int q = 0; q < 2; q++)
#pragma unroll
                for (int rr = 0; rr < 2; rr++) {
                    float v0 = accs[2*ks + q][2*rr + 0];
                    float v1 = accs[2*ks + q][2*rr + 1];
                    bf h0, l0, h1, l1;
                    splitw(v0, h0, l0);
                    splitw(v1, h1, l1);
                    __nv_bfloat162 hp = __halves2bfloat162(h0, h1);
                    __nv_bfloat162 lp = __halves2bfloat162(l0, l1);
                    ah[q*2 + rr] = *reinterpret_cast<unsigned*>(&hp);
                    al[q*2 + rr] = *reinterpret_cast<unsigned*>(&lp);
                }
            int kk = ks * 16 + (lane & 7) + ((lane >> 3) & 1) * 8;
#pragma unroll
            for (int p = 0; p < 4; p++) {
                int nn = p * 16 + (lane >> 4) * 8;
                unsigned t0, t1, t2, t3;
                ldsm4t(t0, t1, t2, t3, Vh + kk * AVS + nn);
                unsigned bh0[2] = {t0, t1}, bh1[2] = {t2, t3};
                ldsm4t(t0, t1, t2, t3, Vl + kk * AVS + nn);
                unsigned bl0[2] = {t0, t1}, bl1[2] = {t2, t3};
                mma16816(acco[2*p],   ah, bh0);
                mma16816(acco[2*p],   ah, bl0);
                mma16816(acco[2*p],   al, bh0);
                mma16816(acco[2*p+1], ah, bh1);
                mma16816(acco[2*p+1], ah, bl1);
                mma16816(acco[2*p+1], al, bh1);
            }
        }

        int q0 = qbase + tile * TMA2;
#pragma unroll
        for (int nt = 0; nt < 8; nt++) {
            int c = h * 64 + nt * 8 + (lane & 3) * 2;
#pragma unroll
            for (int half = 0; half < 2; half++) {
                int r = warp * 16 + (lane >> 2) + half * 8;
                size_t ro = (size_t)(q0 + r) * Dm + c;
                bf h0, l0, h1, l1;
                splitw(acco[nt][half * 2 + 0], h0, l0);
                splitw(acco[nt][half * 2 + 1], h1, l1);
                *(__nv_bfloat162*)(gOh + ro) = __halves2bfloat162(h0, h1);
                *(__nv_bfloat162*)(gOl + ro) = __halves2bfloat162(l0, l1);
            }
        }
    }
}

// ---------------- launch ----------------
extern "C" void kernel_launch(void* const* d_in, const int* in_sizes, int n_in,
                              void* d_out, int out_size)
{
    const float* hidden  = (const float*)d_in[0];
    const float* text    = (const float*)d_in[1];
    const float* ids     = (const float*)d_in[2];
    const float* hair    = (const float*)d_in[3];
    const float* Wq      = (const float*)d_in[4];
    const float* Wk      = (const float*)d_in[5];
    const float* Wv      = (const float*)d_in[6];
    const float* Wo      = (const float*)d_in[7];
    const float* bo      = (const float*)d_in[8];
    const float* Wk_id   = (const float*)d_in[9];
    const float* Wv_id   = (const float*)d_in[10];
    const float* Wk_hair = (const float*)d_in[11];
    const float* Wv_hair = (const float*)d_in[12];
    float* out = (float*)d_out;

    bf *pHh, *pHl, *pQh, *pQl, *pOh, *pOl, *pTh, *pTl, *pIh, *pIl, *pRh, *pRl;
    bf *pKh, *pKl, *pVh, *pVl;
    bf *pWqH, *pWqL, *pWoH, *pWoL, *pWkH, *pWkL, *pWvH, *pWvL;
    bf *pWkiH, *pWkiL, *pWviH, *pWviL, *pWkhH, *pWkhL, *pWvhH, *pWvhL;
    cudaGetSymbolAddress((void**)&pHh, gHh);   cudaGetSymbolAddress((void**)&pHl, gHl);
    cudaGetSymbolAddress((void**)&pQh, gQh);   cudaGetSymbolAddress((void**)&pQl, gQl);
    cudaGetSymbolAddress((void**)&pOh, gOh);   cudaGetSymbolAddress((void**)&pOl, gOl);
    cudaGetSymbolAddress((void**)&pTh, gTh);   cudaGetSymbolAddress((void**)&pTl, gTl);
    cudaGetSymbolAddress((void**)&pIh, gIh);   cudaGetSymbolAddress((void**)&pIl, gIl);
    cudaGetSymbolAddress((void**)&pRh, gRh);   cudaGetSymbolAddress((void**)&pRl, gRl);
    cudaGetSymbolAddress((void**)&pKh, gKh);   cudaGetSymbolAddress((void**)&pKl, gKl);
    cudaGetSymbolAddress((void**)&pVh, gVh);   cudaGetSymbolAddress((void**)&pVl, gVl);
    cudaGetSymbolAddress((void**)&pWqH, gWqH); cudaGetSymbolAddress((void**)&pWqL, gWqL);
    cudaGetSymbolAddress((void**)&pWoH, gWoH); cudaGetSymbolAddress((void**)&pWoL, gWoL);
    cudaGetSymbolAddress((void**)&pWkH, gWkH); cudaGetSymbolAddress((void**)&pWkL, gWkL);
    cudaGetSymbolAddress((void**)&pWvH, gWvH); cudaGetSymbolAddress((void**)&pWvL, gWvL);
    cudaGetSymbolAddress((void**)&pWkiH, gWkiH); cudaGetSymbolAddress((void**)&pWkiL, gWkiL);
    cudaGetSymbolAddress((void**)&pWviH, gWviH); cudaGetSymbolAddress((void**)&pWviL, gWviL);
    cudaGetSymbolAddress((void**)&pWkhH, gWkhH); cudaGetSymbolAddress((void**)&pWkhL, gWkhL);
    cudaGetSymbolAddress((void**)&pWvhH, gWvhH); cudaGetSymbolAddress((void**)&pWvhL, gWvhL);

    cudaFuncSetAttribute(gemm_main, cudaFuncAttributeMaxDynamicSharedMemorySize, GEMM_SMEM_BYTES);
    cudaFuncSetAttribute(gemm_kv,   cudaFuncAttributeMaxDynamicSharedMemorySize, GEMM_SMEM_BYTES);
    cudaFuncSetAttribute(attn3,     cudaFuncAttributeMaxDynamicSharedMemorySize, ATT2_SMEM_BYTES);

    // ---- launch 1: all activation splits, batched ----
    {
        SplitArr A{};
        int off = 0;
        auto add = [&](int idx, const float* src, bf* dh, bf* dl, size_t n) {
            int n4 = (int)(n / 4);
            A.s[idx] = { (const float4*)src, (uint2*)dh, (uint2*)dl, off, n4 };
            off += n4;
        };
        add(0, hidden, pHh, pHl, (size_t)MQ * Dm);
        add(1, text,   pTh, pTl, (size_t)Bsz * LT * Cm);
        add(2, ids,    pIh, pIl, (size_t)Bsz * LI * Cm);
        add(3, hair,   pRh, pRl, (size_t)Bsz * LI * Cm);
        A.cnt = 4;
        split_batch<<<(off + 255) / 256, 256>>>(A);
    }
    // ---- launch 2: all weight splits, batched ----
    {
        SplitArr W{};
        int off = 0;
        auto add = [&](int idx, const float* src, bf* dh, bf* dl, size_t n) {
            int n4 = (int)(n / 4);
            W.s[idx] = { (const float4*)src, (uint2*)dh, (uint2*)dl, off, n4 };
            off += n4;
        };
        add(0, Wq,      pWqH,  pWqL,  (size_t)Dm * Dm);
        add(1, Wo,      pWoH,  pWoL,  (size_t)Dm * Dm);
        add(2, Wk,      pWkH,  pWkL,  (size_t)Cm * Dm);
        add(3, Wv,      pWvH,  pWvL,  (size_t)Cm * Dm);
        add(4, Wk_id,   pWkiH, pWkiL, (size_t)Cm * Dm);
        add(5, Wv_id,   pWviH, pWviL, (size_t)Cm * Dm);
        add(6, Wk_hair, pWkhH, pWkhL, (size_t)Cm * Dm);
        add(7, Wv_hair, pWvhH, pWvhL, (size_t)Cm * Dm);
        W.cnt = 8;
        split_batch<<<(off + 255) / 256, 256>>>(W);
    }

    // launch 3: Q projection
    gemm_main<<<dim3(Dm / 128, MQ / 128), 256, GEMM_SMEM_BYTES>>>(
        pHh, pHl, pWqH, pWqL, nullptr, nullptr, pQh, pQl, MQ, Dm, 0.125f, 1);

    // launch 4: all 6 KV projections
    GSegArr P;
    P.s[0] = { pTh, pTl, pWkH,  pWkL,  pKh, pKl, Bsz * LT, LT, 0 };
    P.s[1] = { pTh, pTl, pWvH,  pWvL,  pVh, pVl, Bsz * LT, LT, 0 };
    P.s[2] = { pIh, pIl, pWkiH, pWkiL, pKh, pKl, Bsz * LI, LI, LT };
    P.s[3] = { pIh, pIl, pWviH, pWviL, pVh, pVl, Bsz * LI, LI, LT };
    P.s[4] = { pRh, pRl, pWkhH, pWkhL, pKh, pKl, Bsz * LI, LI, LT + LI };
    P.s[5] = { pRh, pRl, pWvhH, pWvhL, pVh, pVl, Bsz * LI, LI, LT + LI };
    gemm_kv<<<dim3(Dm / 128, 5, 6), 256, GEMM_SMEM_BYTES>>>(P);

    // launch 5: fused attention (1280 blocks, 4 tiles each)
    attn3<<<dim3(8, Hn, Bsz), 256, ATT2_SMEM_BYTES>>>();

    // launch 6: output projection
    gemm_main<<<dim3(Dm / 128, MQ / 128), 256, GEMM_SMEM_BYTES>>>(
        pOh, pOl, pWoH, pWoL, bo, out, nullptr, nullptr, MQ, Dm, 1.0f, 0);
}

// round 11
// speedup vs baseline: 4.0676x; 1.0182x over previous
#include <cuda_runtime.h>
#include <cuda_bf16.h>
#include <cstdint>

// ---------------- problem constants ----------------
#define Bsz   8
#define Sq    4096
#define Dm    1280
#define Cm    2048
#define Hn    20
#define DHd   64
#define LT    77
#define LI    16
#define LTOT  109
#define MQ    (Bsz*Sq)

typedef __nv_bfloat16 bf;

// ---------------- scratch (bf16 hi/lo pairs) ----------------
__device__ bf gHh[(size_t)MQ*Dm], gHl[(size_t)MQ*Dm];
__device__ bf gQh[(size_t)MQ*Dm], gQl[(size_t)MQ*Dm];
__device__ bf gOh[(size_t)MQ*Dm], gOl[(size_t)MQ*Dm];
__device__ bf gTh[(size_t)Bsz*LT*Cm], gTl[(size_t)Bsz*LT*Cm];
__device__ bf gIh[(size_t)Bsz*LI*Cm], gIl[(size_t)Bsz*LI*Cm];
__device__ bf gRh[(size_t)Bsz*LI*Cm], gRl[(size_t)Bsz*LI*Cm];
__device__ bf gKh[(size_t)Bsz*LTOT*Dm], gKl[(size_t)Bsz*LTOT*Dm];
__device__ bf gVh[(size_t)Bsz*LTOT*Dm], gVl[(size_t)Bsz*LTOT*Dm];
__device__ bf gWqH[1280*1280], gWqL[1280*1280];
__device__ bf gWoH[1280*1280], gWoL[1280*1280];
__device__ bf gWkH[2048*1280], gWkL[2048*1280];
__device__ bf gWvH[2048*1280], gWvL[2048*1280];
__device__ bf gWkiH[2048*1280], gWkiL[2048*1280];
__device__ bf gWviH[2048*1280], gWviL[2048*1280];
__device__ bf gWkhH[2048*1280], gWkhL[2048*1280];
__device__ bf gWvhH[2048*1280], gWvhL[2048*1280];

// ---------------- helpers ----------------
__device__ __forceinline__ void split2u(float x, float y, unsigned& hi, unsigned& lo)
{
    __nv_bfloat16 hx = __float2bfloat16_rn(x);
    __nv_bfloat16 hy = __float2bfloat16_rn(y);
    float rx = x - __bfloat162float(hx);
    float ry = y - __bfloat162float(hy);
    __nv_bfloat162 hp = __halves2bfloat162(hx, hy);
    __nv_bfloat162 lp = __halves2bfloat162(__float2bfloat16_rn(rx), __float2bfloat16_rn(ry));
    hi = *reinterpret_cast<unsigned*>(&hp);
    lo = *reinterpret_cast<unsigned*>(&lp);
}
__device__ __forceinline__ void splitw(float v, bf& h, bf& l)
{
    h = __float2bfloat16_rn(v);
    l = __float2bfloat16_rn(v - __bfloat162float(h));
}
__device__ __forceinline__ unsigned s2u(const void* p)
{
    return (unsigned)__cvta_generic_to_shared(p);
}
__device__ __forceinline__ void cpa16(unsigned dst, const void* src, int sz)
{
    asm volatile("cp.async.cg.shared.global [%0], [%1], 16, %2;\n"
                 :: "r"(dst), "l"(src), "r"(sz));
}
#define CP_COMMIT() asm volatile("cp.async.commit_group;\n")
#define CP_WAIT0()  asm volatile("cp.async.wait_group 0;\n")

__device__ __forceinline__ void ldsm4(unsigned& r0, unsigned& r1, unsigned& r2, unsigned& r3,
                                      const void* p)
{
    unsigned a = s2u(p);
    asm volatile("ldmatrix.sync.aligned.m8n8.x4.shared.b16 {%0,%1,%2,%3},[%4];"
                 : "=r"(r0), "=r"(r1), "=r"(r2), "=r"(r3) : "r"(a));
}
__device__ __forceinline__ void ldsm4t(unsigned& r0, unsigned& r1, unsigned& r2, unsigned& r3,
                                       const void* p)
{
    unsigned a = s2u(p);
    asm volatile("ldmatrix.sync.aligned.m8n8.x4.trans.shared.b16 {%0,%1,%2,%3},[%4];"
                 : "=r"(r0), "=r"(r1), "=r"(r2), "=r"(r3) : "r"(a));
}
__device__ __forceinline__ void mma16816(float* c, const unsigned* a, const unsigned* b)
{
    asm volatile(
        "mma.sync.aligned.m16n8k16.row.col.f32.bf16.bf16.f32 "
        "{%0,%1,%2,%3}, {%4,%5,%6,%7}, {%8,%9}, {%0,%1,%2,%3};"
        : "+f"(c[0]), "+f"(c[1]), "+f"(c[2]), "+f"(c[3])
        : "r"(a[0]), "r"(a[1]), "r"(a[2]), "r"(a[3]), "r"(b[0]), "r"(b[1]));
}

// FMA-only exp (x <= 0 expected)
__device__ __forceinline__ float fexp(float x)
{
    float t  = x * 1.4426950408889634f;
    float fl = floorf(t);
    float f  = t - fl;
    float p  = 1.5403e-4f;
    p = fmaf(p, f, 1.3333558e-3f);
    p = fmaf(p, f, 9.6181291e-3f);
    p = fmaf(p, f, 5.5504109e-2f);
    p = fmaf(p, f, 2.4022651e-1f);
    p = fmaf(p, f, 6.9314718e-1f);
    p = fmaf(p, f, 1.0f);
    int i = (int)fl;
    i = max(i, -126);
    return p * __int_as_float((i + 127) << 23);
}

// ---------------- batched split kernel (single launch, 12 segments) ----------------
struct SplitSeg { const float4* src; uint2* dh; uint2* dl; int off; int n4; };
struct SplitArr { SplitSeg s[12]; int cnt; };

__global__ __launch_bounds__(256) void split_batch(SplitArr P)
{
    int gid = blockIdx.x * 256 + threadIdx.x;
#pragma unroll 1
    for (int sg = 0; sg < P.cnt; sg++) {
        int local = gid - P.s[sg].off;
        if (local >= 0 && local < P.s[sg].n4) {
            float4 v = P.s[sg].src[local];
            unsigned h0, l0, h1, l1;
            split2u(v.x, v.y, h0, l0);
            split2u(v.z, v.w, h1, l1);
            P.s[sg].dh[local] = make_uint2(h0, h1);
            P.s[sg].dl[local] = make_uint2(l0, l1);
            return;
        }
    }
}

// ---------------- bf16-split GEMM ----------------
#define BKP 40
#define BNP 136
#define STG_A (128*BKP)
#define STG_B (32*BNP)
#define STG   (2*STG_A + 2*STG_B)
#define GEMM_SMEM_BYTES (2*STG*2)

__device__ __forceinline__ int orow(int r, int Lseg, int segOff)
{
    if (Lseg == 0) return r;
    int b = r / Lseg;
    return b * LTOT + segOff + (r - b * Lseg);
}

__device__ __forceinline__ void gemm_dev(
    bf* dynsm, unsigned sbase,
    const bf* __restrict__ Ah, const bf* __restrict__ Al,
    const bf* __restrict__ Wh, const bf* __restrict__ Wl,
    int M, int K, int bx, int by, float alpha, int mode,
    const float* __restrict__ bias, float* __restrict__ outF,
    bf* __restrict__ outH, bf* __restrict__ outL, int Lseg, int segOff)
{
    const int N = Dm;
    const int tid = threadIdx.x, lane = tid & 31, warp = tid >> 5;
    const int wM = warp >> 2, wN = warp & 3;
    const int brow = by * 128, bcol = bx * 128;

    float acc[4][4][4];
#pragma unroll
    for (int i = 0; i < 4; i++)
#pragma unroll
        for (int j = 0; j < 4; j++)
#pragma unroll
            for (int q = 0; q < 4; q++) acc[i][j][q] = 0.f;

    const int nT = K / 32;

    auto load_stage = [&](int st, int k0) {
        unsigned aH = sbase + (unsigned)(st * STG) * 2;
        unsigned aL = aH + STG_A * 2;
        unsigned bH = aL + STG_A * 2;
        unsigned bL = bH + STG_B * 2;
#pragma unroll
        for (int u = 0; u < 2; u++) {
            int i   = tid + u * 256;
            int row = i >> 2, k8 = (i & 3) * 8;
            const bf* sH = Ah + (size_t)(brow + row) * K + k0 + k8;
            const bf* sL = Al + (size_t)(brow + row) * K + k0 + k8;
            int ok = 16;
            if (brow + row >= M) { sH = Ah; sL = Al; ok = 0; }
            cpa16(aH + (unsigned)(row * BKP + k8) * 2, sH, ok);
            cpa16(aL + (unsigned)(row * BKP + k8) * 2, sL, ok);
            int kr = i >> 4, n8 = (i & 15) * 8;
            cpa16(bH + (unsigned)(kr * BNP + n8) * 2, Wh + (size_t)(k0 + kr) * N + bcol + n8, 16);
            cpa16(bL + (unsigned)(kr * BNP + n8) * 2, Wl + (size_t)(k0 + kr) * N + bcol + n8, 16);
        }
    };

    load_stage(0, 0);
    CP_COMMIT();

    for (int t = 0; t < nT; t++) {
        CP_WAIT0();
        __syncthreads();
        if (t + 1 < nT) { load_stage((t + 1) & 1, (t + 1) * 32); CP_COMMIT(); }

        bf* AsH = dynsm + (t & 1) * STG;
        bf* AsL = AsH + STG_A;
        bf* BsH = AsL + STG_A;
        bf* BsL = BsH + STG_B;

#pragma unroll
        for (int ks = 0; ks < 2; ks++) {
            unsigned ah[4][4], al[4][4], bh[4][2], bl[4][2];
            {
                int rowb = wM * 64 + (lane & 15);
                int kk   = ks * 16 + (lane >> 4) * 8;
#pragma unroll
                for (int mt = 0; mt < 4; mt++) {
                    int off = (rowb + mt * 16) * BKP + kk;
                    ldsm4(ah[mt][0], ah[mt][1], ah[mt][2], ah[mt][3], AsH + off);
                    ldsm4(al[mt][0], al[mt][1], al[mt][2], al[mt][3], AsL + off);
                }
            }
            {
                int kk = ks * 16 + (lane & 7) + ((lane >> 3) & 1) * 8;
#pragma unroll
                for (int p = 0; p < 2; p++) {
                    int nn = wN * 32 + p * 16 + (lane >> 4) * 8;
                    unsigned t0, t1, t2, t3;
                    ldsm4t(t0, t1, t2, t3, BsH + kk * BNP + nn);
                    bh[2*p][0] = t0; bh[2*p][1] = t1;
                    bh[2*p+1][0] = t2; bh[2*p+1][1] = t3;
                    ldsm4t(t0, t1, t2, t3, BsL + kk * BNP + nn);
                    bl[2*p][0] = t0; bl[2*p][1] = t1;
                    bl[2*p+1][0] = t2; bl[2*p+1][1] = t3;
                }
            }
#pragma unroll
            for (int mt = 0; mt < 4; mt++)
#pragma unroll
                for (int nt = 0; nt < 4; nt++) {
                    mma16816(acc[mt][nt], ah[mt], bh[nt]);
                    mma16816(acc[mt][nt], ah[mt], bl[nt]);
                    mma16816(acc[mt][nt], al[mt], bh[nt]);
                }
        }
    }

#pragma unroll
    for (int mt = 0; mt < 4; mt++) {
        int r0 = brow + wM * 64 + mt * 16 + (lane >> 2);
#pragma unroll
        for (int nt = 0; nt < 4; nt++) {
            int col = bcol + wN * 32 + nt * 8 + (lane & 3) * 2;
#pragma unroll
            for (int half = 0; half < 2; half++) {
                int r = r0 + half * 8;
                if (r >= M) continue;
                float v0 = alpha * acc[mt][nt][half * 2 + 0];
                float v1 = alpha * acc[mt][nt][half * 2 + 1];
                if (mode == 0) {
                    if (bias) { v0 += bias[col]; v1 += bias[col + 1]; }
                    *(float2*)&outF[(size_t)r * N + col] = make_float2(v0, v1);
                } else {
                    bf h0, l0, h1, l1;
                    splitw(v0, h0, l0); splitw(v1, h1, l1);
                    size_t ro = (size_t)orow(r, Lseg, segOff) * N + col;
                    *(__nv_bfloat162*)(outH + ro) = __halves2bfloat162(h0, h1);
                    *(__nv_bfloat162*)(outL + ro) = __halves2bfloat162(l0, l1);
                }
            }
        }
    }
}

// plain output-projection GEMM launch
__global__ __launch_bounds__(256, 2) void gemm_main(
    const bf* Ah, const bf* Al, const bf* Wh, const bf* Wl,
    const float* bias, float* outF, bf* outH, bf* outL,
    int M, int K, float alpha, int mode)
{
    extern __shared__ __align__(16) bf dynsm_g[];
    unsigned sbase = (unsigned)__cvta_generic_to_shared(dynsm_g);
    gemm_dev(dynsm_g, sbase, Ah, Al, Wh, Wl, M, K, blockIdx.x, blockIdx.y,
             alpha, mode, bias, outF, outH, outL, 0, 0);
}

// fused Q + KV projection launch: 1D grid, Q tiles first, KV tiles fill the tail
struct GSeg { const bf *Ah, *Al, *Wh, *Wl; bf *Ch, *Cl; int M, Lseg, segOff; };
struct GFused {
    const bf *QAh, *QAl, *QWh, *QWl;   // Q gemm operands
    bf *QCh, *QCl;
    GSeg s[6];
};
#define QBLOCKS (10 * (MQ / 128))   // 2560

__global__ __launch_bounds__(256, 2) void gemm_qkv(GFused P)
{
    extern __shared__ __align__(16) bf dynsm_f[];
    unsigned sbase = (unsigned)__cvta_generic_to_shared(dynsm_f);
    int bid = blockIdx.x;
    if (bid < QBLOCKS) {
        int bx = bid % 10, by = bid / 10;
        gemm_dev(dynsm_f, sbase, P.QAh, P.QAl, P.QWh, P.QWl, MQ, Dm, bx, by,
                 0.125f, 1, nullptr, nullptr, P.QCh, P.QCl, 0, 0);
    } else {
        int kid = bid - QBLOCKS;
        int z = kid / 50, rem = kid % 50;
        int by = rem / 10, bx = rem % 10;
        const GSeg s = P.s[z];
        if (by * 128 >= s.M) return;
        gemm_dev(dynsm_f, sbase, s.Ah, s.Al, s.Wh, s.Wl, s.M, Cm, bx, by,
                 1.0f, 2, nullptr, nullptr, s.Ch, s.Cl, s.Lseg, s.segOff);
    }
}

// ---------------- register-resident fused attention ----------------
// 128-row Q tile, 8 warps, warp = 16 rows x 112 cols of S (accs[14][4]).
// grid (16, Hn, Bsz): 2 tiles per block -> 2560 blocks (4% wave-quant tail).
#define TMA2 128
#define NTILE 2
#define AQS 72
#define AKS 120
#define AVS 72
#define A2_QH  0
#define A2_QL  (A2_QH + TMA2*AQS)
#define A2_KTH (A2_QL + TMA2*AQS)
#define A2_KTL (A2_KTH + 64*AKS)
#define A2_VH  (A2_KTL + 64*AKS)
#define A2_VL  (A2_VH + 112*AVS)
#define ATT2_SMEM_BYTES ((A2_VL + 112*AVS) * 2)   // 99840

__global__ __launch_bounds__(256, 2) void attn3()
{
    extern __shared__ __align__(16) bf sm3[];
    bf* Qh  = sm3 + A2_QH;
    bf* Ql  = sm3 + A2_QL;
    bf* Kth = sm3 + A2_KTH;
    bf* Ktl = sm3 + A2_KTL;
    bf* Vh  = sm3 + A2_VH;
    bf* Vl  = sm3 + A2_VL;

    const int t = threadIdx.x, lane = t & 31, warp = t >> 5;
    const int qq = blockIdx.x, h = blockIdx.y, b = blockIdx.z;
    const size_t kvbase = ((size_t)b * LTOT) * Dm + h * 64;

    // K^T load [d=64][l], pad cols 109..111 zero
    for (int idx = t; idx < LTOT * 64; idx += 256) {
        int l = idx >> 6, d = idx & 63;
        Kth[d * AKS + l] = gKh[kvbase + (size_t)l * Dm + d];
        Ktl[d * AKS + l] = gKl[kvbase + (size_t)l * Dm + d];
    }
    if (t < 192) {
        int d = t / 3, l = LTOT + t % 3;
        Kth[d * AKS + l] = __float2bfloat16(0.f);
        Ktl[d * AKS + l] = __float2bfloat16(0.f);
    }
    // V load [l][d], pad rows 109..111 zero
    for (int idx = t; idx < LTOT * 8; idx += 256) {
        int l = idx >> 3, j = idx & 7;
        *(uint4*)(Vh + l * AVS + j * 8) = *(const uint4*)(gVh + kvbase + (size_t)l * Dm + j * 8);
        *(uint4*)(Vl + l * AVS + j * 8) = *(const uint4*)(gVl + kvbase + (size_t)l * Dm + j * 8);
    }
    uint4 z4 = make_uint4(0, 0, 0, 0);
    if (t < 24) {
        int l = LTOT + t / 8, j = t & 7;
        *(uint4*)(Vh + l * AVS + j * 8) = z4;
        *(uint4*)(Vl + l * AVS + j * 8) = z4;
    }

    const int qbase = b * Sq + qq * (TMA2 * NTILE);

    auto loadQ = [&](int tile) {
        int q0 = qbase + tile * TMA2;
#pragma unroll
        for (int u = 0; u < 4; u++) {
            int i = t + u * 256;
            int r = i >> 3, j = i & 7;
            size_t go = (size_t)(q0 + r) * Dm + h * 64 + j * 8;
            cpa16(s2u(Qh + r * AQS + j * 8), gQh + go, 16);
            cpa16(s2u(Ql + r * AQS + j * 8), gQl + go, 16);
        }
    };

    loadQ(0);
    CP_COMMIT();

    for (int tile = 0; tile < NTILE; tile++) {
        CP_WAIT0();
        __syncthreads();

        // ---- S = Q @ K^T ----
        float accs[14][4];
#pragma unroll
        for (int i = 0; i < 14; i++)
#pragma unroll
            for (int j = 0; j < 4; j++) accs[i][j] = 0.f;

#pragma unroll
        for (int ks = 0; ks < 4; ks++) {
            unsigned ah[4], al[4];
            int aoff = (warp * 16 + (lane & 15)) * AQS + ks * 16 + (lane >> 4) * 8;
            ldsm4(ah[0], ah[1], ah[2], ah[3], Qh + aoff);
            ldsm4(al[0], al[1], al[2], al[3], Ql + aoff);
            int kk = ks * 16 + (lane & 7) + ((lane >> 3) & 1) * 8;
#pragma unroll
            for (int p = 0; p < 7; p++) {
                int nn = p * 16 + (lane >> 4) * 8;
                unsigned t0, t1, t2, t3;
                ldsm4t(t0, t1, t2, t3, Kth + kk * AKS + nn);
                unsigned bh0[2] = {t0, t1}, bh1[2] = {t2, t3};
                ldsm4t(t0, t1, t2, t3, Ktl + kk * AKS + nn);
                unsigned bl0[2] = {t0, t1}, bl1[2] = {t2, t3};
                mma16816(accs[2*p],   ah, bh0);
                mma16816(accs[2*p],   ah, bl0);
                mma16816(accs[2*p],   al, bh0);
                mma16816(accs[2*p+1], ah, bh1);
                mma16816(accs[2*p+1], ah, bl1);
                mma16816(accs[2*p+1], al, bh1);
            }
        }
        __syncthreads();
        if (tile + 1 < NTILE) { loadQ(tile + 1); CP_COMMIT(); }

        // ---- in-register per-segment softmax ----
        const int cbase = (lane & 3) * 2;
#pragma unroll
        for (int j = 0; j < 2; j++) {
            float mx0 = -1e30f, mx1 = -1e30f, mx2 = -1e30f;
#pragma unroll
            for (int nt = 0; nt < 14; nt++)
#pragma unroll
                for (int e = 0; e < 2; e++) {
                    int c = nt * 8 + cbase + e;
                    float v = accs[nt][2*j + e];
                    if (c < LT) mx0 = fmaxf(mx0, v);
                    else if (c < LT + LI) mx1 = fmaxf(mx1, v);
                    else if (c < LTOT) mx2 = fmaxf(mx2, v);
                }
#pragma unroll
            for (int d = 1; d < 4; d <<= 1) {
                mx0 = fmaxf(mx0, __shfl_xor_sync(0xffffffffu, mx0, d));
                mx1 = fmaxf(mx1, __shfl_xor_sync(0xffffffffu, mx1, d));
                mx2 = fmaxf(mx2, __shfl_xor_sync(0xffffffffu, mx2, d));
            }
            float s0 = 0.f, s1 = 0.f, s2 = 0.f;
#pragma unroll
            for (int nt = 0; nt < 14; nt++)
#pragma unroll
                for (int e = 0; e < 2; e++) {
                    int c = nt * 8 + cbase + e;
                    float v = accs[nt][2*j + e], r;
                    if (c < LT)           { r = fexp(v - mx0); s0 += r; }
                    else if (c < LT + LI) { r = fexp(v - mx1); s1 += r; }
                    else if (c < LTOT)    { r = fexp(v - mx2); s2 += r; }
                    else r = 0.f;
                    accs[nt][2*j + e] = r;
                }
#pragma unroll
            for (int d = 1; d < 4; d <<= 1) {
                s0 += __shfl_xor_sync(0xffffffffu, s0, d);
                s1 += __shfl_xor_sync(0xffffffffu, s1, d);
                s2 += __shfl_xor_sync(0xffffffffu, s2, d);
            }
            float i0 = 1.0f / s0, i1 = 1.0f / s1, i2 = 1.0f / s2;
#pragma unroll
            for (int nt = 0; nt < 14; nt++)
#pragma unroll
                for (int e = 0; e < 2; e++) {
                    int c = nt * 8 + cbase + e;
                    float inv = (c < LT) ? i0 : (c < LT + LI) ? i1 : i2;
                    accs[nt][2*j + e] *= inv;
                }
        }

        // ---- O = P @ V ----
        float acco[8][4];
#pragma unroll
        for (int i = 0; i < 8; i++)
#pragma unroll
            for (int j = 0; j < 4; j++) acco[i][j] = 0.f;

#pragma unroll
        for (int ks = 0; ks < 7; ks++) {
            unsigned ah[4], al[4];
#pragma unroll
            for (int q = 0; q < 2; q++)
#pragma unroll
                for (int rr = 0; rr < 2; rr++) {
                    float v0 = accs[2*ks + q][2*rr + 0];
                    float v1 = accs[2*ks + q][2*rr + 1];
                    bf h0, l0, h1, l1;
                    splitw(v0, h0, l0);
                    splitw(v1, h1, l1);
                    __nv_bfloat162 hp = __halves2bfloat162(h0, h1);
                    __nv_bfloat162 lp = __halves2bfloat162(l0, l1);
                    ah[q*2 + rr] = *reinterpret_cast<unsigned*>(&hp);
                    al[q*2 + rr] = *reinterpret_cast<unsigned*>(&lp);
                }
            int kk = ks * 16 + (lane & 7) + ((lane >> 3) & 1) * 8;
#pragma unroll
            for (int p = 0; p < 4; p++) {
                int nn = p * 16 + (lane >> 4) * 8;
                unsigned t0, t1, t2, t3;
                ldsm4t(t0, t1, t2, t3, Vh + kk * AVS + nn);
                unsigned bh0[2] = {t0, t1}, bh1[2] = {t2, t3};
                ldsm4t(t0, t1, t2, t3, Vl + kk * AVS + nn);
                unsigned bl0[2] = {t0, t1}, bl1[2] = {t2, t3};
                mma16816(acco[2*p],   ah, bh0);
                mma16816(acco[2*p],   ah, bl0);
                mma16816(acco[2*p],   al, bh0);
                mma16816(acco[2*p+1], ah, bh1);
                mma16816(acco[2*p+1], ah, bl1);
                mma16816(acco[2*p+1], al, bh1);
            }
        }

        int q0 = qbase + tile * TMA2;
#pragma unroll
        for (int nt = 0; nt < 8; nt++) {
            int c = h * 64 + nt * 8 + (lane & 3) * 2;
#pragma unroll
            for (int half = 0; half < 2; half++) {
                int r = warp * 16 + (lane >> 2) + half * 8;
                size_t ro = (size_t)(q0 + r) * Dm + c;
                bf h0, l0, h1, l1;
                splitw(acco[nt][half * 2 + 0], h0, l0);
                splitw(acco[nt][half * 2 + 1], h1, l1);
                *(__nv_bfloat162*)(gOh + ro) = __halves2bfloat162(h0, h1);
                *(__nv_bfloat162*)(gOl + ro) = __halves2bfloat162(l0, l1);
            }
        }
    }
}

// ---------------- launch ----------------
extern "C" void kernel_launch(void* const* d_in, const int* in_sizes, int n_in,
                              void* d_out, int out_size)
{
    const float* hidden  = (const float*)d_in[0];
    const float* text    = (const float*)d_in[1];
    const float* ids     = (const float*)d_in[2];
    const float* hair    = (const float*)d_in[3];
    const float* Wq      = (const float*)d_in[4];
    const float* Wk      = (const float*)d_in[5];
    const float* Wv      = (const float*)d_in[6];
    const float* Wo      = (const float*)d_in[7];
    const float* bo      = (const float*)d_in[8];
    const float* Wk_id   = (const float*)d_in[9];
    const float* Wv_id   = (const float*)d_in[10];
    const float* Wk_hair = (const float*)d_in[11];
    const float* Wv_hair = (const float*)d_in[12];
    float* out = (float*)d_out;

    bf *pHh, *pHl, *pQh, *pQl, *pOh, *pOl, *pTh, *pTl, *pIh, *pIl, *pRh, *pRl;
    bf *pKh, *pKl, *pVh, *pVl;
    bf *pWqH, *pWqL, *pWoH, *pWoL, *pWkH, *pWkL, *pWvH, *pWvL;
    bf *pWkiH, *pWkiL, *pWviH, *pWviL, *pWkhH, *pWkhL, *pWvhH, *pWvhL;
    cudaGetSymbolAddress((void**)&pHh, gHh);   cudaGetSymbolAddress((void**)&pHl, gHl);
    cudaGetSymbolAddress((void**)&pQh, gQh);   cudaGetSymbolAddress((void**)&pQl, gQl);
    cudaGetSymbolAddress((void**)&pOh, gOh);   cudaGetSymbolAddress((void**)&pOl, gOl);
    cudaGetSymbolAddress((void**)&pTh, gTh);   cudaGetSymbolAddress((void**)&pTl, gTl);
    cudaGetSymbolAddress((void**)&pIh, gIh);   cudaGetSymbolAddress((void**)&pIl, gIl);
    cudaGetSymbolAddress((void**)&pRh, gRh);   cudaGetSymbolAddress((void**)&pRl, gRl);
    cudaGetSymbolAddress((void**)&pKh, gKh);   cudaGetSymbolAddress((void**)&pKl, gKl);
    cudaGetSymbolAddress((void**)&pVh, gVh);   cudaGetSymbolAddress((void**)&pVl, gVl);
    cudaGetSymbolAddress((void**)&pWqH, gWqH); cudaGetSymbolAddress((void**)&pWqL, gWqL);
    cudaGetSymbolAddress((void**)&pWoH, gWoH); cudaGetSymbolAddress((void**)&pWoL, gWoL);
    cudaGetSymbolAddress((void**)&pWkH, gWkH); cudaGetSymbolAddress((void**)&pWkL, gWkL);
    cudaGetSymbolAddress((void**)&pWvH, gWvH); cudaGetSymbolAddress((void**)&pWvL, gWvL);
    cudaGetSymbolAddress((void**)&pWkiH, gWkiH); cudaGetSymbolAddress((void**)&pWkiL, gWkiL);
    cudaGetSymbolAddress((void**)&pWviH, gWviH); cudaGetSymbolAddress((void**)&pWviL, gWviL);
    cudaGetSymbolAddress((void**)&pWkhH, gWkhH); cudaGetSymbolAddress((void**)&pWkhL, gWkhL);
    cudaGetSymbolAddress((void**)&pWvhH, gWvhH); cudaGetSymbolAddress((void**)&pWvhL, gWvhL);

    cudaFuncSetAttribute(gemm_main, cudaFuncAttributeMaxDynamicSharedMemorySize, GEMM_SMEM_BYTES);
    cudaFuncSetAttribute(gemm_qkv,  cudaFuncAttributeMaxDynamicSharedMemorySize, GEMM_SMEM_BYTES);
    cudaFuncSetAttribute(attn3,     cudaFuncAttributeMaxDynamicSharedMemorySize, ATT2_SMEM_BYTES);

    // ---- launch 1: ALL splits (activations + weights), one batched kernel ----
    {
        SplitArr A{};
        int off = 0, idx = 0;
        auto add = [&](const float* src, bf* dh, bf* dl, size_t n) {
            int n4 = (int)(n / 4);
            A.s[idx++] = { (const float4*)src, (uint2*)dh, (uint2*)dl, off, n4 };
            off += n4;
        };
        add(hidden,  pHh,  pHl,  (size_t)MQ * Dm);
        add(text,    pTh,  pTl,  (size_t)Bsz * LT * Cm);
        add(ids,     pIh,  pIl,  (size_t)Bsz * LI * Cm);
        add(hair,    pRh,  pRl,  (size_t)Bsz * LI * Cm);
        add(Wq,      pWqH,  pWqL,  (size_t)Dm * Dm);
        add(Wo,      pWoH,  pWoL,  (size_t)Dm * Dm);
        add(Wk,      pWkH,  pWkL,  (size_t)Cm * Dm);
        add(Wv,      pWvH,  pWvL,  (size_t)Cm * Dm);
        add(Wk_id,   pWkiH, pWkiL, (size_t)Cm * Dm);
        add(Wv_id,   pWviH, pWviL, (size_t)Cm * Dm);
        add(Wk_hair, pWkhH, pWkhL, (size_t)Cm * Dm);
        add(Wv_hair, pWvhH, pWvhL, (size_t)Cm * Dm);
        A.cnt = idx;
        split_batch<<<(off + 255) / 256, 256>>>(A);
    }

    // ---- launch 2: fused Q + KV projections (KV fills Q's tail waves) ----
    {
        GFused F{};
        F.QAh = pHh; F.QAl = pHl; F.QWh = pWqH; F.QWl = pWqL;
        F.QCh = pQh; F.QCl = pQl;
        F.s[0] = { pTh, pTl, pWkH,  pWkL,  pKh, pKl, Bsz * LT, LT, 0 };
        F.s[1] = { pTh, pTl, pWvH,  pWvL,  pVh, pVl, Bsz * LT, LT, 0 };
        F.s[2] = { pIh, pIl, pWkiH, pWkiL, pKh, pKl, Bsz * LI, LI, LT };
        F.s[3] = { pIh, pIl, pWviH, pWviL, pVh, pVl, Bsz * LI, LI, LT };
        F.s[4] = { pRh, pRl, pWkhH, pWkhL, pKh, pKl, Bsz * LI, LI, LT + LI };
        F.s[5] = { pRh, pRl, pWvhH, pWvhL, pVh, pVl, Bsz * LI, LI, LT + LI };
        gemm_qkv<<<QBLOCKS + 300, 256, GEMM_SMEM_BYTES>>>(F);
    }

    // ---- launch 3: fused attention (2560 blocks, 2 tiles each) ----
    attn3<<<dim3(16, Hn, Bsz), 256, ATT2_SMEM_BYTES>>>();

    // ---- launch 4: output projection ----
    gemm_main<<<dim3(Dm / 128, MQ / 128), 256, GEMM_SMEM_BYTES>>>(
        pOh, pOl, pWoH, pWoL, bo, out, nullptr, nullptr, MQ, Dm, 1.0f, 0);
}

// round 12
// speedup vs baseline: 5.3094x; 1.3053x over previous
#include <cuda_runtime.h>
#include <cuda_fp16.h>
#include <cstdint>

// ---------------- problem constants ----------------
#define Bsz   8
#define Sq    4096
#define Dm    1280
#define Cm    2048
#define Hn    20
#define DHd   64
#define LT    77
#define LI    16
#define LTOT  109
#define MQ    (Bsz*Sq)

typedef __half bf;

// ---------------- scratch (fp16; activations hi/lo, weights hi only) ----------------
__device__ bf gHh[(size_t)MQ*Dm], gHl[(size_t)MQ*Dm];
__device__ bf gQh[(size_t)MQ*Dm], gQl[(size_t)MQ*Dm];
__device__ bf gOh[(size_t)MQ*Dm], gOl[(size_t)MQ*Dm];
__device__ bf gTh[(size_t)Bsz*LT*Cm], gTl[(size_t)Bsz*LT*Cm];
__device__ bf gIh[(size_t)Bsz*LI*Cm], gIl[(size_t)Bsz*LI*Cm];
__device__ bf gRh[(size_t)Bsz*LI*Cm], gRl[(size_t)Bsz*LI*Cm];
__device__ bf gKh[(size_t)Bsz*LTOT*Dm], gKl[(size_t)Bsz*LTOT*Dm];
__device__ bf gVh[(size_t)Bsz*LTOT*Dm], gVl[(size_t)Bsz*LTOT*Dm];
__device__ bf gWqH[1280*1280];
__device__ bf gWoH[1280*1280];
__device__ bf gWkH[2048*1280];
__device__ bf gWvH[2048*1280];
__device__ bf gWkiH[2048*1280];
__device__ bf gWviH[2048*1280];
__device__ bf gWkhH[2048*1280];
__device__ bf gWvhH[2048*1280];

// ---------------- helpers ----------------
__device__ __forceinline__ void split2u(float x, float y, unsigned& hi, unsigned& lo)
{
    __half hx = __float2half_rn(x);
    __half hy = __float2half_rn(y);
    float rx = x - __half2float(hx);
    float ry = y - __half2float(hy);
    __half2 hp = __halves2half2(hx, hy);
    __half2 lp = __halves2half2(__float2half_rn(rx), __float2half_rn(ry));
    hi = *reinterpret_cast<unsigned*>(&hp);
    lo = *reinterpret_cast<unsigned*>(&lp);
}
__device__ __forceinline__ void splitw(float v, bf& h, bf& l)
{
    h = __float2half_rn(v);
    l = __float2half_rn(v - __half2float(h));
}
__device__ __forceinline__ unsigned s2u(const void* p)
{
    return (unsigned)__cvta_generic_to_shared(p);
}
__device__ __forceinline__ void cpa16(unsigned dst, const void* src, int sz)
{
    asm volatile("cp.async.cg.shared.global [%0], [%1], 16, %2;\n"
                 :: "r"(dst), "l"(src), "r"(sz));
}
#define CP_COMMIT() asm volatile("cp.async.commit_group;\n")
#define CP_WAIT0()  asm volatile("cp.async.wait_group 0;\n")

__device__ __forceinline__ void ldsm4(unsigned& r0, unsigned& r1, unsigned& r2, unsigned& r3,
                                      const void* p)
{
    unsigned a = s2u(p);
    asm volatile("ldmatrix.sync.aligned.m8n8.x4.shared.b16 {%0,%1,%2,%3},[%4];"
                 : "=r"(r0), "=r"(r1), "=r"(r2), "=r"(r3) : "r"(a));
}
__device__ __forceinline__ void ldsm4t(unsigned& r0, unsigned& r1, unsigned& r2, unsigned& r3,
                                       const void* p)
{
    unsigned a = s2u(p);
    asm volatile("ldmatrix.sync.aligned.m8n8.x4.trans.shared.b16 {%0,%1,%2,%3},[%4];"
                 : "=r"(r0), "=r"(r1), "=r"(r2), "=r"(r3) : "r"(a));
}
__device__ __forceinline__ void mma16816(float* c, const unsigned* a, const unsigned* b)
{
    asm volatile(
        "mma.sync.aligned.m16n8k16.row.col.f32.f16.f16.f32 "
        "{%0,%1,%2,%3}, {%4,%5,%6,%7}, {%8,%9}, {%0,%1,%2,%3};"
        : "+f"(c[0]), "+f"(c[1]), "+f"(c[2]), "+f"(c[3])
        : "r"(a[0]), "r"(a[1]), "r"(a[2]), "r"(a[3]), "r"(b[0]), "r"(b[1]));
}

// FMA-only exp (x <= 0 expected)
__device__ __forceinline__ float fexp(float x)
{
    float t  = x * 1.4426950408889634f;
    float fl = floorf(t);
    float f  = t - fl;
    float p  = 1.5403e-4f;
    p = fmaf(p, f, 1.3333558e-3f);
    p = fmaf(p, f, 9.6181291e-3f);
    p = fmaf(p, f, 5.5504109e-2f);
    p = fmaf(p, f, 2.4022651e-1f);
    p = fmaf(p, f, 6.9314718e-1f);
    p = fmaf(p, f, 1.0f);
    int i = (int)fl;
    i = max(i, -126);
    return p * __int_as_float((i + 127) << 23);
}

// ---------------- batched split kernel (dl==nullptr -> hi-only) ----------------
struct SplitSeg { const float4* src; uint2* dh; uint2* dl; int off; int n4; };
struct SplitArr { SplitSeg s[12]; int cnt; };

__global__ __launch_bounds__(256) void split_batch(SplitArr P)
{
    int gid = blockIdx.x * 256 + threadIdx.x;
#pragma unroll 1
    for (int sg = 0; sg < P.cnt; sg++) {
        int local = gid - P.s[sg].off;
        if (local >= 0 && local < P.s[sg].n4) {
            float4 v = P.s[sg].src[local];
            unsigned h0, l0, h1, l1;
            split2u(v.x, v.y, h0, l0);
            split2u(v.z, v.w, h1, l1);
            P.s[sg].dh[local] = make_uint2(h0, h1);
            if (P.s[sg].dl) P.s[sg].dl[local] = make_uint2(l0, l1);
            return;
        }
    }
}

// ---------------- fp16-split GEMM: A 2-term, B(weights) 1-term, 2 mma ----------------
#define BKP 40
#define BNP 136
#define STG_A (128*BKP)
#define STG_B (32*BNP)
#define STG   (2*STG_A + STG_B)
#define GEMM_SMEM_BYTES (2*STG*2)   // 58368

__device__ __forceinline__ int orow(int r, int Lseg, int segOff)
{
    if (Lseg == 0) return r;
    int b = r / Lseg;
    return b * LTOT + segOff + (r - b * Lseg);
}

__device__ __forceinline__ void gemm_dev(
    bf* dynsm, unsigned sbase,
    const bf* __restrict__ Ah, const bf* __restrict__ Al,
    const bf* __restrict__ Wh,
    int M, int K, int bx, int by, float alpha, int mode,
    const float* __restrict__ bias, float* __restrict__ outF,
    bf* __restrict__ outH, bf* __restrict__ outL, int Lseg, int segOff)
{
    const int N = Dm;
    const int tid = threadIdx.x, lane = tid & 31, warp = tid >> 5;
    const int wM = warp >> 2, wN = warp & 3;
    const int brow = by * 128, bcol = bx * 128;

    float acc[4][4][4];
#pragma unroll
    for (int i = 0; i < 4; i++)
#pragma unroll
        for (int j = 0; j < 4; j++)
#pragma unroll
            for (int q = 0; q < 4; q++) acc[i][j][q] = 0.f;

    const int nT = K / 32;

    auto load_stage = [&](int st, int k0) {
        unsigned aH = sbase + (unsigned)(st * STG) * 2;
        unsigned aL = aH + STG_A * 2;
        unsigned bH = aL + STG_A * 2;
#pragma unroll
        for (int u = 0; u < 2; u++) {
            int i   = tid + u * 256;
            int row = i >> 2, k8 = (i & 3) * 8;
            const bf* sH = Ah + (size_t)(brow + row) * K + k0 + k8;
            const bf* sL = Al + (size_t)(brow + row) * K + k0 + k8;
            int ok = 16;
            if (brow + row >= M) { sH = Ah; sL = Al; ok = 0; }
            cpa16(aH + (unsigned)(row * BKP + k8) * 2, sH, ok);
            cpa16(aL + (unsigned)(row * BKP + k8) * 2, sL, ok);
            int kr = i >> 4, n8 = (i & 15) * 8;
            cpa16(bH + (unsigned)(kr * BNP + n8) * 2, Wh + (size_t)(k0 + kr) * N + bcol + n8, 16);
        }
    };

    load_stage(0, 0);
    CP_COMMIT();

    for (int t = 0; t < nT; t++) {
        CP_WAIT0();
        __syncthreads();
        if (t + 1 < nT) { load_stage((t + 1) & 1, (t + 1) * 32); CP_COMMIT(); }

        bf* AsH = dynsm + (t & 1) * STG;
        bf* AsL = AsH + STG_A;
        bf* BsH = AsL + STG_A;

#pragma unroll
        for (int ks = 0; ks < 2; ks++) {
            unsigned ah[4][4], al[4][4], bh[4][2];
            {
                int rowb = wM * 64 + (lane & 15);
                int kk   = ks * 16 + (lane >> 4) * 8;
#pragma unroll
                for (int mt = 0; mt < 4; mt++) {
                    int off = (rowb + mt * 16) * BKP + kk;
                    ldsm4(ah[mt][0], ah[mt][1], ah[mt][2], ah[mt][3], AsH + off);
                    ldsm4(al[mt][0], al[mt][1], al[mt][2], al[mt][3], AsL + off);
                }
            }
            {
                int kk = ks * 16 + (lane & 7) + ((lane >> 3) & 1) * 8;
#pragma unroll
                for (int p = 0; p < 2; p++) {
                    int nn = wN * 32 + p * 16 + (lane >> 4) * 8;
                    unsigned t0, t1, t2, t3;
                    ldsm4t(t0, t1, t2, t3, BsH + kk * BNP + nn);
                    bh[2*p][0] = t0; bh[2*p][1] = t1;
                    bh[2*p+1][0] = t2; bh[2*p+1][1] = t3;
                }
            }
#pragma unroll
            for (int mt = 0; mt < 4; mt++)
#pragma unroll
                for (int nt = 0; nt < 4; nt++) {
                    mma16816(acc[mt][nt], ah[mt], bh[nt]);
                    mma16816(acc[mt][nt], al[mt], bh[nt]);
                }
        }
    }

#pragma unroll
    for (int mt = 0; mt < 4; mt++) {
        int r0 = brow + wM * 64 + mt * 16 + (lane >> 2);
#pragma unroll
        for (int nt = 0; nt < 4; nt++) {
            int col = bcol + wN * 32 + nt * 8 + (lane & 3) * 2;
#pragma unroll
            for (int half = 0; half < 2; half++) {
                int r = r0 + half * 8;
                if (r >= M) continue;
                float v0 = alpha * acc[mt][nt][half * 2 + 0];
                float v1 = alpha * acc[mt][nt][half * 2 + 1];
                if (mode == 0) {
                    if (bias) { v0 += bias[col]; v1 += bias[col + 1]; }
                    *(float2*)&outF[(size_t)r * N + col] = make_float2(v0, v1);
                } else {
                    bf h0, l0, h1, l1;
                    splitw(v0, h0, l0); splitw(v1, h1, l1);
                    size_t ro = (size_t)orow(r, Lseg, segOff) * N + col;
                    *(__half2*)(outH + ro) = __halves2half2(h0, h1);
                    *(__half2*)(outL + ro) = __halves2half2(l0, l1);
                }
            }
        }
    }
}

// plain output-projection GEMM launch
__global__ __launch_bounds__(256, 2) void gemm_main(
    const bf* Ah, const bf* Al, const bf* Wh,
    const float* bias, float* outF, bf* outH, bf* outL,
    int M, int K, float alpha, int mode)
{
    extern __shared__ __align__(16) bf dynsm_g[];
    unsigned sbase = (unsigned)__cvta_generic_to_shared(dynsm_g);
    gemm_dev(dynsm_g, sbase, Ah, Al, Wh, M, K, blockIdx.x, blockIdx.y,
             alpha, mode, bias, outF, outH, outL, 0, 0);
}

// fused Q + KV projection launch: 1D grid, Q tiles first, KV tiles fill the tail
struct GSeg { const bf *Ah, *Al, *Wh; bf *Ch, *Cl; int M, Lseg, segOff; };
struct GFused {
    const bf *QAh, *QAl, *QWh;
    bf *QCh, *QCl;
    GSeg s[6];
};
#define QBLOCKS (10 * (MQ / 128))   // 2560

__global__ __launch_bounds__(256, 2) void gemm_qkv(GFused P)
{
    extern __shared__ __align__(16) bf dynsm_f[];
    unsigned sbase = (unsigned)__cvta_generic_to_shared(dynsm_f);
    int bid = blockIdx.x;
    if (bid < QBLOCKS) {
        int bx = bid % 10, by = bid / 10;
        gemm_dev(dynsm_f, sbase, P.QAh, P.QAl, P.QWh, MQ, Dm, bx, by,
                 0.125f, 1, nullptr, nullptr, P.QCh, P.QCl, 0, 0);
    } else {
        int kid = bid - QBLOCKS;
        int z = kid / 50, rem = kid % 50;
        int by = rem / 10, bx = rem % 10;
        const GSeg s = P.s[z];
        if (by * 128 >= s.M) return;
        gemm_dev(dynsm_f, sbase, s.Ah, s.Al, s.Wh, s.M, Cm, bx, by,
                 1.0f, 2, nullptr, nullptr, s.Ch, s.Cl, s.Lseg, s.segOff);
    }
}

// ---------------- register-resident fused attention (fp16 3-term) ----------------
#define TMA2 128
#define NTILE 2
#define AQS 72
#define AKS 120
#define AVS 72
#define A2_QH  0
#define A2_QL  (A2_QH + TMA2*AQS)
#define A2_KTH (A2_QL + TMA2*AQS)
#define A2_KTL (A2_KTH + 64*AKS)
#define A2_VH  (A2_KTL + 64*AKS)
#define A2_VL  (A2_VH + 112*AVS)
#define ATT2_SMEM_BYTES ((A2_VL + 112*AVS) * 2)   // 99840

__global__ __launch_bounds__(256, 2) void attn3()
{
    extern __shared__ __align__(16) bf sm3[];
    bf* Qh  = sm3 + A2_QH;
    bf* Ql  = sm3 + A2_QL;
    bf* Kth = sm3 + A2_KTH;
    bf* Ktl = sm3 + A2_KTL;
    bf* Vh  = sm3 + A2_VH;
    bf* Vl  = sm3 + A2_VL;

    const int t = threadIdx.x, lane = t & 31, warp = t >> 5;
    const int qq = blockIdx.x, h = blockIdx.y, b = blockIdx.z;
    const size_t kvbase = ((size_t)b * LTOT) * Dm + h * 64;

    // K^T load [d=64][l], pad cols 109..111 zero
    for (int idx = t; idx < LTOT * 64; idx += 256) {
        int l = idx >> 6, d = idx & 63;
        Kth[d * AKS + l] = gKh[kvbase + (size_t)l * Dm + d];
        Ktl[d * AKS + l] = gKl[kvbase + (size_t)l * Dm + d];
    }
    if (t < 192) {
        int d = t / 3, l = LTOT + t % 3;
        Kth[d * AKS + l] = __float2half(0.f);
        Ktl[d * AKS + l] = __float2half(0.f);
    }
    // V load [l][d], pad rows 109..111 zero
    for (int idx = t; idx < LTOT * 8; idx += 256) {
        int l = idx >> 3, j = idx & 7;
        *(uint4*)(Vh + l * AVS + j * 8) = *(const uint4*)(gVh + kvbase + (size_t)l * Dm + j * 8);
        *(uint4*)(Vl + l * AVS + j * 8) = *(const uint4*)(gVl + kvbase + (size_t)l * Dm + j * 8);
    }
    uint4 z4 = make_uint4(0, 0, 0, 0);
    if (t < 24) {
        int l = LTOT + t / 8, j = t & 7;
        *(uint4*)(Vh + l * AVS + j * 8) = z4;
        *(uint4*)(Vl + l * AVS + j * 8) = z4;
    }

    const int qbase = b * Sq + qq * (TMA2 * NTILE);

    auto loadQ = [&](int tile) {
        int q0 = qbase + tile * TMA2;
#pragma unroll
        for (int u = 0; u < 4; u++) {
            int i = t + u * 256;
            int r = i >> 3, j = i & 7;
            size_t go = (size_t)(q0 + r) * Dm + h * 64 + j * 8;
            cpa16(s2u(Qh + r * AQS + j * 8), gQh + go, 16);
            cpa16(s2u(Ql + r * AQS + j * 8), gQl + go, 16);
        }
    };

    loadQ(0);
    CP_COMMIT();

    for (int tile = 0; tile < NTILE; tile++) {
        CP_WAIT0();
        __syncthreads();

        // ---- S = Q @ K^T ----
        float accs[14][4];
#pragma unroll
        for (int i = 0; i < 14; i++)
#pragma unroll
            for (int j = 0; j < 4; j++) accs[i][j] = 0.f;

#pragma unroll
        for (int ks = 0; ks < 4; ks++) {
            unsigned ah[4], al[4];
            int aoff = (warp * 16 + (lane & 15)) * AQS + ks * 16 + (lane >> 4) * 8;
            ldsm4(ah[0], ah[1], ah[2], ah[3], Qh + aoff);
            ldsm4(al[0], al[1], al[2], al[3], Ql + aoff);
            int kk = ks * 16 + (lane & 7) + ((lane >> 3) & 1) * 8;
#pragma unroll
            for (int p = 0; p < 7; p++) {
                int nn = p * 16 + (lane >> 4) * 8;
                unsigned t0, t1, t2, t3;
                ldsm4t(t0, t1, t2, t3, Kth + kk * AKS + nn);
                unsigned bh0[2] = {t0, t1}, bh1[2] = {t2, t3};
                ldsm4t(t0, t1, t2, t3, Ktl + kk * AKS + nn);
                unsigned bl0[2] = {t0, t1}, bl1[2] = {t2, t3};
                mma16816(accs[2*p],   ah, bh0);
                mma16816(accs[2*p],   ah, bl0);
                mma16816(accs[2*p],   al, bh0);
                mma16816(accs[2*p+1], ah, bh1);
                mma16816(accs[2*p+1], ah, bl1);
                mma16816(accs[2*p+1], al, bh1);
            }
        }
        __syncthreads();
        if (tile + 1 < NTILE) { loadQ(tile + 1); CP_COMMIT(); }

        // ---- in-register per-segment softmax ----
        const int cbase = (lane & 3) * 2;
#pragma unroll
        for (int j = 0; j < 2; j++) {
            float mx0 = -1e30f, mx1 = -1e30f, mx2 = -1e30f;
#pragma unroll
            for (int nt = 0; nt < 14; nt++)
#pragma unroll
                for (int e = 0; e < 2; e++) {
                    int c = nt * 8 + cbase + e;
                    float v = accs[nt][2*j + e];
                    if (c < LT) mx0 = fmaxf(mx0, v);
                    else if (c < LT + LI) mx1 = fmaxf(mx1, v);
                    else if (c < LTOT) mx2 = fmaxf(mx2, v);
                }
#pragma unroll
            for (int d = 1; d < 4; d <<= 1) {
                mx0 = fmaxf(mx0, __shfl_xor_sync(0xffffffffu, mx0, d));
                mx1 = fmaxf(mx1, __shfl_xor_sync(0xffffffffu, mx1, d));
                mx2 = fmaxf(mx2, __shfl_xor_sync(0xffffffffu, mx2, d));
            }
            float s0 = 0.f, s1 = 0.f, s2 = 0.f;
#pragma unroll
            for (int nt = 0; nt < 14; nt++)
#pragma unroll
                for (int e = 0; e < 2; e++) {
                    int c = nt * 8 + cbase + e;
                    float v = accs[nt][2*j + e], r;
                    if (c < LT)           { r = fexp(v - mx0); s0 += r; }
                    else if (c < LT + LI) { r = fexp(v - mx1); s1 += r; }
                    else if (c < LTOT)    { r = fexp(v - mx2); s2 += r; }
                    else r = 0.f;
                    accs[nt][2*j + e] = r;
                }
#pragma unroll
            for (int d = 1; d < 4; d <<= 1) {
                s0 += __shfl_xor_sync(0xffffffffu, s0, d);
                s1 += __shfl_xor_sync(0xffffffffu, s1, d);
                s2 += __shfl_xor_sync(0xffffffffu, s2, d);
            }
            float i0 = 1.0f / s0, i1 = 1.0f / s1, i2 = 1.0f / s2;
#pragma unroll
            for (int nt = 0; nt < 14; nt++)
#pragma unroll
                for (int e = 0; e < 2; e++) {
                    int c = nt * 8 + cbase + e;
                    float inv = (c < LT) ? i0 : (c < LT + LI) ? i1 : i2;
                    accs[nt][2*j + e] *= inv;
                }
        }

        // ---- O = P @ V ----
        float acco[8][4];
#pragma unroll
        for (int i = 0; i < 8; i++)
#pragma unroll
            for (int j = 0; j < 4; j++) acco[i][j] = 0.f;

#pragma unroll
        for (int ks = 0; ks < 7; ks++) {
            unsigned ah[4], al[4];
#pragma unroll
            for (int q = 0; q < 2; q++)
#pragma unroll
                for (int rr = 0; rr < 2; rr++) {
                    float v0 = accs[2*ks + q][2*rr + 0];
                    float v1 = accs[2*ks + q][2*rr + 1];
                    bf h0, l0, h1, l1;
                    splitw(v0, h0, l0);
                    splitw(v1, h1, l1);
                    __half2 hp = __halves2half2(h0, h1);
                    __half2 lp = __halves2half2(l0, l1);
                    ah[q*2 + rr] = *reinterpret_cast<unsigned*>(&hp);
                    al[q*2 + rr] = *reinterpret_cast<unsigned*>(&lp);
                }
            int kk = ks * 16 + (lane & 7) + ((lane >> 3) & 1) * 8;
#pragma unroll
            for (int p = 0; p < 4; p++) {
                int nn = p * 16 + (lane >> 4) * 8;
                unsigned t0, t1, t2, t3;
                ldsm4t(t0, t1, t2, t3, Vh + kk * AVS + nn);
                unsigned bh0[2] = {t0, t1}, bh1[2] = {t2, t3};
                ldsm4t(t0, t1, t2, t3, Vl + kk * AVS + nn);
                unsigned bl0[2] = {t0, t1}, bl1[2] = {t2, t3};
                mma16816(acco[2*p],   ah, bh0);
                mma16816(acco[2*p],   ah, bl0);
                mma16816(acco[2*p],   al, bh0);
                mma16816(acco[2*p+1], ah, bh1);
                mma16816(acco[2*p+1], ah, bl1);
                mma16816(acco[2*p+1], al, bh1);
            }
        }

        int q0 = qbase + tile * TMA2;
#pragma unroll
        for (int nt = 0; nt < 8; nt++) {
            int c = h * 64 + nt * 8 + (lane & 3) * 2;
#pragma unroll
            for (int half = 0; half < 2; half++) {
                int r = warp * 16 + (lane >> 2) + half * 8;
                size_t ro = (size_t)(q0 + r) * Dm + c;
                bf h0, l0, h1, l1;
                splitw(acco[nt][half * 2 + 0], h0, l0);
                splitw(acco[nt][half * 2 + 1], h1, l1);
                *(__half2*)(gOh + ro) = __halves2half2(h0, h1);
                *(__half2*)(gOl + ro) = __halves2half2(l0, l1);
            }
        }
    }
}

// ---------------- launch ----------------
extern "C" void kernel_launch(void* const* d_in, const int* in_sizes, int n_in,
                              void* d_out, int out_size)
{
    const float* hidden  = (const float*)d_in[0];
    const float* text    = (const float*)d_in[1];
    const float* ids     = (const float*)d_in[2];
    const float* hair    = (const float*)d_in[3];
    const float* Wq      = (const float*)d_in[4];
    const float* Wk      = (const float*)d_in[5];
    const float* Wv      = (const float*)d_in[6];
    const float* Wo      = (const float*)d_in[7];
    const float* bo      = (const float*)d_in[8];
    const float* Wk_id   = (const float*)d_in[9];
    const float* Wv_id   = (const float*)d_in[10];
    const float* Wk_hair = (const float*)d_in[11];
    const float* Wv_hair = (const float*)d_in[12];
    float* out = (float*)d_out;

    bf *pHh, *pHl, *pQh, *pQl, *pOh, *pOl, *pTh, *pTl, *pIh, *pIl, *pRh, *pRl;
    bf *pKh, *pKl, *pVh, *pVl;
    bf *pWqH, *pWoH, *pWkH, *pWvH, *pWkiH, *pWviH, *pWkhH, *pWvhH;
    cudaGetSymbolAddress((void**)&pHh, gHh);   cudaGetSymbolAddress((void**)&pHl, gHl);
    cudaGetSymbolAddress((void**)&pQh, gQh);   cudaGetSymbolAddress((void**)&pQl, gQl);
    cudaGetSymbolAddress((void**)&pOh, gOh);   cudaGetSymbolAddress((void**)&pOl, gOl);
    cudaGetSymbolAddress((void**)&pTh, gTh);   cudaGetSymbolAddress((void**)&pTl, gTl);
    cudaGetSymbolAddress((void**)&pIh, gIh);   cudaGetSymbolAddress((void**)&pIl, gIl);
    cudaGetSymbolAddress((void**)&pRh, gRh);   cudaGetSymbolAddress((void**)&pRl, gRl);
    cudaGetSymbolAddress((void**)&pKh, gKh);   cudaGetSymbolAddress((void**)&pKl, gKl);
    cudaGetSymbolAddress((void**)&pVh, gVh);   cudaGetSymbolAddress((void**)&pVl, gVl);
    cudaGetSymbolAddress((void**)&pWqH, gWqH);
    cudaGetSymbolAddress((void**)&pWoH, gWoH);
    cudaGetSymbolAddress((void**)&pWkH, gWkH);
    cudaGetSymbolAddress((void**)&pWvH, gWvH);
    cudaGetSymbolAddress((void**)&pWkiH, gWkiH);
    cudaGetSymbolAddress((void**)&pWviH, gWviH);
    cudaGetSymbolAddress((void**)&pWkhH, gWkhH);
    cudaGetSymbolAddress((void**)&pWvhH, gWvhH);

    cudaFuncSetAttribute(gemm_main, cudaFuncAttributeMaxDynamicSharedMemorySize, GEMM_SMEM_BYTES);
    cudaFuncSetAttribute(gemm_qkv,  cudaFuncAttributeMaxDynamicSharedMemorySize, GEMM_SMEM_BYTES);
    cudaFuncSetAttribute(attn3,     cudaFuncAttributeMaxDynamicSharedMemorySize, ATT2_SMEM_BYTES);

    // ---- launch 1: ALL splits (activations hi/lo, weights hi-only) ----
    {
        SplitArr A{};
        int off = 0, idx = 0;
        auto add = [&](const float* src, bf* dh, bf* dl, size_t n) {
            int n4 = (int)(n / 4);
            A.s[idx++] = { (const float4*)src, (uint2*)dh, (uint2*)dl, off, n4 };
            off += n4;
        };
        add(hidden,  pHh,  pHl,  (size_t)MQ * Dm);
        add(text,    pTh,  pTl,  (size_t)Bsz * LT * Cm);
        add(ids,     pIh,  pIl,  (size_t)Bsz * LI * Cm);
        add(hair,    pRh,  pRl,  (size_t)Bsz * LI * Cm);
        add(Wq,      pWqH,  nullptr, (size_t)Dm * Dm);
        add(Wo,      pWoH,  nullptr, (size_t)Dm * Dm);
        add(Wk,      pWkH,  nullptr, (size_t)Cm * Dm);
        add(Wv,      pWvH,  nullptr, (size_t)Cm * Dm);
        add(Wk_id,   pWkiH, nullptr, (size_t)Cm * Dm);
        add(Wv_id,   pWviH, nullptr, (size_t)Cm * Dm);
        add(Wk_hair, pWkhH, nullptr, (size_t)Cm * Dm);
        add(Wv_hair, pWvhH, nullptr, (size_t)Cm * Dm);
        A.cnt = idx;
        split_batch<<<(off + 255) / 256, 256>>>(A);
    }

    // ---- launch 2: fused Q + KV projections ----
    {
        GFused F{};
        F.QAh = pHh; F.QAl = pHl; F.QWh = pWqH;
        F.QCh = pQh; F.QCl = pQl;
        F.s[0] = { pTh, pTl, pWkH,  pKh, pKl, Bsz * LT, LT, 0 };
        F.s[1] = { pTh, pTl, pWvH,  pVh, pVl, Bsz * LT, LT, 0 };
        F.s[2] = { pIh, pIl, pWkiH, pKh, pKl, Bsz * LI, LI, LT };
        F.s[3] = { pIh, pIl, pWviH, pVh, pVl, Bsz * LI, LI, LT };
        F.s[4] = { pRh, pRl, pWkhH, pKh, pKl, Bsz * LI, LI, LT + LI };
        F.s[5] = { pRh, pRl, pWvhH, pVh, pVl, Bsz * LI, LI, LT + LI };
        gemm_qkv<<<QBLOCKS + 300, 256, GEMM_SMEM_BYTES>>>(F);
    }

    // ---- launch 3: fused attention ----
    attn3<<<dim3(16, Hn, Bsz), 256, ATT2_SMEM_BYTES>>>();

    // ---- launch 4: output projection ----
    gemm_main<<<dim3(Dm / 128, MQ / 128), 256, GEMM_SMEM_BYTES>>>(
        pOh, pOl, pWoH, bo, out, nullptr, nullptr, MQ, Dm, 1.0f, 0);
}

// round 13
// speedup vs baseline: 5.4221x; 1.0212x over previous
#include <cuda_runtime.h>
#include <cuda_fp16.h>
#include <cstdint>

// ---------------- problem constants ----------------
#define Bsz   8
#define Sq    4096
#define Dm    1280
#define Cm    2048
#define Hn    20
#define DHd   64
#define LT    77
#define LI    16
#define LTOT  109
#define MQ    (Bsz*Sq)

typedef __half bf;

// ---------------- scratch ----------------
__device__ bf gHh[(size_t)MQ*Dm], gHl[(size_t)MQ*Dm];
__device__ bf gQh[(size_t)MQ*Dm], gQl[(size_t)MQ*Dm];
__device__ bf gOh[(size_t)MQ*Dm], gOl[(size_t)MQ*Dm];
__device__ bf gTh[(size_t)Bsz*LT*Cm], gTl[(size_t)Bsz*LT*Cm];
__device__ bf gIh[(size_t)Bsz*LI*Cm], gIl[(size_t)Bsz*LI*Cm];
__device__ bf gRh[(size_t)Bsz*LI*Cm], gRl[(size_t)Bsz*LI*Cm];
__device__ bf gKh[(size_t)Bsz*LTOT*Dm];          // K single-term
__device__ bf gVh[(size_t)Bsz*LTOT*Dm];          // V single-term
__device__ bf gWqH[1280*1280];
__device__ bf gWoH[1280*1280];
__device__ bf gWkH[2048*1280];
__device__ bf gWvH[2048*1280];
__device__ bf gWkiH[2048*1280];
__device__ bf gWviH[2048*1280];
__device__ bf gWkhH[2048*1280];
__device__ bf gWvhH[2048*1280];

// ---------------- helpers ----------------
__device__ __forceinline__ void split2u(float x, float y, unsigned& hi, unsigned& lo)
{
    __half hx = __float2half_rn(x);
    __half hy = __float2half_rn(y);
    float rx = x - __half2float(hx);
    float ry = y - __half2float(hy);
    __half2 hp = __halves2half2(hx, hy);
    __half2 lp = __halves2half2(__float2half_rn(rx), __float2half_rn(ry));
    hi = *reinterpret_cast<unsigned*>(&hp);
    lo = *reinterpret_cast<unsigned*>(&lp);
}
__device__ __forceinline__ void splitw(float v, bf& h, bf& l)
{
    h = __float2half_rn(v);
    l = __float2half_rn(v - __half2float(h));
}
__device__ __forceinline__ unsigned s2u(const void* p)
{
    return (unsigned)__cvta_generic_to_shared(p);
}
__device__ __forceinline__ void cpa16(unsigned dst, const void* src, int sz)
{
    asm volatile("cp.async.cg.shared.global [%0], [%1], 16, %2;\n"
                 :: "r"(dst), "l"(src), "r"(sz));
}
#define CP_COMMIT() asm volatile("cp.async.commit_group;\n")
#define CP_WAIT0()  asm volatile("cp.async.wait_group 0;\n")
#define CP_WAIT1()  asm volatile("cp.async.wait_group 1;\n")

__device__ __forceinline__ void ldsm4(unsigned& r0, unsigned& r1, unsigned& r2, unsigned& r3,
                                      const void* p)
{
    unsigned a = s2u(p);
    asm volatile("ldmatrix.sync.aligned.m8n8.x4.shared.b16 {%0,%1,%2,%3},[%4];"
                 : "=r"(r0), "=r"(r1), "=r"(r2), "=r"(r3) : "r"(a));
}
__device__ __forceinline__ void ldsm4t(unsigned& r0, unsigned& r1, unsigned& r2, unsigned& r3,
                                       const void* p)
{
    unsigned a = s2u(p);
    asm volatile("ldmatrix.sync.aligned.m8n8.x4.trans.shared.b16 {%0,%1,%2,%3},[%4];"
                 : "=r"(r0), "=r"(r1), "=r"(r2), "=r"(r3) : "r"(a));
}
__device__ __forceinline__ void mma16816(float* c, const unsigned* a, const unsigned* b)
{
    asm volatile(
        "mma.sync.aligned.m16n8k16.row.col.f32.f16.f16.f32 "
        "{%0,%1,%2,%3}, {%4,%5,%6,%7}, {%8,%9}, {%0,%1,%2,%3};"
        : "+f"(c[0]), "+f"(c[1]), "+f"(c[2]), "+f"(c[3])
        : "r"(a[0]), "r"(a[1]), "r"(a[2]), "r"(a[3]), "r"(b[0]), "r"(b[1]));
}

// FMA-only exp (x <= 0 expected)
__device__ __forceinline__ float fexp(float x)
{
    float t  = x * 1.4426950408889634f;
    float fl = floorf(t);
    float f  = t - fl;
    float p  = 1.5403e-4f;
    p = fmaf(p, f, 1.3333558e-3f);
    p = fmaf(p, f, 9.6181291e-3f);
    p = fmaf(p, f, 5.5504109e-2f);
    p = fmaf(p, f, 2.4022651e-1f);
    p = fmaf(p, f, 6.9314718e-1f);
    p = fmaf(p, f, 1.0f);
    int i = (int)fl;
    i = max(i, -126);
    return p * __int_as_float((i + 127) << 23);
}

// ---------------- batched split kernel (dl==nullptr -> hi-only) ----------------
struct SplitSeg { const float4* src; uint2* dh; uint2* dl; int off; int n4; };
struct SplitArr { SplitSeg s[12]; int cnt; };

__global__ __launch_bounds__(256) void split_batch(SplitArr P)
{
    int gid = blockIdx.x * 256 + threadIdx.x;
#pragma unroll 1
    for (int sg = 0; sg < P.cnt; sg++) {
        int local = gid - P.s[sg].off;
        if (local >= 0 && local < P.s[sg].n4) {
            float4 v = P.s[sg].src[local];
            unsigned h0, l0, h1, l1;
            split2u(v.x, v.y, h0, l0);
            split2u(v.z, v.w, h1, l1);
            P.s[sg].dh[local] = make_uint2(h0, h1);
            if (P.s[sg].dl) P.s[sg].dl[local] = make_uint2(l0, l1);
            return;
        }
    }
}

// ---------------- fp16-split GEMM: A 2-term, B 1-term; 3-stage cp.async ----------------
#define BKP 40
#define BNP 136
#define STG_A (128*BKP)
#define STG_B (32*BNP)
#define STG   (2*STG_A + STG_B)
#define NSTAGE 3
#define GEMM_SMEM_BYTES (NSTAGE*STG*2)   // 87552

__device__ __forceinline__ int orow(int r, int Lseg, int segOff)
{
    if (Lseg == 0) return r;
    int b = r / Lseg;
    return b * LTOT + segOff + (r - b * Lseg);
}

// mode: 0 = fp32 out (+bias); 1 = split hi/lo out; 2 = hi-only out with orow
__device__ __forceinline__ void gemm_dev(
    bf* dynsm, unsigned sbase,
    const bf* __restrict__ Ah, const bf* __restrict__ Al,
    const bf* __restrict__ Wh,
    int M, int K, int bx, int by, float alpha, int mode,
    const float* __restrict__ bias, float* __restrict__ outF,
    bf* __restrict__ outH, bf* __restrict__ outL, int Lseg, int segOff)
{
    const int N = Dm;
    const int tid = threadIdx.x, lane = tid & 31, warp = tid >> 5;
    const int wM = warp >> 2, wN = warp & 3;
    const int brow = by * 128, bcol = bx * 128;

    float acc[4][4][4];
#pragma unroll
    for (int i = 0; i < 4; i++)
#pragma unroll
        for (int j = 0; j < 4; j++)
#pragma unroll
            for (int q = 0; q < 4; q++) acc[i][j][q] = 0.f;

    const int nT = K / 32;

    auto load_stage = [&](int st, int k0) {
        unsigned aH = sbase + (unsigned)(st * STG) * 2;
        unsigned aL = aH + STG_A * 2;
        unsigned bH = aL + STG_A * 2;
#pragma unroll
        for (int u = 0; u < 2; u++) {
            int i   = tid + u * 256;
            int row = i >> 2, k8 = (i & 3) * 8;
            const bf* sH = Ah + (size_t)(brow + row) * K + k0 + k8;
            const bf* sL = Al + (size_t)(brow + row) * K + k0 + k8;
            int ok = 16;
            if (brow + row >= M) { sH = Ah; sL = Al; ok = 0; }
            cpa16(aH + (unsigned)(row * BKP + k8) * 2, sH, ok);
            cpa16(aL + (unsigned)(row * BKP + k8) * 2, sL, ok);
            int kr = i >> 4, n8 = (i & 15) * 8;
            cpa16(bH + (unsigned)(kr * BNP + n8) * 2, Wh + (size_t)(k0 + kr) * N + bcol + n8, 16);
        }
    };

    load_stage(0, 0); CP_COMMIT();
    load_stage(1, 32); CP_COMMIT();

    int st = 0;
    for (int t = 0; t < nT; t++) {
        CP_WAIT1();        // stage t done (t+1 may still be in flight)
        __syncthreads();   // also: all warps done with compute(t-1) -> stage (t+2)%3 free
        if (t + 2 < nT) { load_stage((t + 2) % NSTAGE, (t + 2) * 32); CP_COMMIT(); }

        bf* AsH = dynsm + st * STG;
        bf* AsL = AsH + STG_A;
        bf* BsH = AsL + STG_A;
        st = (st + 1 == NSTAGE) ? 0 : st + 1;

#pragma unroll
        for (int ks = 0; ks < 2; ks++) {
            unsigned ah[4][4], al[4][4], bh[4][2];
            {
                int rowb = wM * 64 + (lane & 15);
                int kk   = ks * 16 + (lane >> 4) * 8;
#pragma unroll
                for (int mt = 0; mt < 4; mt++) {
                    int off = (rowb + mt * 16) * BKP + kk;
                    ldsm4(ah[mt][0], ah[mt][1], ah[mt][2], ah[mt][3], AsH + off);
                    ldsm4(al[mt][0], al[mt][1], al[mt][2], al[mt][3], AsL + off);
                }
            }
            {
                int kk = ks * 16 + (lane & 7) + ((lane >> 3) & 1) * 8;
#pragma unroll
                for (int p = 0; p < 2; p++) {
                    int nn = wN * 32 + p * 16 + (lane >> 4) * 8;
                    unsigned t0, t1, t2, t3;
                    ldsm4t(t0, t1, t2, t3, BsH + kk * BNP + nn);
                    bh[2*p][0] = t0; bh[2*p][1] = t1;
                    bh[2*p+1][0] = t2; bh[2*p+1][1] = t3;
                }
            }
#pragma unroll
            for (int mt = 0; mt < 4; mt++)
#pragma unroll
                for (int nt = 0; nt < 4; nt++) {
                    mma16816(acc[mt][nt], ah[mt], bh[nt]);
                    mma16816(acc[mt][nt], al[mt], bh[nt]);
                }
        }
    }

#pragma unroll
    for (int mt = 0; mt < 4; mt++) {
        int r0 = brow + wM * 64 + mt * 16 + (lane >> 2);
#pragma unroll
        for (int nt = 0; nt < 4; nt++) {
            int col = bcol + wN * 32 + nt * 8 + (lane & 3) * 2;
#pragma unroll
            for (int half = 0; half < 2; half++) {
                int r = r0 + half * 8;
                if (r >= M) continue;
                float v0 = alpha * acc[mt][nt][half * 2 + 0];
                float v1 = alpha * acc[mt][nt][half * 2 + 1];
                if (mode == 0) {
                    if (bias) { v0 += bias[col]; v1 += bias[col + 1]; }
                    *(float2*)&outF[(size_t)r * N + col] = make_float2(v0, v1);
                } else if (mode == 1) {
                    bf h0, l0, h1, l1;
                    splitw(v0, h0, l0); splitw(v1, h1, l1);
                    size_t ro = (size_t)r * N + col;
                    *(__half2*)(outH + ro) = __halves2half2(h0, h1);
                    *(__half2*)(outL + ro) = __halves2half2(l0, l1);
                } else {
                    size_t ro = (size_t)orow(r, Lseg, segOff) * N + col;
                    *(__half2*)(outH + ro) =
                        __halves2half2(__float2half_rn(v0), __float2half_rn(v1));
                }
            }
        }
    }
}

// plain output-projection GEMM launch
__global__ __launch_bounds__(256, 2) void gemm_main(
    const bf* Ah, const bf* Al, const bf* Wh,
    const float* bias, float* outF, bf* outH, bf* outL,
    int M, int K, float alpha, int mode)
{
    extern __shared__ __align__(16) bf dynsm_g[];
    unsigned sbase = (unsigned)__cvta_generic_to_shared(dynsm_g);
    gemm_dev(dynsm_g, sbase, Ah, Al, Wh, M, K, blockIdx.x, blockIdx.y,
             alpha, mode, bias, outF, outH, outL, 0, 0);
}

// fused Q + KV projection launch
struct GSeg { const bf *Ah, *Al, *Wh; bf *Ch; int M, Lseg, segOff; };
struct GFused {
    const bf *QAh, *QAl, *QWh;
    bf *QCh, *QCl;
    GSeg s[6];
};
#define QBLOCKS (10 * (MQ / 128))   // 2560

__global__ __launch_bounds__(256, 2) void gemm_qkv(GFused P)
{
    extern __shared__ __align__(16) bf dynsm_f[];
    unsigned sbase = (unsigned)__cvta_generic_to_shared(dynsm_f);
    int bid = blockIdx.x;
    if (bid < QBLOCKS) {
        int bx = bid % 10, by = bid / 10;
        gemm_dev(dynsm_f, sbase, P.QAh, P.QAl, P.QWh, MQ, Dm, bx, by,
                 0.125f, 1, nullptr, nullptr, P.QCh, P.QCl, 0, 0);
    } else {
        int kid = bid - QBLOCKS;
        int z = kid / 50, rem = kid % 50;
        int by = rem / 10, bx = rem % 10;
        const GSeg s = P.s[z];
        if (by * 128 >= s.M) return;
        gemm_dev(dynsm_f, sbase, s.Ah, s.Al, s.Wh, s.M, Cm, bx, by,
                 1.0f, 2, nullptr, nullptr, s.Ch, nullptr, s.Lseg, s.segOff);
    }
}

// ---------------- register-resident fused attention ----------------
// Q 2-term x K 1-term; P 2-term x V 1-term.
#define TMA2 128
#define NTILE 2
#define AQS 72
#define AKS 120
#define AVS 72
#define A2_QH  0
#define A2_QL  (A2_QH + TMA2*AQS)
#define A2_KTH (A2_QL + TMA2*AQS)
#define A2_VH  (A2_KTH + 64*AKS)
#define ATT2_SMEM_BYTES ((A2_VH + 112*AVS) * 2)   // 68352

__global__ __launch_bounds__(256, 2) void attn3()
{
    extern __shared__ __align__(16) bf sm3[];
    bf* Qh  = sm3 + A2_QH;
    bf* Ql  = sm3 + A2_QL;
    bf* Kth = sm3 + A2_KTH;
    bf* Vh  = sm3 + A2_VH;

    const int t = threadIdx.x, lane = t & 31, warp = t >> 5;
    const int qq = blockIdx.x, h = blockIdx.y, b = blockIdx.z;
    const size_t kvbase = ((size_t)b * LTOT) * Dm + h * 64;

    // K^T load [d=64][l], pad cols 109..111 zero
    for (int idx = t; idx < LTOT * 64; idx += 256) {
        int l = idx >> 6, d = idx & 63;
        Kth[d * AKS + l] = gKh[kvbase + (size_t)l * Dm + d];
    }
    if (t < 192) {
        int d = t / 3, l = LTOT + t % 3;
        Kth[d * AKS + l] = __float2half(0.f);
    }
    // V load [l][d], pad rows 109..111 zero
    for (int idx = t; idx < LTOT * 8; idx += 256) {
        int l = idx >> 3, j = idx & 7;
        *(uint4*)(Vh + l * AVS + j * 8) = *(const uint4*)(gVh + kvbase + (size_t)l * Dm + j * 8);
    }
    uint4 z4 = make_uint4(0, 0, 0, 0);
    if (t < 24) {
        int l = LTOT + t / 8, j = t & 7;
        *(uint4*)(Vh + l * AVS + j * 8) = z4;
    }

    const int qbase = b * Sq + qq * (TMA2 * NTILE);

    auto loadQ = [&](int tile) {
        int q0 = qbase + tile * TMA2;
#pragma unroll
        for (int u = 0; u < 4; u++) {
            int i = t + u * 256;
            int r = i >> 3, j = i & 7;
            size_t go = (size_t)(q0 + r) * Dm + h * 64 + j * 8;
            cpa16(s2u(Qh + r * AQS + j * 8), gQh + go, 16);
            cpa16(s2u(Ql + r * AQS + j * 8), gQl + go, 16);
        }
    };

    loadQ(0);
    CP_COMMIT();

    for (int tile = 0; tile < NTILE; tile++) {
        CP_WAIT0();
        __syncthreads();

        // ---- S = Q @ K^T  (Q 2-term, K 1-term) ----
        float accs[14][4];
#pragma unroll
        for (int i = 0; i < 14; i++)
#pragma unroll
            for (int j = 0; j < 4; j++) accs[i][j] = 0.f;

#pragma unroll
        for (int ks = 0; ks < 4; ks++) {
            unsigned ah[4], al[4];
            int aoff = (warp * 16 + (lane & 15)) * AQS + ks * 16 + (lane >> 4) * 8;
            ldsm4(ah[0], ah[1], ah[2], ah[3], Qh + aoff);
            ldsm4(al[0], al[1], al[2], al[3], Ql + aoff);
            int kk = ks * 16 + (lane & 7) + ((lane >> 3) & 1) * 8;
#pragma unroll
            for (int p = 0; p < 7; p++) {
                int nn = p * 16 + (lane >> 4) * 8;
                unsigned t0, t1, t2, t3;
                ldsm4t(t0, t1, t2, t3, Kth + kk * AKS + nn);
                unsigned bh0[2] = {t0, t1}, bh1[2] = {t2, t3};
                mma16816(accs[2*p],   ah, bh0);
                mma16816(accs[2*p],   al, bh0);
                mma16816(accs[2*p+1], ah, bh1);
                mma16816(accs[2*p+1], al, bh1);
            }
        }
        __syncthreads();
        if (tile + 1 < NTILE) { loadQ(tile + 1); CP_COMMIT(); }

        // ---- in-register per-segment softmax ----
        const int cbase = (lane & 3) * 2;
#pragma unroll
        for (int j = 0; j < 2; j++) {
            float mx0 = -1e30f, mx1 = -1e30f, mx2 = -1e30f;
#pragma unroll
            for (int nt = 0; nt < 14; nt++)
#pragma unroll
                for (int e = 0; e < 2; e++) {
                    int c = nt * 8 + cbase + e;
                    float v = accs[nt][2*j + e];
                    if (c < LT) mx0 = fmaxf(mx0, v);
                    else if (c < LT + LI) mx1 = fmaxf(mx1, v);
                    else if (c < LTOT) mx2 = fmaxf(mx2, v);
                }
#pragma unroll
            for (int d = 1; d < 4; d <<= 1) {
                mx0 = fmaxf(mx0, __shfl_xor_sync(0xffffffffu, mx0, d));
                mx1 = fmaxf(mx1, __shfl_xor_sync(0xffffffffu, mx1, d));
                mx2 = fmaxf(mx2, __shfl_xor_sync(0xffffffffu, mx2, d));
            }
            float s0 = 0.f, s1 = 0.f, s2 = 0.f;
#pragma unroll
            for (int nt = 0; nt < 14; nt++)
#pragma unroll
                for (int e = 0; e < 2; e++) {
                    int c = nt * 8 + cbase + e;
                    float v = accs[nt][2*j + e], r;
                    if (c < LT)           { r = fexp(v - mx0); s0 += r; }
                    else if (c < LT + LI) { r = fexp(v - mx1); s1 += r; }
                    else if (c < LTOT)    { r = fexp(v - mx2); s2 += r; }
                    else r = 0.f;
                    accs[nt][2*j + e] = r;
                }
#pragma unroll
            for (int d = 1; d < 4; d <<= 1) {
                s0 += __shfl_xor_sync(0xffffffffu, s0, d);
                s1 += __shfl_xor_sync(0xffffffffu, s1, d);
                s2 += __shfl_xor_sync(0xffffffffu, s2, d);
            }
            float i0 = 1.0f / s0, i1 = 1.0f / s1, i2 = 1.0f / s2;
#pragma unroll
            for (int nt = 0; nt < 14; nt++)
#pragma unroll
                for (int e = 0; e < 2; e++) {
                    int c = nt * 8 + cbase + e;
                    float inv = (c < LT) ? i0 : (c < LT + LI) ? i1 : i2;
                    accs[nt][2*j + e] *= inv;
                }
        }

        // ---- O = P @ V  (P 2-term, V 1-term) ----
        float acco[8][4];
#pragma unroll
        for (int i = 0; i < 8; i++)
#pragma unroll
            for (int j = 0; j < 4; j++) acco[i][j] = 0.f;

#pragma unroll
        for (int ks = 0; ks < 7; ks++) {
            unsigned ah[4], al[4];
#pragma unroll
            for (int q = 0; q < 2; q++)
#pragma unroll
                for (int rr = 0; rr < 2; rr++) {
                    float v0 = accs[2*ks + q][2*rr + 0];
                    float v1 = accs[2*ks + q][2*rr + 1];
                    bf h0, l0, h1, l1;
                    splitw(v0, h0, l0);
                    splitw(v1, h1, l1);
                    __half2 hp = __halves2half2(h0, h1);
                    __half2 lp = __halves2half2(l0, l1);
                    ah[q*2 + rr] = *reinterpret_cast<unsigned*>(&hp);
                    al[q*2 + rr] = *reinterpret_cast<unsigned*>(&lp);
                }
            int kk = ks * 16 + (lane & 7) + ((lane >> 3) & 1) * 8;
#pragma unroll
            for (int p = 0; p < 4; p++) {
                int nn = p * 16 + (lane >> 4) * 8;
                unsigned t0, t1, t2, t3;
                ldsm4t(t0, t1, t2, t3, Vh + kk * AVS + nn);
                unsigned bh0[2] = {t0, t1}, bh1[2] = {t2, t3};
                mma16816(acco[2*p],   ah, bh0);
                mma16816(acco[2*p],   al, bh0);
                mma16816(acco[2*p+1], ah, bh1);
                mma16816(acco[2*p+1], al, bh1);
            }
        }

        int q0 = qbase + tile * TMA2;
#pragma unroll
        for (int nt = 0; nt < 8; nt++) {
            int c = h * 64 + nt * 8 + (lane & 3) * 2;
#pragma unroll
            for (int half = 0; half < 2; half++) {
                int r = warp * 16 + (lane >> 2) + half * 8;
                size_t ro = (size_t)(q0 + r) * Dm + c;
                bf h0, l0, h1, l1;
                splitw(acco[nt][half * 2 + 0], h0, l0);
                splitw(acco[nt][half * 2 + 1], h1, l1);
                *(__half2*)(gOh + ro) = __halves2half2(h0, h1);
                *(__half2*)(gOl + ro) = __halves2half2(l0, l1);
            }
        }
    }
}

// ---------------- launch ----------------
extern "C" void kernel_launch(void* const* d_in, const int* in_sizes, int n_in,
                              void* d_out, int out_size)
{
    const float* hidden  = (const float*)d_in[0];
    const float* text    = (const float*)d_in[1];
    const float* ids     = (const float*)d_in[2];
    const float* hair    = (const float*)d_in[3];
    const float* Wq      = (const float*)d_in[4];
    const float* Wk      = (const float*)d_in[5];
    const float* Wv      = (const float*)d_in[6];
    const float* Wo      = (const float*)d_in[7];
    const float* bo      = (const float*)d_in[8];
    const float* Wk_id   = (const float*)d_in[9];
    const float* Wv_id   = (const float*)d_in[10];
    const float* Wk_hair = (const float*)d_in[11];
    const float* Wv_hair = (const float*)d_in[12];
    float* out = (float*)d_out;

    bf *pHh, *pHl, *pQh, *pQl, *pOh, *pOl, *pTh, *pTl, *pIh, *pIl, *pRh, *pRl;
    bf *pKh, *pVh;
    bf *pWqH, *pWoH, *pWkH, *pWvH, *pWkiH, *pWviH, *pWkhH, *pWvhH;
    cudaGetSymbolAddress((void**)&pHh, gHh);   cudaGetSymbolAddress((void**)&pHl, gHl);
    cudaGetSymbolAddress((void**)&pQh, gQh);   cudaGetSymbolAddress((void**)&pQl, gQl);
    cudaGetSymbolAddress((void**)&pOh, gOh);   cudaGetSymbolAddress((void**)&pOl, gOl);
    cudaGetSymbolAddress((void**)&pTh, gTh);   cudaGetSymbolAddress((void**)&pTl, gTl);
    cudaGetSymbolAddress((void**)&pIh, gIh);   cudaGetSymbolAddress((void**)&pIl, gIl);
    cudaGetSymbolAddress((void**)&pRh, gRh);   cudaGetSymbolAddress((void**)&pRl, gRl);
    cudaGetSymbolAddress((void**)&pKh, gKh);   cudaGetSymbolAddress((void**)&pVh, gVh);
    cudaGetSymbolAddress((void**)&pWqH, gWqH);
    cudaGetSymbolAddress((void**)&pWoH, gWoH);
    cudaGetSymbolAddress((void**)&pWkH, gWkH);
    cudaGetSymbolAddress((void**)&pWvH, gWvH);
    cudaGetSymbolAddress((void**)&pWkiH, gWkiH);
    cudaGetSymbolAddress((void**)&pWviH, gWviH);
    cudaGetSymbolAddress((void**)&pWkhH, gWkhH);
    cudaGetSymbolAddress((void**)&pWvhH, gWvhH);

    cudaFuncSetAttribute(gemm_main, cudaFuncAttributeMaxDynamicSharedMemorySize, GEMM_SMEM_BYTES);
    cudaFuncSetAttribute(gemm_qkv,  cudaFuncAttributeMaxDynamicSharedMemorySize, GEMM_SMEM_BYTES);
    cudaFuncSetAttribute(attn3,     cudaFuncAttributeMaxDynamicSharedMemorySize, ATT2_SMEM_BYTES);

    // ---- launch 1: ALL splits ----
    {
        SplitArr A{};
        int off = 0, idx = 0;
        auto add = [&](const float* src, bf* dh, bf* dl, size_t n) {
            int n4 = (int)(n / 4);
            A.s[idx++] = { (const float4*)src, (uint2*)dh, (uint2*)dl, off, n4 };
            off += n4;
        };
        add(hidden,  pHh,  pHl,  (size_t)MQ * Dm);
        add(text,    pTh,  pTl,  (size_t)Bsz * LT * Cm);
        add(ids,     pIh,  pIl,  (size_t)Bsz * LI * Cm);
        add(hair,    pRh,  pRl,  (size_t)Bsz * LI * Cm);
        add(Wq,      pWqH,  nullptr, (size_t)Dm * Dm);
        add(Wo,      pWoH,  nullptr, (size_t)Dm * Dm);
        add(Wk,      pWkH,  nullptr, (size_t)Cm * Dm);
        add(Wv,      pWvH,  nullptr, (size_t)Cm * Dm);
        add(Wk_id,   pWkiH, nullptr, (size_t)Cm * Dm);
        add(Wv_id,   pWviH, nullptr, (size_t)Cm * Dm);
        add(Wk_hair, pWkhH, nullptr, (size_t)Cm * Dm);
        add(Wv_hair, pWvhH, nullptr, (size_t)Cm * Dm);
        A.cnt = idx;
        split_batch<<<(off + 255) / 256, 256>>>(A);
    }

    // ---- launch 2: fused Q + KV projections ----
    {
        GFused F{};
        F.QAh = pHh; F.QAl = pHl; F.QWh = pWqH;
        F.QCh = pQh; F.QCl = pQl;
        F.s[0] = { pTh, pTl, pWkH,  pKh, Bsz * LT, LT, 0 };
        F.s[1] = { pTh, pTl, pWvH,  pVh, Bsz * LT, LT, 0 };
        F.s[2] = { pIh, pIl, pWkiH, pKh, Bsz * LI, LI, LT };
        F.s[3] = { pIh, pIl, pWviH, pVh, Bsz * LI, LI, LT };
        F.s[4] = { pRh, pRl, pWkhH, pKh, Bsz * LI, LI, LT + LI };
        F.s[5] = { pRh, pRl, pWvhH, pVh, Bsz * LI, LI, LT + LI };
        gemm_qkv<<<QBLOCKS + 300, 256, GEMM_SMEM_BYTES>>>(F);
    }

    // ---- launch 3: fused attention ----
    attn3<<<dim3(16, Hn, Bsz), 256, ATT2_SMEM_BYTES>>>();

    // ---- launch 4: output projection ----
    gemm_main<<<dim3(Dm / 128, MQ / 128), 256, GEMM_SMEM_BYTES>>>(
        pOh, pOl, pWoH, bo, out, nullptr, nullptr, MQ, Dm, 1.0f, 0);
}

// round 15
// speedup vs baseline: 5.9011x; 1.0883x over previous
#include <cuda_runtime.h>
#include <cuda_fp16.h>
#include <cstdint>

// ---------------- problem constants ----------------
#define Bsz   8
#define Sq    4096
#define Dm    1280
#define Cm    2048
#define Hn    20
#define DHd   64
#define LT    77
#define LI    16
#define LTOT  109
#define MQ    (Bsz*Sq)

typedef __half bf;

// ---------------- scratch ----------------
__device__ bf gHh[(size_t)MQ*Dm], gHl[(size_t)MQ*Dm];
__device__ bf gQh[(size_t)MQ*Dm], gQl[(size_t)MQ*Dm];
__device__ bf gOh[(size_t)MQ*Dm], gOl[(size_t)MQ*Dm];
__device__ bf gTh[(size_t)Bsz*LT*Cm], gTl[(size_t)Bsz*LT*Cm];
__device__ bf gIh[(size_t)Bsz*LI*Cm], gIl[(size_t)Bsz*LI*Cm];
__device__ bf gRh[(size_t)Bsz*LI*Cm], gRl[(size_t)Bsz*LI*Cm];
__device__ bf gKh[(size_t)Bsz*LTOT*Dm];
__device__ bf gVh[(size_t)Bsz*LTOT*Dm];
__device__ bf gWqH[1280*1280];
__device__ bf gWoH[1280*1280];
__device__ bf gWkH[2048*1280];
__device__ bf gWvH[2048*1280];
__device__ bf gWkiH[2048*1280];
__device__ bf gWviH[2048*1280];
__device__ bf gWkhH[2048*1280];
__device__ bf gWvhH[2048*1280];

// ---------------- helpers ----------------
__device__ __forceinline__ void split2u(float x, float y, unsigned& hi, unsigned& lo)
{
    __half hx = __float2half_rn(x);
    __half hy = __float2half_rn(y);
    float rx = x - __half2float(hx);
    float ry = y - __half2float(hy);
    __half2 hp = __halves2half2(hx, hy);
    __half2 lp = __halves2half2(__float2half_rn(rx), __float2half_rn(ry));
    hi = *reinterpret_cast<unsigned*>(&hp);
    lo = *reinterpret_cast<unsigned*>(&lp);
}
__device__ __forceinline__ void splitw(float v, bf& h, bf& l)
{
    h = __float2half_rn(v);
    l = __float2half_rn(v - __half2float(h));
}
__device__ __forceinline__ unsigned s2u(const void* p)
{
    return (unsigned)__cvta_generic_to_shared(p);
}
__device__ __forceinline__ void cpa16(unsigned dst, const void* src, int sz)
{
    asm volatile("cp.async.cg.shared.global [%0], [%1], 16, %2;\n"
                 :: "r"(dst), "l"(src), "r"(sz));
}
#define CP_COMMIT() asm volatile("cp.async.commit_group;\n")
#define CP_WAIT0()  asm volatile("cp.async.wait_group 0;\n")

__device__ __forceinline__ void ldsm4(unsigned& r0, unsigned& r1, unsigned& r2, unsigned& r3,
                                      const void* p)
{
    unsigned a = s2u(p);
    asm volatile("ldmatrix.sync.aligned.m8n8.x4.shared.b16 {%0,%1,%2,%3},[%4];"
                 : "=r"(r0), "=r"(r1), "=r"(r2), "=r"(r3) : "r"(a));
}
__device__ __forceinline__ void ldsm4t(unsigned& r0, unsigned& r1, unsigned& r2, unsigned& r3,
                                       const void* p)
{
    unsigned a = s2u(p);
    asm volatile("ldmatrix.sync.aligned.m8n8.x4.trans.shared.b16 {%0,%1,%2,%3},[%4];"
                 : "=r"(r0), "=r"(r1), "=r"(r2), "=r"(r3) : "r"(a));
}
__device__ __forceinline__ void mma16816(float* c, const unsigned* a, const unsigned* b)
{
    asm volatile(
        "mma.sync.aligned.m16n8k16.row.col.f32.f16.f16.f32 "
        "{%0,%1,%2,%3}, {%4,%5,%6,%7}, {%8,%9}, {%0,%1,%2,%3};"
        : "+f"(c[0]), "+f"(c[1]), "+f"(c[2]), "+f"(c[3])
        : "r"(a[0]), "r"(a[1]), "r"(a[2]), "r"(a[3]), "r"(b[0]), "r"(b[1]));
}

// FMA-only exp (x <= 0 expected)
__device__ __forceinline__ float fexp(float x)
{
    float t  = x * 1.4426950408889634f;
    float fl = floorf(t);
    float f  = t - fl;
    float p  = 1.5403e-4f;
    p = fmaf(p, f, 1.3333558e-3f);
    p = fmaf(p, f, 9.6181291e-3f);
    p = fmaf(p, f, 5.5504109e-2f);
    p = fmaf(p, f, 2.4022651e-1f);
    p = fmaf(p, f, 6.9314718e-1f);
    p = fmaf(p, f, 1.0f);
    int i = (int)fl;
    i = max(i, -126);
    return p * __int_as_float((i + 127) << 23);
}

// ---------------- batched split kernel (dl==nullptr -> hi-only) ----------------
struct SplitSeg { const float4* src; uint2* dh; uint2* dl; int off; int n4; };
struct SplitArr { SplitSeg s[12]; int cnt; };

__global__ __launch_bounds__(256) void split_batch(SplitArr P)
{
    int gid = blockIdx.x * 256 + threadIdx.x;
#pragma unroll 1
    for (int sg = 0; sg < P.cnt; sg++) {
        int local = gid - P.s[sg].off;
        if (local >= 0 && local < P.s[sg].n4) {
            float4 v = P.s[sg].src[local];
            unsigned h0, l0, h1, l1;
            split2u(v.x, v.y, h0, l0);
            split2u(v.z, v.w, h1, l1);
            P.s[sg].dh[local] = make_uint2(h0, h1);
            if (P.s[sg].dl) P.s[sg].dl[local] = make_uint2(l0, l1);
            return;
        }
    }
}

// ---------------- fp16-split GEMM: A 2-term, B 1-term; BK=64, 2-stage ----------------
#define BKT 64
#define BKP 72
#define BNP 136
#define STG_A (128*BKP)     // per A term: 9216
#define STG_B (BKT*BNP)     // 8704
#define STG   (2*STG_A + STG_B)   // 27136
#define GEMM_SMEM_BYTES (2*STG*2)  // 108544

__device__ __forceinline__ int orow(int r, int Lseg, int segOff)
{
    if (Lseg == 0) return r;
    int b = r / Lseg;
    return b * LTOT + segOff + (r - b * Lseg);
}

// mode: 0 = fp32 out (+bias); 1 = split hi/lo out; 2 = hi-only out with orow
__device__ __forceinline__ void gemm_dev(
    bf* dynsm, unsigned sbase,
    const bf* __restrict__ Ah, const bf* __restrict__ Al,
    const bf* __restrict__ Wh,
    int M, int K, int bx, int by, float alpha, int mode,
    const float* __restrict__ bias, float* __restrict__ outF,
    bf* __restrict__ outH, bf* __restrict__ outL, int Lseg, int segOff)
{
    const int N = Dm;
    const int tid = threadIdx.x, lane = tid & 31, warp = tid >> 5;
    const int wM = warp >> 2, wN = warp & 3;
    const int brow = by * 128, bcol = bx * 128;

    float acc[4][4][4];
#pragma unroll
    for (int i = 0; i < 4; i++)
#pragma unroll
        for (int j = 0; j < 4; j++)
#pragma unroll
            for (int q = 0; q < 4; q++) acc[i][j][q] = 0.f;

    const int nT = K / BKT;

    auto load_stage = [&](int st, int k0) {
        unsigned aH = sbase + (unsigned)(st * STG) * 2;
        unsigned aL = aH + STG_A * 2;
        unsigned bH = aL + STG_A * 2;
        // A tiles: 128 rows x 64 k, hi+lo (1024 chunks each)
#pragma unroll
        for (int u = 0; u < 4; u++) {
            int i = tid + u * 256;            // 0..1023
            int row = i >> 3, k8 = (i & 7) * 8;
            const bf* sH = Ah + (size_t)(brow + row) * K + k0 + k8;
            const bf* sL = Al + (size_t)(brow + row) * K + k0 + k8;
            int ok = 16;
            if (brow + row >= M) { sH = Ah; sL = Al; ok = 0; }
            cpa16(aH + (unsigned)(row * BKP + k8) * 2, sH, ok);
            cpa16(aL + (unsigned)(row * BKP + k8) * 2, sL, ok);
        }
        // B tile: 64 k-rows x 128 n (1024 chunks)
#pragma unroll
        for (int u = 0; u < 4; u++) {
            int j = tid + u * 256;            // 0..1023
            int kr = j >> 4, n8 = (j & 15) * 8;
            cpa16(bH + (unsigned)(kr * BNP + n8) * 2,
                  Wh + (size_t)(k0 + kr) * N + bcol + n8, 16);
        }
    };

    load_stage(0, 0);
    CP_COMMIT();

    for (int t = 0; t < nT; t++) {
        CP_WAIT0();
        __syncthreads();
        if (t + 1 < nT) { load_stage((t + 1) & 1, (t + 1) * BKT); CP_COMMIT(); }

        bf* AsH = dynsm + (t & 1) * STG;
        bf* AsL = AsH + STG_A;
        bf* BsH = AsL + STG_A;

#pragma unroll
        for (int ks = 0; ks < 4; ks++) {
            unsigned ah[4][4], al[4][4], bh[4][2];
            {
                int rowb = wM * 64 + (lane & 15);
                int kk   = ks * 16 + (lane >> 4) * 8;
#pragma unroll
                for (int mt = 0; mt < 4; mt++) {
                    int off = (rowb + mt * 16) * BKP + kk;
                    ldsm4(ah[mt][0], ah[mt][1], ah[mt][2], ah[mt][3], AsH + off);
                    ldsm4(al[mt][0], al[mt][1], al[mt][2], al[mt][3], AsL + off);
                }
            }
            {
                int kk = ks * 16 + (lane & 7) + ((lane >> 3) & 1) * 8;
#pragma unroll
                for (int p = 0; p < 2; p++) {
                    int nn = wN * 32 + p * 16 + (lane >> 4) * 8;
                    unsigned t0, t1, t2, t3;
                    ldsm4t(t0, t1, t2, t3, BsH + kk * BNP + nn);
                    bh[2*p][0] = t0; bh[2*p][1] = t1;
                    bh[2*p+1][0] = t2; bh[2*p+1][1] = t3;
                }
            }
#pragma unroll
            for (int mt = 0; mt < 4; mt++)
#pragma unroll
                for (int nt = 0; nt < 4; nt++) {
                    mma16816(acc[mt][nt], ah[mt], bh[nt]);
                    mma16816(acc[mt][nt], al[mt], bh[nt]);
                }
        }
    }

#pragma unroll
    for (int mt = 0; mt < 4; mt++) {
        int r0 = brow + wM * 64 + mt * 16 + (lane >> 2);
#pragma unroll
        for (int nt = 0; nt < 4; nt++) {
            int col = bcol + wN * 32 + nt * 8 + (lane & 3) * 2;
#pragma unroll
            for (int half = 0; half < 2; half++) {
                int r = r0 + half * 8;
                if (r >= M) continue;
                float v0 = alpha * acc[mt][nt][half * 2 + 0];
                float v1 = alpha * acc[mt][nt][half * 2 + 1];
                if (mode == 0) {
                    if (bias) { v0 += bias[col]; v1 += bias[col + 1]; }
                    *(float2*)&outF[(size_t)r * N + col] = make_float2(v0, v1);
                } else if (mode == 1) {
                    bf h0, l0, h1, l1;
                    splitw(v0, h0, l0); splitw(v1, h1, l1);
                    size_t ro = (size_t)r * N + col;
                    *(__half2*)(outH + ro) = __halves2half2(h0, h1);
                    *(__half2*)(outL + ro) = __halves2half2(l0, l1);
                } else {
                    size_t ro = (size_t)orow(r, Lseg, segOff) * N + col;
                    *(__half2*)(outH + ro) =
                        __halves2half2(__float2half_rn(v0), __float2half_rn(v1));
                }
            }
        }
    }
}

__global__ __launch_bounds__(256, 2) void gemm_main(
    const bf* Ah, const bf* Al, const bf* Wh,
    const float* bias, float* outF, bf* outH, bf* outL,
    int M, int K, float alpha, int mode)
{
    extern __shared__ __align__(16) bf dynsm_g[];
    unsigned sbase = (unsigned)__cvta_generic_to_shared(dynsm_g);
    gemm_dev(dynsm_g, sbase, Ah, Al, Wh, M, K, blockIdx.x, blockIdx.y,
             alpha, mode, bias, outF, outH, outL, 0, 0);
}

struct GSeg { const bf *Ah, *Al, *Wh; bf *Ch; int M, Lseg, segOff; };
struct GFused {
    const bf *QAh, *QAl, *QWh;
    bf *QCh, *QCl;
    GSeg s[6];
};
#define QBLOCKS (10 * (MQ / 128))   // 2560

__global__ __launch_bounds__(256, 2) void gemm_qkv(GFused P)
{
    extern __shared__ __align__(16) bf dynsm_f[];
    unsigned sbase = (unsigned)__cvta_generic_to_shared(dynsm_f);
    int bid = blockIdx.x;
    if (bid < QBLOCKS) {
        int bx = bid % 10, by = bid / 10;
        gemm_dev(dynsm_f, sbase, P.QAh, P.QAl, P.QWh, MQ, Dm, bx, by,
                 0.125f, 1, nullptr, nullptr, P.QCh, P.QCl, 0, 0);
    } else {
        int kid = bid - QBLOCKS;
        int z = kid / 50, rem = kid % 50;
        int by = rem / 10, bx = rem % 10;
        const GSeg s = P.s[z];
        if (by * 128 >= s.M) return;
        gemm_dev(dynsm_f, sbase, s.Ah, s.Al, s.Wh, s.M, Cm, bx, by,
                 1.0f, 2, nullptr, nullptr, s.Ch, nullptr, s.Lseg, s.segOff);
    }
}

// ---------------- register-resident fused attention (unchanged from R13) ----------------
#define TMA2 128
#define NTILE 2
#define AQS 72
#define AKS 120
#define AVS 72
#define A2_QH  0
#define A2_QL  (A2_QH + TMA2*AQS)
#define A2_KTH (A2_QL + TMA2*AQS)
#define A2_VH  (A2_KTH + 64*AKS)
#define ATT2_SMEM_BYTES ((A2_VH + 112*AVS) * 2)   // 68352

__global__ __launch_bounds__(256, 2) void attn3()
{
    extern __shared__ __align__(16) bf sm3[];
    bf* Qh  = sm3 + A2_QH;
    bf* Ql  = sm3 + A2_QL;
    bf* Kth = sm3 + A2_KTH;
    bf* Vh  = sm3 + A2_VH;

    const int t = threadIdx.x, lane = t & 31, warp = t >> 5;
    const int qq = blockIdx.x, h = blockIdx.y, b = blockIdx.z;
    const size_t kvbase = ((size_t)b * LTOT) * Dm + h * 64;

    for (int idx = t; idx < LTOT * 64; idx += 256) {
        int l = idx >> 6, d = idx & 63;
        Kth[d * AKS + l] = gKh[kvbase + (size_t)l * Dm + d];
    }
    if (t < 192) {
        int d = t / 3, l = LTOT + t % 3;
        Kth[d * AKS + l] = __float2half(0.f);
    }
    for (int idx = t; idx < LTOT * 8; idx += 256) {
        int l = idx >> 3, j = idx & 7;
        *(uint4*)(Vh + l * AVS + j * 8) = *(const uint4*)(gVh + kvbase + (size_t)l * Dm + j * 8);
    }
    uint4 z4 = make_uint4(0, 0, 0, 0);
    if (t < 24) {
        int l = LTOT + t / 8, j = t & 7;
        *(uint4*)(Vh + l * AVS + j * 8) = z4;
    }

    const int qbase = b * Sq + qq * (TMA2 * NTILE);

    auto loadQ = [&](int tile) {
        int q0 = qbase + tile * TMA2;
#pragma unroll
        for (int u = 0; u < 4; u++) {
            int i = t + u * 256;
            int r = i >> 3, j = i & 7;
            size_t go = (size_t)(q0 + r) * Dm + h * 64 + j * 8;
            cpa16(s2u(Qh + r * AQS + j * 8), gQh + go, 16);
            cpa16(s2u(Ql + r * AQS + j * 8), gQl + go, 16);
        }
    };

    loadQ(0);
    CP_COMMIT();

    for (int tile = 0; tile < NTILE; tile++) {
        CP_WAIT0();
        __syncthreads();

        float accs[14][4];
#pragma unroll
        for (int i = 0; i < 14; i++)
#pragma unroll
            for (int j = 0; j < 4; j++) accs[i][j] = 0.f;

#pragma unroll
        for (int ks = 0; ks < 4; ks++) {
            unsigned ah[4], al[4];
            int aoff = (warp * 16 + (lane & 15)) * AQS + ks * 16 + (lane >> 4) * 8;
            ldsm4(ah[0], ah[1], ah[2], ah[3], Qh + aoff);
            ldsm4(al[0], al[1], al[2], al[3], Ql + aoff);
            int kk = ks * 16 + (lane & 7) + ((lane >> 3) & 1) * 8;
#pragma unroll
            for (int p = 0; p < 7; p++) {
                int nn = p * 16 + (lane >> 4) * 8;
                unsigned t0, t1, t2, t3;
                ldsm4t(t0, t1, t2, t3, Kth + kk * AKS + nn);
                unsigned bh0[2] = {t0, t1}, bh1[2] = {t2, t3};
                mma16816(accs[2*p],   ah, bh0);
                mma16816(accs[2*p],   al, bh0);
                mma16816(accs[2*p+1], ah, bh1);
                mma16816(accs[2*p+1], al, bh1);
            }
        }
        __syncthreads();
        if (tile + 1 < NTILE) { loadQ(tile + 1); CP_COMMIT(); }

        const int cbase = (lane & 3) * 2;
#pragma unroll
        for (int j = 0; j < 2; j++) {
            float mx0 = -1e30f, mx1 = -1e30f, mx2 = -1e30f;
#pragma unroll
            for (int nt = 0; nt < 14; nt++)
#pragma unroll
                for (int e = 0; e < 2; e++) {
                    int c = nt * 8 + cbase + e;
                    float v = accs[nt][2*j + e];
                    if (c < LT) mx0 = fmaxf(mx0, v);
                    else if (c < LT + LI) mx1 = fmaxf(mx1, v);
                    else if (c < LTOT) mx2 = fmaxf(mx2, v);
                }
#pragma unroll
            for (int d = 1; d < 4; d <<= 1) {
                mx0 = fmaxf(mx0, __shfl_xor_sync(0xffffffffu, mx0, d));
                mx1 = fmaxf(mx1, __shfl_xor_sync(0xffffffffu, mx1, d));
                mx2 = fmaxf(mx2, __shfl_xor_sync(0xffffffffu, mx2, d));
            }
            float s0 = 0.f, s1 = 0.f, s2 = 0.f;
#pragma unroll
            for (int nt = 0; nt < 14; nt++)
#pragma unroll
                for (int e = 0; e < 2; e++) {
                    int c = nt * 8 + cbase + e;
                    float v = accs[nt][2*j + e], r;
                    if (c < LT)           { r = fexp(v - mx0); s0 += r; }
                    else if (c < LT + LI) { r = fexp(v - mx1); s1 += r; }
                    else if (c < LTOT)    { r = fexp(v - mx2); s2 += r; }
                    else r = 0.f;
                    accs[nt][2*j + e] = r;
                }
#pragma unroll
            for (int d = 1; d < 4; d <<= 1) {
                s0 += __shfl_xor_sync(0xffffffffu, s0, d);
                s1 += __shfl_xor_sync(0xffffffffu, s1, d);
                s2 += __shfl_xor_sync(0xffffffffu, s2, d);
            }
            float i0 = 1.0f / s0, i1 = 1.0f / s1, i2 = 1.0f / s2;
#pragma unroll
            for (int nt = 0; nt < 14; nt++)
#pragma unroll
                for (int e = 0; e < 2; e++) {
                    int c = nt * 8 + cbase + e;
                    float inv = (c < LT) ? i0 : (c < LT + LI) ? i1 : i2;
                    accs[nt][2*j + e] *= inv;
                }
        }

        float acco[8][4];
#pragma unroll
        for (int i = 0; i < 8; i++)
#pragma unroll
            for (int j = 0; j < 4; j++) acco[i][j] = 0.f;

#pragma unroll
        for (int ks = 0; ks < 7; ks++) {
            unsigned ah[4], al[4];
#pragma unroll
            for (int q = 0; q < 2; q++)
#pragma unroll
                for (int rr = 0; rr < 2; rr++) {
                    float v0 = accs[2*ks + q][2*rr + 0];
                    float v1 = accs[2*ks + q][2*rr + 1];
                    bf h0, l0, h1, l1;
                    splitw(v0, h0, l0);
                    splitw(v1, h1, l1);
                    __half2 hp = __halves2half2(h0, h1);
                    __half2 lp = __halves2half2(l0, l1);
                    ah[q*2 + rr] = *reinterpret_cast<unsigned*>(&hp);
                    al[q*2 + rr] = *reinterpret_cast<unsigned*>(&lp);
                }
            int kk = ks * 16 + (lane & 7) + ((lane >> 3) & 1) * 8;
#pragma unroll
            for (int p = 0; p < 4; p++) {
                int nn = p * 16 + (lane >> 4) * 8;
                unsigned t0, t1, t2, t3;
                ldsm4t(t0, t1, t2, t3, Vh + kk * AVS + nn);
                unsigned bh0[2] = {t0, t1}, bh1[2] = {t2, t3};
                mma16816(acco[2*p],   ah, bh0);
                mma16816(acco[2*p],   al, bh0);
                mma16816(acco[2*p+1], ah, bh1);
                mma16816(acco[2*p+1], al, bh1);
            }
        }

        int q0 = qbase + tile * TMA2;
#pragma unroll
        for (int nt = 0; nt < 8; nt++) {
            int c = h * 64 + nt * 8 + (lane & 3) * 2;
#pragma unroll
            for (int half = 0; half < 2; half++) {
                int r = warp * 16 + (lane >> 2) + half * 8;
                size_t ro = (size_t)(q0 + r) * Dm + c;
                bf h0, l0, h1, l1;
                splitw(acco[nt][half * 2 + 0], h0, l0);
                splitw(acco[nt][half * 2 + 1], h1, l1);
                *(__half2*)(gOh + ro) = __halves2half2(h0, h1);
                *(__half2*)(gOl + ro) = __halves2half2(l0, l1);
            }
        }
    }
}

// ---------------- launch ----------------
extern "C" void kernel_launch(void* const* d_in, const int* in_sizes, int n_in,
                              void* d_out, int out_size)
{
    const float* hidden  = (const float*)d_in[0];
    const float* text    = (const float*)d_in[1];
    const float* ids     = (const float*)d_in[2];
    const float* hair    = (const float*)d_in[3];
    const float* Wq      = (const float*)d_in[4];
    const float* Wk      = (const float*)d_in[5];
    const float* Wv      = (const float*)d_in[6];
    const float* Wo      = (const float*)d_in[7];
    const float* bo      = (const float*)d_in[8];
    const float* Wk_id   = (const float*)d_in[9];
    const float* Wv_id   = (const float*)d_in[10];
    const float* Wk_hair = (const float*)d_in[11];
    const float* Wv_hair = (const float*)d_in[12];
    float* out = (float*)d_out;

    bf *pHh, *pHl, *pQh, *pQl, *pOh, *pOl, *pTh, *pTl, *pIh, *pIl, *pRh, *pRl;
    bf *pKh, *pVh;
    bf *pWqH, *pWoH, *pWkH, *pWvH, *pWkiH, *pWviH, *pWkhH, *pWvhH;
    cudaGetSymbolAddress((void**)&pHh, gHh);   cudaGetSymbolAddress((void**)&pHl, gHl);
    cudaGetSymbolAddress((void**)&pQh, gQh);   cudaGetSymbolAddress((void**)&pQl, gQl);
    cudaGetSymbolAddress((void**)&pOh, gOh);   cudaGetSymbolAddress((void**)&pOl, gOl);
    cudaGetSymbolAddress((void**)&pTh, gTh);   cudaGetSymbolAddress((void**)&pTl, gTl);
    cudaGetSymbolAddress((void**)&pIh, gIh);   cudaGetSymbolAddress((void**)&pIl, gIl);
    cudaGetSymbolAddress((void**)&pRh, gRh);   cudaGetSymbolAddress((void**)&pRl, gRl);
    cudaGetSymbolAddress((void**)&pKh, gKh);   cudaGetSymbolAddress((void**)&pVh, gVh);
    cudaGetSymbolAddress((void**)&pWqH, gWqH);
    cudaGetSymbolAddress((void**)&pWoH, gWoH);
    cudaGetSymbolAddress((void**)&pWkH, gWkH);
    cudaGetSymbolAddress((void**)&pWvH, gWvH);
    cudaGetSymbolAddress((void**)&pWkiH, gWkiH);
    cudaGetSymbolAddress((void**)&pWviH, gWviH);
    cudaGetSymbolAddress((void**)&pWkhH, gWkhH);
    cudaGetSymbolAddress((void**)&pWvhH, gWvhH);

    cudaFuncSetAttribute(gemm_main, cudaFuncAttributeMaxDynamicSharedMemorySize, GEMM_SMEM_BYTES);
    cudaFuncSetAttribute(gemm_qkv,  cudaFuncAttributeMaxDynamicSharedMemorySize, GEMM_SMEM_BYTES);
    cudaFuncSetAttribute(attn3,     cudaFuncAttributeMaxDynamicSharedMemorySize, ATT2_SMEM_BYTES);

    // ---- launch 1: ALL splits ----
    {
        SplitArr A{};
        int off = 0, idx = 0;
        auto add = [&](const float* src, bf* dh, bf* dl, size_t n) {
            int n4 = (int)(n / 4);
            A.s[idx++] = { (const float4*)src, (uint2*)dh, (uint2*)dl, off, n4 };
            off += n4;
        };
        add(hidden,  pHh,  pHl,  (size_t)MQ * Dm);
        add(text,    pTh,  pTl,  (size_t)Bsz * LT * Cm);
        add(ids,     pIh,  pIl,  (size_t)Bsz * LI * Cm);
        add(hair,    pRh,  pRl,  (size_t)Bsz * LI * Cm);
        add(Wq,      pWqH,  nullptr, (size_t)Dm * Dm);
        add(Wo,      pWoH,  nullptr, (size_t)Dm * Dm);
        add(Wk,      pWkH,  nullptr, (size_t)Cm * Dm);
        add(Wv,      pWvH,  nullptr, (size_t)Cm * Dm);
        add(Wk_id,   pWkiH, nullptr, (size_t)Cm * Dm);
        add(Wv_id,   pWviH, nullptr, (size_t)Cm * Dm);
        add(Wk_hair, pWkhH, nullptr, (size_t)Cm * Dm);
        add(Wv_hair, pWvhH, nullptr, (size_t)Cm * Dm);
        A.cnt = idx;
        split_batch<<<(off + 255) / 256, 256>>>(A);
    }

    // ---- launch 2: fused Q + KV projections ----
    {
        GFused F{};
        F.QAh = pHh; F.QAl = pHl; F.QWh = pWqH;
        F.QCh = pQh; F.QCl = pQl;
        F.s[0] = { pTh, pTl, pWkH,  pKh, Bsz * LT, LT, 0 };
        F.s[1] = { pTh, pTl, pWvH,  pVh, Bsz * LT, LT, 0 };
        F.s[2] = { pIh, pIl, pWkiH, pKh, Bsz * LI, LI, LT };
        F.s[3] = { pIh, pIl, pWviH, pVh, Bsz * LI, LI, LT };
        F.s[4] = { pRh, pRl, pWkhH, pKh, Bsz * LI, LI, LT + LI };
        F.s[5] = { pRh, pRl, pWvhH, pVh, Bsz * LI, LI, LT + LI };
        gemm_qkv<<<QBLOCKS + 300, 256, GEMM_SMEM_BYTES>>>(F);
    }

    // ---- launch 3: fused attention ----
    attn3<<<dim3(16, Hn, Bsz), 256, ATT2_SMEM_BYTES>>>();

    // ---- launch 4: output projection ----
    gemm_main<<<dim3(Dm / 128, MQ / 128), 256, GEMM_SMEM_BYTES>>>(
        pOh, pOl, pWoH, bo, out, nullptr, nullptr, MQ, Dm, 1.0f, 0);
}

// round 16
// speedup vs baseline: 6.2750x; 1.0634x over previous
#include <cuda_runtime.h>
#include <cuda_fp16.h>
#include <cstdint>

// ---------------- problem constants ----------------
#define Bsz   8
#define Sq    4096
#define Dm    1280
#define Cm    2048
#define Hn    20
#define DHd   64
#define LT    77
#define LI    16
#define LTOT  109
#define MQ    (Bsz*Sq)

typedef __half bf;

// ---------------- scratch ----------------
__device__ bf gHh[(size_t)MQ*Dm], gHl[(size_t)MQ*Dm];
__device__ bf gQh[(size_t)MQ*Dm];                 // Q single-term
__device__ bf gOh[(size_t)MQ*Dm];                 // attention out single-term
__device__ bf gTh[(size_t)Bsz*LT*Cm], gTl[(size_t)Bsz*LT*Cm];
__device__ bf gIh[(size_t)Bsz*LI*Cm], gIl[(size_t)Bsz*LI*Cm];
__device__ bf gRh[(size_t)Bsz*LI*Cm], gRl[(size_t)Bsz*LI*Cm];
__device__ bf gKh[(size_t)Bsz*LTOT*Dm];
__device__ bf gVh[(size_t)Bsz*LTOT*Dm];
__device__ bf gWqH[1280*1280];
__device__ bf gWoH[1280*1280];
__device__ bf gWkH[2048*1280];
__device__ bf gWvH[2048*1280];
__device__ bf gWkiH[2048*1280];
__device__ bf gWviH[2048*1280];
__device__ bf gWkhH[2048*1280];
__device__ bf gWvhH[2048*1280];

// ---------------- helpers ----------------
__device__ __forceinline__ void split2u(float x, float y, unsigned& hi, unsigned& lo)
{
    __half hx = __float2half_rn(x);
    __half hy = __float2half_rn(y);
    float rx = x - __half2float(hx);
    float ry = y - __half2float(hy);
    __half2 hp = __halves2half2(hx, hy);
    __half2 lp = __halves2half2(__float2half_rn(rx), __float2half_rn(ry));
    hi = *reinterpret_cast<unsigned*>(&hp);
    lo = *reinterpret_cast<unsigned*>(&lp);
}
__device__ __forceinline__ void splitw(float v, bf& h, bf& l)
{
    h = __float2half_rn(v);
    l = __float2half_rn(v - __half2float(h));
}
__device__ __forceinline__ unsigned s2u(const void* p)
{
    return (unsigned)__cvta_generic_to_shared(p);
}
__device__ __forceinline__ void cpa16(unsigned dst, const void* src, int sz)
{
    asm volatile("cp.async.cg.shared.global [%0], [%1], 16, %2;\n"
                 :: "r"(dst), "l"(src), "r"(sz));
}
#define CP_COMMIT() asm volatile("cp.async.commit_group;\n")
#define CP_WAIT0()  asm volatile("cp.async.wait_group 0;\n")

__device__ __forceinline__ void ldsm4(unsigned& r0, unsigned& r1, unsigned& r2, unsigned& r3,
                                      const void* p)
{
    unsigned a = s2u(p);
    asm volatile("ldmatrix.sync.aligned.m8n8.x4.shared.b16 {%0,%1,%2,%3},[%4];"
                 : "=r"(r0), "=r"(r1), "=r"(r2), "=r"(r3) : "r"(a));
}
__device__ __forceinline__ void ldsm4t(unsigned& r0, unsigned& r1, unsigned& r2, unsigned& r3,
                                       const void* p)
{
    unsigned a = s2u(p);
    asm volatile("ldmatrix.sync.aligned.m8n8.x4.trans.shared.b16 {%0,%1,%2,%3},[%4];"
                 : "=r"(r0), "=r"(r1), "=r"(r2), "=r"(r3) : "r"(a));
}
__device__ __forceinline__ void mma16816(float* c, const unsigned* a, const unsigned* b)
{
    asm volatile(
        "mma.sync.aligned.m16n8k16.row.col.f32.f16.f16.f32 "
        "{%0,%1,%2,%3}, {%4,%5,%6,%7}, {%8,%9}, {%0,%1,%2,%3};"
        : "+f"(c[0]), "+f"(c[1]), "+f"(c[2]), "+f"(c[3])
        : "r"(a[0]), "r"(a[1]), "r"(a[2]), "r"(a[3]), "r"(b[0]), "r"(b[1]));
}

// FMA-only exp (x <= 0 expected)
__device__ __forceinline__ float fexp(float x)
{
    float t  = x * 1.4426950408889634f;
    float fl = floorf(t);
    float f  = t - fl;
    float p  = 1.5403e-4f;
    p = fmaf(p, f, 1.3333558e-3f);
    p = fmaf(p, f, 9.6181291e-3f);
    p = fmaf(p, f, 5.5504109e-2f);
    p = fmaf(p, f, 2.4022651e-1f);
    p = fmaf(p, f, 6.9314718e-1f);
    p = fmaf(p, f, 1.0f);
    int i = (int)fl;
    i = max(i, -126);
    return p * __int_as_float((i + 127) << 23);
}

// ---------------- batched split kernel (dl==nullptr -> hi-only) ----------------
struct SplitSeg { const float4* src; uint2* dh; uint2* dl; int off; int n4; };
struct SplitArr { SplitSeg s[12]; int cnt; };

__global__ __launch_bounds__(256) void split_batch(SplitArr P)
{
    int gid = blockIdx.x * 256 + threadIdx.x;
#pragma unroll 1
    for (int sg = 0; sg < P.cnt; sg++) {
        int local = gid - P.s[sg].off;
        if (local >= 0 && local < P.s[sg].n4) {
            float4 v = P.s[sg].src[local];
            unsigned h0, l0, h1, l1;
            split2u(v.x, v.y, h0, l0);
            split2u(v.z, v.w, h1, l1);
            P.s[sg].dh[local] = make_uint2(h0, h1);
            if (P.s[sg].dl) P.s[sg].dl[local] = make_uint2(l0, l1);
            return;
        }
    }
}

// ---------------- fp16-split GEMM: A 2- or 1-term (Al nullable), B 1-term; BK=64 ----------------
#define BKT 64
#define BKP 72
#define BNP 136
#define STG_A (128*BKP)
#define STG_B (BKT*BNP)
#define STG   (2*STG_A + STG_B)
#define GEMM_SMEM_BYTES (2*STG*2)  // 108544

__device__ __forceinline__ int orow(int r, int Lseg, int segOff)
{
    if (Lseg == 0) return r;
    int b = r / Lseg;
    return b * LTOT + segOff + (r - b * Lseg);
}

// mode: 0 = fp32 out (+bias); 2 = hi-only fp16 out with orow
__device__ __forceinline__ void gemm_dev(
    bf* dynsm, unsigned sbase,
    const bf* __restrict__ Ah, const bf* __restrict__ Al,   // Al may be nullptr
    const bf* __restrict__ Wh,
    int M, int K, int bx, int by, float alpha, int mode,
    const float* __restrict__ bias, float* __restrict__ outF,
    bf* __restrict__ outH, int Lseg, int segOff)
{
    const int N = Dm;
    const int tid = threadIdx.x, lane = tid & 31, warp = tid >> 5;
    const int wM = warp >> 2, wN = warp & 3;
    const int brow = by * 128, bcol = bx * 128;
    const bool twoTerm = (Al != nullptr);

    float acc[4][4][4];
#pragma unroll
    for (int i = 0; i < 4; i++)
#pragma unroll
        for (int j = 0; j < 4; j++)
#pragma unroll
            for (int q = 0; q < 4; q++) acc[i][j][q] = 0.f;

    const int nT = K / BKT;

    auto load_stage = [&](int st, int k0) {
        unsigned aH = sbase + (unsigned)(st * STG) * 2;
        unsigned aL = aH + STG_A * 2;
        unsigned bH = aL + STG_A * 2;
#pragma unroll
        for (int u = 0; u < 4; u++) {
            int i = tid + u * 256;
            int row = i >> 3, k8 = (i & 7) * 8;
            const bf* sH = Ah + (size_t)(brow + row) * K + k0 + k8;
            int ok = 16;
            if (brow + row >= M) { sH = Ah; ok = 0; }
            cpa16(aH + (unsigned)(row * BKP + k8) * 2, sH, ok);
            if (twoTerm) {
                const bf* sL = Al + (size_t)(brow + row) * K + k0 + k8;
                if (brow + row >= M) sL = Al;
                cpa16(aL + (unsigned)(row * BKP + k8) * 2, sL, ok);
            }
        }
#pragma unroll
        for (int u = 0; u < 4; u++) {
            int j = tid + u * 256;
            int kr = j >> 4, n8 = (j & 15) * 8;
            cpa16(bH + (unsigned)(kr * BNP + n8) * 2,
                  Wh + (size_t)(k0 + kr) * N + bcol + n8, 16);
        }
    };

    load_stage(0, 0);
    CP_COMMIT();

    for (int t = 0; t < nT; t++) {
        CP_WAIT0();
        __syncthreads();
        if (t + 1 < nT) { load_stage((t + 1) & 1, (t + 1) * BKT); CP_COMMIT(); }

        bf* AsH = dynsm + (t & 1) * STG;
        bf* AsL = AsH + STG_A;
        bf* BsH = AsL + STG_A;

#pragma unroll
        for (int ks = 0; ks < 4; ks++) {
            unsigned ah[4][4], al[4][4], bh[4][2];
            {
                int rowb = wM * 64 + (lane & 15);
                int kk   = ks * 16 + (lane >> 4) * 8;
#pragma unroll
                for (int mt = 0; mt < 4; mt++) {
                    int off = (rowb + mt * 16) * BKP + kk;
                    ldsm4(ah[mt][0], ah[mt][1], ah[mt][2], ah[mt][3], AsH + off);
                    if (twoTerm)
                        ldsm4(al[mt][0], al[mt][1], al[mt][2], al[mt][3], AsL + off);
                }
            }
            {
                int kk = ks * 16 + (lane & 7) + ((lane >> 3) & 1) * 8;
#pragma unroll
                for (int p = 0; p < 2; p++) {
                    int nn = wN * 32 + p * 16 + (lane >> 4) * 8;
                    unsigned t0, t1, t2, t3;
                    ldsm4t(t0, t1, t2, t3, BsH + kk * BNP + nn);
                    bh[2*p][0] = t0; bh[2*p][1] = t1;
                    bh[2*p+1][0] = t2; bh[2*p+1][1] = t3;
                }
            }
#pragma unroll
            for (int mt = 0; mt < 4; mt++)
#pragma unroll
                for (int nt = 0; nt < 4; nt++) {
                    mma16816(acc[mt][nt], ah[mt], bh[nt]);
                    if (twoTerm) mma16816(acc[mt][nt], al[mt], bh[nt]);
                }
        }
    }

#pragma unroll
    for (int mt = 0; mt < 4; mt++) {
        int r0 = brow + wM * 64 + mt * 16 + (lane >> 2);
#pragma unroll
        for (int nt = 0; nt < 4; nt++) {
            int col = bcol + wN * 32 + nt * 8 + (lane & 3) * 2;
#pragma unroll
            for (int half = 0; half < 2; half++) {
                int r = r0 + half * 8;
                if (r >= M) continue;
                float v0 = alpha * acc[mt][nt][half * 2 + 0];
                float v1 = alpha * acc[mt][nt][half * 2 + 1];
                if (mode == 0) {
                    if (bias) { v0 += bias[col]; v1 += bias[col + 1]; }
                    *(float2*)&outF[(size_t)r * N + col] = make_float2(v0, v1);
                } else {
                    size_t ro = (size_t)orow(r, Lseg, segOff) * N + col;
                    *(__half2*)(outH + ro) =
                        __halves2half2(__float2half_rn(v0), __float2half_rn(v1));
                }
            }
        }
    }
}

// output-projection GEMM (A single-term)
__global__ __launch_bounds__(256, 2) void gemm_main(
    const bf* Ah, const bf* Al, const bf* Wh,
    const float* bias, float* outF, bf* outH,
    int M, int K, float alpha, int mode)
{
    extern __shared__ __align__(16) bf dynsm_g[];
    unsigned sbase = (unsigned)__cvta_generic_to_shared(dynsm_g);
    gemm_dev(dynsm_g, sbase, Ah, Al, Wh, M, K, blockIdx.x, blockIdx.y,
             alpha, mode, bias, outF, outH, 0, 0);
}

struct GSeg { const bf *Ah, *Al, *Wh; bf *Ch; int M, Lseg, segOff; };
struct GFused {
    const bf *QAh, *QAl, *QWh;
    bf *QCh;
    GSeg s[6];
};
#define QBLOCKS (10 * (MQ / 128))   // 2560

__global__ __launch_bounds__(256, 2) void gemm_qkv(GFused P)
{
    extern __shared__ __align__(16) bf dynsm_f[];
    unsigned sbase = (unsigned)__cvta_generic_to_shared(dynsm_f);
    int bid = blockIdx.x;
    if (bid < QBLOCKS) {
        int bx = bid % 10, by = bid / 10;
        gemm_dev(dynsm_f, sbase, P.QAh, P.QAl, P.QWh, MQ, Dm, bx, by,
                 0.125f, 2, nullptr, nullptr, P.QCh, 0, 0);
    } else {
        int kid = bid - QBLOCKS;
        int z = kid / 50, rem = kid % 50;
        int by = rem / 10, bx = rem % 10;
        const GSeg s = P.s[z];
        if (by * 128 >= s.M) return;
        gemm_dev(dynsm_f, sbase, s.Ah, s.Al, s.Wh, s.M, Cm, bx, by,
                 1.0f, 2, nullptr, nullptr, s.Ch, s.Lseg, s.segOff);
    }
}

// ---------------- register-resident fused attention ----------------
// Q 1-term x K 1-term; P 2-term x V 1-term; O written 1-term.
#define TMA2 128
#define NTILE 2
#define AQS 72
#define AKS 120
#define AVS 72
#define A2_QH  0
#define A2_KTH (A2_QH + TMA2*AQS)
#define A2_VH  (A2_KTH + 64*AKS)
#define ATT2_SMEM_BYTES ((A2_VH + 112*AVS) * 2)   // 49920

__global__ __launch_bounds__(256, 2) void attn3()
{
    extern __shared__ __align__(16) bf sm3[];
    bf* Qh  = sm3 + A2_QH;
    bf* Kth = sm3 + A2_KTH;
    bf* Vh  = sm3 + A2_VH;

    const int t = threadIdx.x, lane = t & 31, warp = t >> 5;
    const int qq = blockIdx.x, h = blockIdx.y, b = blockIdx.z;
    const size_t kvbase = ((size_t)b * LTOT) * Dm + h * 64;

    for (int idx = t; idx < LTOT * 64; idx += 256) {
        int l = idx >> 6, d = idx & 63;
        Kth[d * AKS + l] = gKh[kvbase + (size_t)l * Dm + d];
    }
    if (t < 192) {
        int d = t / 3, l = LTOT + t % 3;
        Kth[d * AKS + l] = __float2half(0.f);
    }
    for (int idx = t; idx < LTOT * 8; idx += 256) {
        int l = idx >> 3, j = idx & 7;
        *(uint4*)(Vh + l * AVS + j * 8) = *(const uint4*)(gVh + kvbase + (size_t)l * Dm + j * 8);
    }
    uint4 z4 = make_uint4(0, 0, 0, 0);
    if (t < 24) {
        int l = LTOT + t / 8, j = t & 7;
        *(uint4*)(Vh + l * AVS + j * 8) = z4;
    }

    const int qbase = b * Sq + qq * (TMA2 * NTILE);

    auto loadQ = [&](int tile) {
        int q0 = qbase + tile * TMA2;
#pragma unroll
        for (int u = 0; u < 4; u++) {
            int i = t + u * 256;
            int r = i >> 3, j = i & 7;
            size_t go = (size_t)(q0 + r) * Dm + h * 64 + j * 8;
            cpa16(s2u(Qh + r * AQS + j * 8), gQh + go, 16);
        }
    };

    loadQ(0);
    CP_COMMIT();

    for (int tile = 0; tile < NTILE; tile++) {
        CP_WAIT0();
        __syncthreads();

        // ---- S = Qh @ Kh^T ----
        float accs[14][4];
#pragma unroll
        for (int i = 0; i < 14; i++)
#pragma unroll
            for (int j = 0; j < 4; j++) accs[i][j] = 0.f;

#pragma unroll
        for (int ks = 0; ks < 4; ks++) {
            unsigned ah[4];
            int aoff = (warp * 16 + (lane & 15)) * AQS + ks * 16 + (lane >> 4) * 8;
            ldsm4(ah[0], ah[1], ah[2], ah[3], Qh + aoff);
            int kk = ks * 16 + (lane & 7) + ((lane >> 3) & 1) * 8;
#pragma unroll
            for (int p = 0; p < 7; p++) {
                int nn = p * 16 + (lane >> 4) * 8;
                unsigned t0, t1, t2, t3;
                ldsm4t(t0, t1, t2, t3, Kth + kk * AKS + nn);
                unsigned bh0[2] = {t0, t1}, bh1[2] = {t2, t3};
                mma16816(accs[2*p],   ah, bh0);
                mma16816(accs[2*p+1], ah, bh1);
            }
        }
        __syncthreads();
        if (tile + 1 < NTILE) { loadQ(tile + 1); CP_COMMIT(); }

        // ---- in-register per-segment softmax ----
        const int cbase = (lane & 3) * 2;
#pragma unroll
        for (int j = 0; j < 2; j++) {
            float mx0 = -1e30f, mx1 = -1e30f, mx2 = -1e30f;
#pragma unroll
            for (int nt = 0; nt < 14; nt++)
#pragma unroll
                for (int e = 0; e < 2; e++) {
                    int c = nt * 8 + cbase + e;
                    float v = accs[nt][2*j + e];
                    if (c < LT) mx0 = fmaxf(mx0, v);
                    else if (c < LT + LI) mx1 = fmaxf(mx1, v);
                    else if (c < LTOT) mx2 = fmaxf(mx2, v);
                }
#pragma unroll
            for (int d = 1; d < 4; d <<= 1) {
                mx0 = fmaxf(mx0, __shfl_xor_sync(0xffffffffu, mx0, d));
                mx1 = fmaxf(mx1, __shfl_xor_sync(0xffffffffu, mx1, d));
                mx2 = fmaxf(mx2, __shfl_xor_sync(0xffffffffu, mx2, d));
            }
            float s0 = 0.f, s1 = 0.f, s2 = 0.f;
#pragma unroll
            for (int nt = 0; nt < 14; nt++)
#pragma unroll
                for (int e = 0; e < 2; e++) {
                    int c = nt * 8 + cbase + e;
                    float v = accs[nt][2*j + e], r;
                    if (c < LT)           { r = fexp(v - mx0); s0 += r; }
                    else if (c < LT + LI) { r = fexp(v - mx1); s1 += r; }
                    else if (c < LTOT)    { r = fexp(v - mx2); s2 += r; }
                    else r = 0.f;
                    accs[nt][2*j + e] = r;
                }
#pragma unroll
            for (int d = 1; d < 4; d <<= 1) {
                s0 += __shfl_xor_sync(0xffffffffu, s0, d);
                s1 += __shfl_xor_sync(0xffffffffu, s1, d);
                s2 += __shfl_xor_sync(0xffffffffu, s2, d);
            }
            float i0 = 1.0f / s0, i1 = 1.0f / s1, i2 = 1.0f / s2;
#pragma unroll
            for (int nt = 0; nt < 14; nt++)
#pragma unroll
                for (int e = 0; e < 2; e++) {
                    int c = nt * 8 + cbase + e;
                    float inv = (c < LT) ? i0 : (c < LT + LI) ? i1 : i2;
                    accs[nt][2*j + e] *= inv;
                }
        }

        // ---- O = P @ V  (P 2-term, V 1-term) ----
        float acco[8][4];
#pragma unroll
        for (int i = 0; i < 8; i++)
#pragma unroll
            for (int j = 0; j < 4; j++) acco[i][j] = 0.f;

#pragma unroll
        for (int ks = 0; ks < 7; ks++) {
            unsigned ah[4], al[4];
#pragma unroll
            for (int q = 0; q < 2; q++)
#pragma unroll
                for (int rr = 0; rr < 2; rr++) {
                    float v0 = accs[2*ks + q][2*rr + 0];
                    float v1 = accs[2*ks + q][2*rr + 1];
                    bf h0, l0, h1, l1;
                    splitw(v0, h0, l0);
                    splitw(v1, h1, l1);
                    __half2 hp = __halves2half2(h0, h1);
                    __half2 lp = __halves2half2(l0, l1);
                    ah[q*2 + rr] = *reinterpret_cast<unsigned*>(&hp);
                    al[q*2 + rr] = *reinterpret_cast<unsigned*>(&lp);
                }
            int kk = ks * 16 + (lane & 7) + ((lane >> 3) & 1) * 8;
#pragma unroll
            for (int p = 0; p < 4; p++) {
                int nn = p * 16 + (lane >> 4) * 8;
                unsigned t0, t1, t2, t3;
                ldsm4t(t0, t1, t2, t3, Vh + kk * AVS + nn);
                unsigned bh0[2] = {t0, t1}, bh1[2] = {t2, t3};
                mma16816(acco[2*p],   ah, bh0);
                mma16816(acco[2*p],   al, bh0);
                mma16816(acco[2*p+1], ah, bh1);
                mma16816(acco[2*p+1], al, bh1);
            }
        }

        int q0 = qbase + tile * TMA2;
#pragma unroll
        for (int nt = 0; nt < 8; nt++) {
            int c = h * 64 + nt * 8 + (lane & 3) * 2;
#pragma unroll
            for (int half = 0; half < 2; half++) {
                int r = warp * 16 + (lane >> 2) + half * 8;
                size_t ro = (size_t)(q0 + r) * Dm + c;
                *(__half2*)(gOh + ro) = __halves2half2(
                    __float2half_rn(acco[nt][half * 2 + 0]),
                    __float2half_rn(acco[nt][half * 2 + 1]));
            }
        }
    }
}

// ---------------- launch ----------------
extern "C" void kernel_launch(void* const* d_in, const int* in_sizes, int n_in,
                              void* d_out, int out_size)
{
    const float* hidden  = (const float*)d_in[0];
    const float* text    = (const float*)d_in[1];
    const float* ids     = (const float*)d_in[2];
    const float* hair    = (const float*)d_in[3];
    const float* Wq      = (const float*)d_in[4];
    const float* Wk      = (const float*)d_in[5];
    const float* Wv      = (const float*)d_in[6];
    const float* Wo      = (const float*)d_in[7];
    const float* bo      = (const float*)d_in[8];
    const float* Wk_id   = (const float*)d_in[9];
    const float* Wv_id   = (const float*)d_in[10];
    const float* Wk_hair = (const float*)d_in[11];
    const float* Wv_hair = (const float*)d_in[12];
    float* out = (float*)d_out;

    bf *pHh, *pHl, *pQh, *pOh, *pTh, *pTl, *pIh, *pIl, *pRh, *pRl;
    bf *pKh, *pVh;
    bf *pWqH, *pWoH, *pWkH, *pWvH, *pWkiH, *pWviH, *pWkhH, *pWvhH;
    cudaGetSymbolAddress((void**)&pHh, gHh);   cudaGetSymbolAddress((void**)&pHl, gHl);
    cudaGetSymbolAddress((void**)&pQh, gQh);
    cudaGetSymbolAddress((void**)&pOh, gOh);
    cudaGetSymbolAddress((void**)&pTh, gTh);   cudaGetSymbolAddress((void**)&pTl, gTl);
    cudaGetSymbolAddress((void**)&pIh, gIh);   cudaGetSymbolAddress((void**)&pIl, gIl);
    cudaGetSymbolAddress((void**)&pRh, gRh);   cudaGetSymbolAddress((void**)&pRl, gRl);
    cudaGetSymbolAddress((void**)&pKh, gKh);   cudaGetSymbolAddress((void**)&pVh, gVh);
    cudaGetSymbolAddress((void**)&pWqH, gWqH);
    cudaGetSymbolAddress((void**)&pWoH, gWoH);
    cudaGetSymbolAddress((void**)&pWkH, gWkH);
    cudaGetSymbolAddress((void**)&pWvH, gWvH);
    cudaGetSymbolAddress((void**)&pWkiH, gWkiH);
    cudaGetSymbolAddress((void**)&pWviH, gWviH);
    cudaGetSymbolAddress((void**)&pWkhH, gWkhH);
    cudaGetSymbolAddress((void**)&pWvhH, gWvhH);

    cudaFuncSetAttribute(gemm_main, cudaFuncAttributeMaxDynamicSharedMemorySize, GEMM_SMEM_BYTES);
    cudaFuncSetAttribute(gemm_qkv,  cudaFuncAttributeMaxDynamicSharedMemorySize, GEMM_SMEM_BYTES);
    cudaFuncSetAttribute(attn3,     cudaFuncAttributeMaxDynamicSharedMemorySize, ATT2_SMEM_BYTES);

    // ---- launch 1: ALL splits ----
    {
        SplitArr A{};
        int off = 0, idx = 0;
        auto add = [&](const float* src, bf* dh, bf* dl, size_t n) {
            int n4 = (int)(n / 4);
            A.s[idx++] = { (const float4*)src, (uint2*)dh, (uint2*)dl, off, n4 };
            off += n4;
        };
        add(hidden,  pHh,  pHl,  (size_t)MQ * Dm);
        add(text,    pTh,  pTl,  (size_t)Bsz * LT * Cm);
        add(ids,     pIh,  pIl,  (size_t)Bsz * LI * Cm);
        add(hair,    pRh,  pRl,  (size_t)Bsz * LI * Cm);
        add(Wq,      pWqH,  nullptr, (size_t)Dm * Dm);
        add(Wo,      pWoH,  nullptr, (size_t)Dm * Dm);
        add(Wk,      pWkH,  nullptr, (size_t)Cm * Dm);
        add(Wv,      pWvH,  nullptr, (size_t)Cm * Dm);
        add(Wk_id,   pWkiH, nullptr, (size_t)Cm * Dm);
        add(Wv_id,   pWviH, nullptr, (size_t)Cm * Dm);
        add(Wk_hair, pWkhH, nullptr, (size_t)Cm * Dm);
        add(Wv_hair, pWvhH, nullptr, (size_t)Cm * Dm);
        A.cnt = idx;
        split_batch<<<(off + 255) / 256, 256>>>(A);
    }

    // ---- launch 2: fused Q + KV projections ----
    {
        GFused F{};
        F.QAh = pHh; F.QAl = pHl; F.QWh = pWqH;
        F.QCh = pQh;
        F.s[0] = { pTh, pTl, pWkH,  pKh, Bsz * LT, LT, 0 };
        F.s[1] = { pTh, pTl, pWvH,  pVh, Bsz * LT, LT, 0 };
        F.s[2] = { pIh, pIl, pWkiH, pKh, Bsz * LI, LI, LT };
        F.s[3] = { pIh, pIl, pWviH, pVh, Bsz * LI, LI, LT };
        F.s[4] = { pRh, pRl, pWkhH, pKh, Bsz * LI, LI, LT + LI };
        F.s[5] = { pRh, pRl, pWvhH, pVh, Bsz * LI, LI, LT + LI };
        gemm_qkv<<<QBLOCKS + 300, 256, GEMM_SMEM_BYTES>>>(F);
    }

    // ---- launch 3: fused attention ----
    attn3<<<dim3(16, Hn, Bsz), 256, ATT2_SMEM_BYTES>>>();

    // ---- launch 4: output projection (A single-term) ----
    gemm_main<<<dim3(Dm / 128, MQ / 128), 256, GEMM_SMEM_BYTES>>>(
        pOh, nullptr, pWoH, bo, out, nullptr, MQ, Dm, 1.0f, 0);
}

// round 17
// speedup vs baseline: 9.4549x; 1.5068x over previous
#include <cuda_runtime.h>
#include <cuda_fp16.h>
#include <cstdint>

// ---------------- problem constants ----------------
#define Bsz   8
#define Sq    4096
#define Dm    1280
#define Cm    2048
#define Hn    20
#define DHd   64
#define LT    77
#define LI    16
#define LTOT  109
#define MQ    (Bsz*Sq)

typedef __half bf;

// ---------------- scratch (all single-term fp16) ----------------
__device__ bf gHh[(size_t)MQ*Dm];
__device__ bf gQh[(size_t)MQ*Dm];
__device__ bf gOh[(size_t)MQ*Dm];
__device__ bf gTh[(size_t)Bsz*LT*Cm];
__device__ bf gIh[(size_t)Bsz*LI*Cm];
__device__ bf gRh[(size_t)Bsz*LI*Cm];
__device__ bf gKh[(size_t)Bsz*LTOT*Dm];
__device__ bf gVh[(size_t)Bsz*LTOT*Dm];
__device__ bf gWqH[1280*1280];
__device__ bf gWoH[1280*1280];
__device__ bf gWkH[2048*1280];
__device__ bf gWvH[2048*1280];
__device__ bf gWkiH[2048*1280];
__device__ bf gWviH[2048*1280];
__device__ bf gWkhH[2048*1280];
__device__ bf gWvhH[2048*1280];

// ---------------- helpers ----------------
__device__ __forceinline__ unsigned s2u(const void* p)
{
    return (unsigned)__cvta_generic_to_shared(p);
}
__device__ __forceinline__ void splitw(float v, bf& h, bf& l)
{
    h = __float2half_rn(v);
    l = __float2half_rn(v - __half2float(h));
}
__device__ __forceinline__ void cpa16(unsigned dst, const void* src, int sz)
{
    asm volatile("cp.async.cg.shared.global [%0], [%1], 16, %2;\n"
                 :: "r"(dst), "l"(src), "r"(sz));
}
#define CP_COMMIT() asm volatile("cp.async.commit_group;\n")
#define CP_WAIT0()  asm volatile("cp.async.wait_group 0;\n")

__device__ __forceinline__ void ldsm4(unsigned& r0, unsigned& r1, unsigned& r2, unsigned& r3,
                                      const void* p)
{
    unsigned a = s2u(p);
    asm volatile("ldmatrix.sync.aligned.m8n8.x4.shared.b16 {%0,%1,%2,%3},[%4];"
                 : "=r"(r0), "=r"(r1), "=r"(r2), "=r"(r3) : "r"(a));
}
__device__ __forceinline__ void ldsm4t(unsigned& r0, unsigned& r1, unsigned& r2, unsigned& r3,
                                       const void* p)
{
    unsigned a = s2u(p);
    asm volatile("ldmatrix.sync.aligned.m8n8.x4.trans.shared.b16 {%0,%1,%2,%3},[%4];"
                 : "=r"(r0), "=r"(r1), "=r"(r2), "=r"(r3) : "r"(a));
}
__device__ __forceinline__ void mma16816(float* c, const unsigned* a, const unsigned* b)
{
    asm volatile(
        "mma.sync.aligned.m16n8k16.row.col.f32.f16.f16.f32 "
        "{%0,%1,%2,%3}, {%4,%5,%6,%7}, {%8,%9}, {%0,%1,%2,%3};"
        : "+f"(c[0]), "+f"(c[1]), "+f"(c[2]), "+f"(c[3])
        : "r"(a[0]), "r"(a[1]), "r"(a[2]), "r"(a[3]), "r"(b[0]), "r"(b[1]));
}

// FMA-only exp (x <= 0 expected)
__device__ __forceinline__ float fexp(float x)
{
    float t  = x * 1.4426950408889634f;
    float fl = floorf(t);
    float f  = t - fl;
    float p  = 1.5403e-4f;
    p = fmaf(p, f, 1.3333558e-3f);
    p = fmaf(p, f, 9.6181291e-3f);
    p = fmaf(p, f, 5.5504109e-2f);
    p = fmaf(p, f, 2.4022651e-1f);
    p = fmaf(p, f, 6.9314718e-1f);
    p = fmaf(p, f, 1.0f);
    int i = (int)fl;
    i = max(i, -126);
    return p * __int_as_float((i + 127) << 23);
}

// ---------------- batched convert kernel: fp32 -> fp16 (hi only) ----------------
struct SplitSeg { const float4* src; uint2* dh; int off; int n4; };
struct SplitArr { SplitSeg s[12]; int cnt; };

__global__ __launch_bounds__(256) void split_batch(SplitArr P)
{
    int gid = blockIdx.x * 256 + threadIdx.x;
#pragma unroll 1
    for (int sg = 0; sg < P.cnt; sg++) {
        int local = gid - P.s[sg].off;
        if (local >= 0 && local < P.s[sg].n4) {
            float4 v = P.s[sg].src[local];
            __half2 a = __halves2half2(__float2half_rn(v.x), __float2half_rn(v.y));
            __half2 b = __halves2half2(__float2half_rn(v.z), __float2half_rn(v.w));
            P.s[sg].dh[local] = make_uint2(*reinterpret_cast<unsigned*>(&a),
                                           *reinterpret_cast<unsigned*>(&b));
            return;
        }
    }
}

// ---------------- fp16 GEMM (1-term x 1-term), BK=64, 2-stage ----------------
#define BKT 64
#define BKP 72
#define BNP 136
#define STG_A (128*BKP)
#define STG_B (BKT*BNP)
#define STG   (STG_A + STG_B)      // 17920
#define GEMM_SMEM_BYTES (2*STG*2)  // 71680

__device__ __forceinline__ int orow(int r, int Lseg, int segOff)
{
    if (Lseg == 0) return r;
    int b = r / Lseg;
    return b * LTOT + segOff + (r - b * Lseg);
}

// mode: 0 = fp32 out (+bias); 2 = fp16 out with orow
__device__ __forceinline__ void gemm_dev(
    bf* dynsm, unsigned sbase,
    const bf* __restrict__ Ah, const bf* __restrict__ Wh,
    int M, int K, int bx, int by, float alpha, int mode,
    const float* __restrict__ bias, float* __restrict__ outF,
    bf* __restrict__ outH, int Lseg, int segOff)
{
    const int N = Dm;
    const int tid = threadIdx.x, lane = tid & 31, warp = tid >> 5;
    const int wM = warp >> 2, wN = warp & 3;
    const int brow = by * 128, bcol = bx * 128;

    float acc[4][4][4];
#pragma unroll
    for (int i = 0; i < 4; i++)
#pragma unroll
        for (int j = 0; j < 4; j++)
#pragma unroll
            for (int q = 0; q < 4; q++) acc[i][j][q] = 0.f;

    const int nT = K / BKT;

    auto load_stage = [&](int st, int k0) {
        unsigned aH = sbase + (unsigned)(st * STG) * 2;
        unsigned bH = aH + STG_A * 2;
#pragma unroll
        for (int u = 0; u < 4; u++) {
            int i = tid + u * 256;
            int row = i >> 3, k8 = (i & 7) * 8;
            const bf* sH = Ah + (size_t)(brow + row) * K + k0 + k8;
            int ok = 16;
            if (brow + row >= M) { sH = Ah; ok = 0; }
            cpa16(aH + (unsigned)(row * BKP + k8) * 2, sH, ok);
        }
#pragma unroll
        for (int u = 0; u < 4; u++) {
            int j = tid + u * 256;
            int kr = j >> 4, n8 = (j & 15) * 8;
            cpa16(bH + (unsigned)(kr * BNP + n8) * 2,
                  Wh + (size_t)(k0 + kr) * N + bcol + n8, 16);
        }
    };

    load_stage(0, 0);
    CP_COMMIT();

    for (int t = 0; t < nT; t++) {
        CP_WAIT0();
        __syncthreads();
        if (t + 1 < nT) { load_stage((t + 1) & 1, (t + 1) * BKT); CP_COMMIT(); }

        bf* AsH = dynsm + (t & 1) * STG;
        bf* BsH = AsH + STG_A;

#pragma unroll
        for (int ks = 0; ks < 4; ks++) {
            unsigned ah[4][4], bh[4][2];
            {
                int rowb = wM * 64 + (lane & 15);
                int kk   = ks * 16 + (lane >> 4) * 8;
#pragma unroll
                for (int mt = 0; mt < 4; mt++) {
                    int off = (rowb + mt * 16) * BKP + kk;
                    ldsm4(ah[mt][0], ah[mt][1], ah[mt][2], ah[mt][3], AsH + off);
                }
            }
            {
                int kk = ks * 16 + (lane & 7) + ((lane >> 3) & 1) * 8;
#pragma unroll
                for (int p = 0; p < 2; p++) {
                    int nn = wN * 32 + p * 16 + (lane >> 4) * 8;
                    unsigned t0, t1, t2, t3;
                    ldsm4t(t0, t1, t2, t3, BsH + kk * BNP + nn);
                    bh[2*p][0] = t0; bh[2*p][1] = t1;
                    bh[2*p+1][0] = t2; bh[2*p+1][1] = t3;
                }
            }
#pragma unroll
            for (int mt = 0; mt < 4; mt++)
#pragma unroll
                for (int nt = 0; nt < 4; nt++)
                    mma16816(acc[mt][nt], ah[mt], bh[nt]);
        }
    }

#pragma unroll
    for (int mt = 0; mt < 4; mt++) {
        int r0 = brow + wM * 64 + mt * 16 + (lane >> 2);
#pragma unroll
        for (int nt = 0; nt < 4; nt++) {
            int col = bcol + wN * 32 + nt * 8 + (lane & 3) * 2;
#pragma unroll
            for (int half = 0; half < 2; half++) {
                int r = r0 + half * 8;
                if (r >= M) continue;
                float v0 = alpha * acc[mt][nt][half * 2 + 0];
                float v1 = alpha * acc[mt][nt][half * 2 + 1];
                if (mode == 0) {
                    if (bias) { v0 += bias[col]; v1 += bias[col + 1]; }
                    *(float2*)&outF[(size_t)r * N + col] = make_float2(v0, v1);
                } else {
                    size_t ro = (size_t)orow(r, Lseg, segOff) * N + col;
                    *(__half2*)(outH + ro) =
                        __halves2half2(__float2half_rn(v0), __float2half_rn(v1));
                }
            }
        }
    }
}

__global__ __launch_bounds__(256, 2) void gemm_main(
    const bf* Ah, const bf* Wh,
    const float* bias, float* outF, bf* outH,
    int M, int K, float alpha, int mode)
{
    extern __shared__ __align__(16) bf dynsm_g[];
    unsigned sbase = (unsigned)__cvta_generic_to_shared(dynsm_g);
    gemm_dev(dynsm_g, sbase, Ah, Wh, M, K, blockIdx.x, blockIdx.y,
             alpha, mode, bias, outF, outH, 0, 0);
}

struct GSeg { const bf *Ah, *Wh; bf *Ch; int M, Lseg, segOff; };
struct GFused {
    const bf *QAh, *QWh;
    bf *QCh;
    GSeg s[6];
};
#define QBLOCKS (10 * (MQ / 128))   // 2560

__global__ __launch_bounds__(256, 2) void gemm_qkv(GFused P)
{
    extern __shared__ __align__(16) bf dynsm_f[];
    unsigned sbase = (unsigned)__cvta_generic_to_shared(dynsm_f);
    int bid = blockIdx.x;
    if (bid < QBLOCKS) {
        int bx = bid % 10, by = bid / 10;
        gemm_dev(dynsm_f, sbase, P.QAh, P.QWh, MQ, Dm, bx, by,
                 0.125f, 2, nullptr, nullptr, P.QCh, 0, 0);
    } else {
        int kid = bid - QBLOCKS;
        int z = kid / 50, rem = kid % 50;
        int by = rem / 10, bx = rem % 10;
        const GSeg s = P.s[z];
        if (by * 128 >= s.M) return;
        gemm_dev(dynsm_f, sbase, s.Ah, s.Wh, s.M, Cm, bx, by,
                 1.0f, 2, nullptr, nullptr, s.Ch, s.Lseg, s.segOff);
    }
}

// ---------------- register-resident fused attention ----------------
// Q 1-term x K 1-term; P 2-term x V 1-term; O written 1-term.
#define TMA2 128
#define NTILE 2
#define AQS 72
#define AKS 120
#define AVS 72
#define A2_QH  0
#define A2_KTH (A2_QH + TMA2*AQS)
#define A2_VH  (A2_KTH + 64*AKS)
#define ATT2_SMEM_BYTES ((A2_VH + 112*AVS) * 2)   // 49920

__global__ __launch_bounds__(256, 2) void attn3()
{
    extern __shared__ __align__(16) bf sm3[];
    bf* Qh  = sm3 + A2_QH;
    bf* Kth = sm3 + A2_KTH;
    bf* Vh  = sm3 + A2_VH;

    const int t = threadIdx.x, lane = t & 31, warp = t >> 5;
    const int qq = blockIdx.x, h = blockIdx.y, b = blockIdx.z;
    const size_t kvbase = ((size_t)b * LTOT) * Dm + h * 64;

    for (int idx = t; idx < LTOT * 64; idx += 256) {
        int l = idx >> 6, d = idx & 63;
        Kth[d * AKS + l] = gKh[kvbase + (size_t)l * Dm + d];
    }
    if (t < 192) {
        int d = t / 3, l = LTOT + t % 3;
        Kth[d * AKS + l] = __float2half(0.f);
    }
    for (int idx = t; idx < LTOT * 8; idx += 256) {
        int l = idx >> 3, j = idx & 7;
        *(uint4*)(Vh + l * AVS + j * 8) = *(const uint4*)(gVh + kvbase + (size_t)l * Dm + j * 8);
    }
    uint4 z4 = make_uint4(0, 0, 0, 0);
    if (t < 24) {
        int l = LTOT + t / 8, j = t & 7;
        *(uint4*)(Vh + l * AVS + j * 8) = z4;
    }

    const int qbase = b * Sq + qq * (TMA2 * NTILE);

    auto loadQ = [&](int tile) {
        int q0 = qbase + tile * TMA2;
#pragma unroll
        for (int u = 0; u < 4; u++) {
            int i = t + u * 256;
            int r = i >> 3, j = i & 7;
            size_t go = (size_t)(q0 + r) * Dm + h * 64 + j * 8;
            cpa16(s2u(Qh + r * AQS + j * 8), gQh + go, 16);
        }
    };

    loadQ(0);
    CP_COMMIT();

    for (int tile = 0; tile < NTILE; tile++) {
        CP_WAIT0();
        __syncthreads();

        // ---- S = Qh @ Kh^T ----
        float accs[14][4];
#pragma unroll
        for (int i = 0; i < 14; i++)
#pragma unroll
            for (int j = 0; j < 4; j++) accs[i][j] = 0.f;

#pragma unroll
        for (int ks = 0; ks < 4; ks++) {
            unsigned ah[4];
            int aoff = (warp * 16 + (lane & 15)) * AQS + ks * 16 + (lane >> 4) * 8;
            ldsm4(ah[0], ah[1], ah[2], ah[3], Qh + aoff);
            int kk = ks * 16 + (lane & 7) + ((lane >> 3) & 1) * 8;
#pragma unroll
            for (int p = 0; p < 7; p++) {
                int nn = p * 16 + (lane >> 4) * 8;
                unsigned t0, t1, t2, t3;
                ldsm4t(t0, t1, t2, t3, Kth + kk * AKS + nn);
                unsigned bh0[2] = {t0, t1}, bh1[2] = {t2, t3};
                mma16816(accs[2*p],   ah, bh0);
                mma16816(accs[2*p+1], ah, bh1);
            }
        }
        __syncthreads();
        if (tile + 1 < NTILE) { loadQ(tile + 1); CP_COMMIT(); }

        // ---- in-register per-segment softmax ----
        const int cbase = (lane & 3) * 2;
#pragma unroll
        for (int j = 0; j < 2; j++) {
            float mx0 = -1e30f, mx1 = -1e30f, mx2 = -1e30f;
#pragma unroll
            for (int nt = 0; nt < 14; nt++)
#pragma unroll
                for (int e = 0; e < 2; e++) {
                    int c = nt * 8 + cbase + e;
                    float v = accs[nt][2*j + e];
                    if (c < LT) mx0 = fmaxf(mx0, v);
                    else if (c < LT + LI) mx1 = fmaxf(mx1, v);
                    else if (c < LTOT) mx2 = fmaxf(mx2, v);
                }
#pragma unroll
            for (int d = 1; d < 4; d <<= 1) {
                mx0 = fmaxf(mx0, __shfl_xor_sync(0xffffffffu, mx0, d));
                mx1 = fmaxf(mx1, __shfl_xor_sync(0xffffffffu, mx1, d));
                mx2 = fmaxf(mx2, __shfl_xor_sync(0xffffffffu, mx2, d));
            }
            float s0 = 0.f, s1 = 0.f, s2 = 0.f;
#pragma unroll
            for (int nt = 0; nt < 14; nt++)
#pragma unroll
                for (int e = 0; e < 2; e++) {
                    int c = nt * 8 + cbase + e;
                    float v = accs[nt][2*j + e], r;
                    if (c < LT)           { r = fexp(v - mx0); s0 += r; }
                    else if (c < LT + LI) { r = fexp(v - mx1); s1 += r; }
                    else if (c < LTOT)    { r = fexp(v - mx2); s2 += r; }
                    else r = 0.f;
                    accs[nt][2*j + e] = r;
                }
#pragma unroll
            for (int d = 1; d < 4; d <<= 1) {
                s0 += __shfl_xor_sync(0xffffffffu, s0, d);
                s1 += __shfl_xor_sync(0xffffffffu, s1, d);
                s2 += __shfl_xor_sync(0xffffffffu, s2, d);
            }
            float i0 = 1.0f / s0, i1 = 1.0f / s1, i2 = 1.0f / s2;
#pragma unroll
            for (int nt = 0; nt < 14; nt++)
#pragma unroll
                for (int e = 0; e < 2; e++) {
                    int c = nt * 8 + cbase + e;
                    float inv = (c < LT) ? i0 : (c < LT + LI) ? i1 : i2;
                    accs[nt][2*j + e] *= inv;
                }
        }

        // ---- O = P @ V  (P 2-term, V 1-term) ----
        float acco[8][4];
#pragma unroll
        for (int i = 0; i < 8; i++)
#pragma unroll
            for (int j = 0; j < 4; j++) acco[i][j] = 0.f;

#pragma unroll
        for (int ks = 0; ks < 7; ks++) {
            unsigned ah[4], al[4];
#pragma unroll
            for (int q = 0; q < 2; q++)
#pragma unroll
                for (int rr = 0; rr < 2; rr++) {
                    float v0 = accs[2*ks + q][2*rr + 0];
                    float v1 = accs[2*ks + q][2*rr + 1];
                    bf h0, l0, h1, l1;
                    splitw(v0, h0, l0);
                    splitw(v1, h1, l1);
                    __half2 hp = __halves2half2(h0, h1);
                    __half2 lp = __halves2half2(l0, l1);
                    ah[q*2 + rr] = *reinterpret_cast<unsigned*>(&hp);
                    al[q*2 + rr] = *reinterpret_cast<unsigned*>(&lp);
                }
            int kk = ks * 16 + (lane & 7) + ((lane >> 3) & 1) * 8;
#pragma unroll
            for (int p = 0; p < 4; p++) {
                int nn = p * 16 + (lane >> 4) * 8;
                unsigned t0, t1, t2, t3;
                ldsm4t(t0, t1, t2, t3, Vh + kk * AVS + nn);
                unsigned bh0[2] = {t0, t1}, bh1[2] = {t2, t3};
                mma16816(acco[2*p],   ah, bh0);
                mma16816(acco[2*p],   al, bh0);
                mma16816(acco[2*p+1], ah, bh1);
                mma16816(acco[2*p+1], al, bh1);
            }
        }

        int q0 = qbase + tile * TMA2;
#pragma unroll
        for (int nt = 0; nt < 8; nt++) {
            int c = h * 64 + nt * 8 + (lane & 3) * 2;
#pragma unroll
            for (int half = 0; half < 2; half++) {
                int r = warp * 16 + (lane >> 2) + half * 8;
                size_t ro = (size_t)(q0 + r) * Dm + c;
                *(__half2*)(gOh + ro) = __halves2half2(
                    __float2half_rn(acco[nt][half * 2 + 0]),
                    __float2half_rn(acco[nt][half * 2 + 1]));
            }
        }
    }
}

// ---------------- launch ----------------
extern "C" void kernel_launch(void* const* d_in, const int* in_sizes, int n_in,
                              void* d_out, int out_size)
{
    const float* hidden  = (const float*)d_in[0];
    const float* text    = (const float*)d_in[1];
    const float* ids     = (const float*)d_in[2];
    const float* hair    = (const float*)d_in[3];
    const float* Wq      = (const float*)d_in[4];
    const float* Wk      = (const float*)d_in[5];
    const float* Wv      = (const float*)d_in[6];
    const float* Wo      = (const float*)d_in[7];
    const float* bo      = (const float*)d_in[8];
    const float* Wk_id   = (const float*)d_in[9];
    const float* Wv_id   = (const float*)d_in[10];
    const float* Wk_hair = (const float*)d_in[11];
    const float* Wv_hair = (const float*)d_in[12];
    float* out = (float*)d_out;

    bf *pHh, *pQh, *pOh, *pTh, *pIh, *pRh, *pKh, *pVh;
    bf *pWqH, *pWoH, *pWkH, *pWvH, *pWkiH, *pWviH, *pWkhH, *pWvhH;
    cudaGetSymbolAddress((void**)&pHh, gHh);
    cudaGetSymbolAddress((void**)&pQh, gQh);
    cudaGetSymbolAddress((void**)&pOh, gOh);
    cudaGetSymbolAddress((void**)&pTh, gTh);
    cudaGetSymbolAddress((void**)&pIh, gIh);
    cudaGetSymbolAddress((void**)&pRh, gRh);
    cudaGetSymbolAddress((void**)&pKh, gKh);
    cudaGetSymbolAddress((void**)&pVh, gVh);
    cudaGetSymbolAddress((void**)&pWqH, gWqH);
    cudaGetSymbolAddress((void**)&pWoH, gWoH);
    cudaGetSymbolAddress((void**)&pWkH, gWkH);
    cudaGetSymbolAddress((void**)&pWvH, gWvH);
    cudaGetSymbolAddress((void**)&pWkiH, gWkiH);
    cudaGetSymbolAddress((void**)&pWviH, gWviH);
    cudaGetSymbolAddress((void**)&pWkhH, gWkhH);
    cudaGetSymbolAddress((void**)&pWvhH, gWvhH);

    cudaFuncSetAttribute(gemm_main, cudaFuncAttributeMaxDynamicSharedMemorySize, GEMM_SMEM_BYTES);
    cudaFuncSetAttribute(gemm_qkv,  cudaFuncAttributeMaxDynamicSharedMemorySize, GEMM_SMEM_BYTES);
    cudaFuncSetAttribute(attn3,     cudaFuncAttributeMaxDynamicSharedMemorySize, ATT2_SMEM_BYTES);

    // ---- launch 1: ALL converts (fp32 -> fp16) ----
    {
        SplitArr A{};
        int off = 0, idx = 0;
        auto add = [&](const float* src, bf* dh, size_t n) {
            int n4 = (int)(n / 4);
            A.s[idx++] = { (const float4*)src, (uint2*)dh, off, n4 };
            off += n4;
        };
        add(hidden,  pHh,  (size_t)MQ * Dm);
        add(text,    pTh,  (size_t)Bsz * LT * Cm);
        add(ids,     pIh,  (size_t)Bsz * LI * Cm);
        add(hair,    pRh,  (size_t)Bsz * LI * Cm);
        add(Wq,      pWqH,  (size_t)Dm * Dm);
        add(Wo,      pWoH,  (size_t)Dm * Dm);
        add(Wk,      pWkH,  (size_t)Cm * Dm);
        add(Wv,      pWvH,  (size_t)Cm * Dm);
        add(Wk_id,   pWkiH, (size_t)Cm * Dm);
        add(Wv_id,   pWviH, (size_t)Cm * Dm);
        add(Wk_hair, pWkhH, (size_t)Cm * Dm);
        add(Wv_hair, pWvhH, (size_t)Cm * Dm);
        A.cnt = idx;
        split_batch<<<(off + 255) / 256, 256>>>(A);
    }

    // ---- launch 2: fused Q + KV projections ----
    {
        GFused F{};
        F.QAh = pHh; F.QWh = pWqH; F.QCh = pQh;
        F.s[0] = { pTh, pWkH,  pKh, Bsz * LT, LT, 0 };
        F.s[1] = { pTh, pWvH,  pVh, Bsz * LT, LT, 0 };
        F.s[2] = { pIh, pWkiH, pKh, Bsz * LI, LI, LT };
        F.s[3] = { pIh, pWviH, pVh, Bsz * LI, LI, LT };
        F.s[4] = { pRh, pWkhH, pKh, Bsz * LI, LI, LT + LI };
        F.s[5] = { pRh, pWvhH, pVh, Bsz * LI, LI, LT + LI };
        gemm_qkv<<<QBLOCKS + 300, 256, GEMM_SMEM_BYTES>>>(F);
    }

    // ---- launch 3: fused attention ----
    attn3<<<dim3(16, Hn, Bsz), 256, ATT2_SMEM_BYTES>>>();

    // ---- launch 4: output projection ----
    gemm_main<<<dim3(Dm / 128, MQ / 128), 256, GEMM_SMEM_BYTES>>>(
        pOh, pWoH, bo, out, nullptr, MQ, Dm, 1.0f, 0);
}